// round 2
// baseline (speedup 1.0000x reference)
#include <cuda_runtime.h>
#include <math.h>

#define D_MODEL 1024
#define NHEAD   16
#define HEAD_DIM 64
#define BATCH   2
#define SEQ     2048
#define MTOT    (BATCH*SEQ)          // 4096

// ---------------- scratch (no allocations allowed) ----------------
__device__ float g_q[MTOT*D_MODEL];
__device__ float g_k[MTOT*D_MODEL];
__device__ float g_v[MTOT*D_MODEL];
__device__ float g_ctx[MTOT*D_MODEL];

// =================================================================
// GEMM:  C[m][n] = sum_k A[m][k]*W[n][k] + bias[n]
// A: [M,K] row-major,  W: [N,K] row-major (i.e. C = A @ W^T + b)
// 64x64 block tile, BK=16, 256 threads, 4x4 microtile.
// =================================================================
__global__ __launch_bounds__(256)
void gemm_bias_kernel(const float* __restrict__ A,
                      const float* __restrict__ W,
                      const float* __restrict__ bias,
                      float* __restrict__ C,
                      int M, int N, int K)
{
    __shared__ float As[16][64];   // k-major
    __shared__ float Bs[16][64];

    const int tid = threadIdx.x;
    const int tx = tid & 15;       // 0..15  -> n micro
    const int ty = tid >> 4;       // 0..15  -> m micro
    const int m0 = blockIdx.y * 64;
    const int n0 = blockIdx.x * 64;

    const int lrow = tid >> 2;         // 0..63
    const int lk4  = (tid & 3) * 4;    // 0,4,8,12

    float acc[4][4] = {};

    for (int k0 = 0; k0 < K; k0 += 16) {
        float4 av = *(const float4*)&A[(size_t)(m0 + lrow) * K + k0 + lk4];
        float4 bv = *(const float4*)&W[(size_t)(n0 + lrow) * K + k0 + lk4];
        As[lk4+0][lrow] = av.x; As[lk4+1][lrow] = av.y;
        As[lk4+2][lrow] = av.z; As[lk4+3][lrow] = av.w;
        Bs[lk4+0][lrow] = bv.x; Bs[lk4+1][lrow] = bv.y;
        Bs[lk4+2][lrow] = bv.z; Bs[lk4+3][lrow] = bv.w;
        __syncthreads();

        #pragma unroll
        for (int kk = 0; kk < 16; kk++) {
            float4 a4 = *(const float4*)&As[kk][ty * 4];
            float4 b4 = *(const float4*)&Bs[kk][tx * 4];
            acc[0][0] += a4.x * b4.x; acc[0][1] += a4.x * b4.y;
            acc[0][2] += a4.x * b4.z; acc[0][3] += a4.x * b4.w;
            acc[1][0] += a4.y * b4.x; acc[1][1] += a4.y * b4.y;
            acc[1][2] += a4.y * b4.z; acc[1][3] += a4.y * b4.w;
            acc[2][0] += a4.z * b4.x; acc[2][1] += a4.z * b4.y;
            acc[2][2] += a4.z * b4.z; acc[2][3] += a4.z * b4.w;
            acc[3][0] += a4.w * b4.x; acc[3][1] += a4.w * b4.y;
            acc[3][2] += a4.w * b4.z; acc[3][3] += a4.w * b4.w;
        }
        __syncthreads();
    }

    #pragma unroll
    for (int i = 0; i < 4; i++) {
        int m = m0 + ty * 4 + i;
        #pragma unroll
        for (int j = 0; j < 4; j++) {
            int n = n0 + tx * 4 + j;
            C[(size_t)m * N + n] = acc[i][j] + bias[n];
        }
    }
}

// =================================================================
// RoPE (in-place on Q and K).  Layout [B,S,H,D] flattened rows of 1024.
// For d<32:  q'[d]    = q[d]*cos[d]      - q[d+32]*sin[d]
//            q'[d+32] = q[d+32]*cos[d+32] + q[d]*sin[d+32]
// =================================================================
__global__ void rope_kernel(float* __restrict__ q, float* __restrict__ k,
                            const float* __restrict__ cosp,
                            const float* __restrict__ sinp)
{
    int idx = blockIdx.x * blockDim.x + threadIdx.x;  // MTOT*NHEAD*32 threads
    int d  = idx & 31;
    int h  = (idx >> 5) & (NHEAD - 1);
    int bs = idx >> 9;                 // 0..MTOT-1
    int s  = bs & (SEQ - 1);

    int base = bs * D_MODEL + h * HEAD_DIM + d;
    float c1 = cosp[s * HEAD_DIM + d];
    float s1 = sinp[s * HEAD_DIM + d];
    float c2 = cosp[s * HEAD_DIM + d + 32];
    float s2 = sinp[s * HEAD_DIM + d + 32];

    float q1 = q[base], q2 = q[base + 32];
    q[base]      = q1 * c1 - q2 * s1;
    q[base + 32] = q2 * c2 + q1 * s2;

    float k1 = k[base], k2 = k[base + 32];
    k[base]      = k1 * c1 - k2 * s1;
    k[base + 32] = k2 * c2 + k1 * s2;
}

// =================================================================
// Flash-style attention. One block = 64 q-rows of one (b,h).
// KV tiles of 64. 256 threads, 4x4 microtiles.
// smem tiles stride 68 floats (16B-aligned, bank-friendly).
// V is stored transposed (Vst[d][kv]) so the P@V loop vectorizes along k.
// =================================================================
#define TS 68                                  // tile row stride (floats)
#define ATTN_SMEM_FLOATS (4*64*TS + 64*17 + 64*3)
#define ATTN_SMEM_BYTES  (ATTN_SMEM_FLOATS * 4)

__global__ __launch_bounds__(256)
void attn_kernel(const float* __restrict__ Q, const float* __restrict__ K,
                 const float* __restrict__ V, float* __restrict__ O)
{
    extern __shared__ float sm[];
    float* Qs   = sm;                     // [64][TS] row-major (row, d)
    float* Ks   = Qs  + 64 * TS;          // [64][TS] row-major (kv, d)
    float* Vst  = Ks  + 64 * TS;          // [64][TS] TRANSPOSED (d, kv)
    float* Ps   = Vst + 64 * TS;          // [64][TS] (row, kv)
    float* red  = Ps  + 64 * TS;          // [64][17]
    float* mrow = red + 64 * 17;          // [64]
    float* lrow = mrow + 64;              // [64]
    float* corr = lrow + 64;              // [64]

    const int b  = blockIdx.z;
    const int h  = blockIdx.y;
    const int qt = blockIdx.x;
    const int tid = threadIdx.x;
    const int tx = tid & 15;              // kv / d micro col
    const int ty = tid >> 4;              // q-row micro
    const int col0 = h * HEAD_DIM;

    // ---- load Q tile (64x64) ----
    #pragma unroll
    for (int c = 0; c < 4; c++) {
        int idx = tid + c * 256;          // float4 index 0..1023
        int r   = idx >> 4;               // 16 float4 per row
        int d4  = (idx & 15) * 4;
        float4 v4 = *(const float4*)&Q[(size_t)(b * SEQ + qt * 64 + r) * D_MODEL + col0 + d4];
        Qs[r * TS + d4 + 0] = v4.x; Qs[r * TS + d4 + 1] = v4.y;
        Qs[r * TS + d4 + 2] = v4.z; Qs[r * TS + d4 + 3] = v4.w;
    }
    if (tid < 64) { mrow[tid] = -1e30f; lrow[tid] = 0.f; }
    float acc[4][4] = {};
    __syncthreads();

    for (int kt = 0; kt < SEQ / 64; kt++) {
        // ---- load K (row-major) and V (transposed) tiles ----
        #pragma unroll
        for (int c = 0; c < 4; c++) {
            int idx = tid + c * 256;
            int r   = idx >> 4;
            int d4  = (idx & 15) * 4;
            size_t g = (size_t)(b * SEQ + kt * 64 + r) * D_MODEL + col0 + d4;
            float4 kv4 = *(const float4*)&K[g];
            Ks[r * TS + d4 + 0] = kv4.x; Ks[r * TS + d4 + 1] = kv4.y;
            Ks[r * TS + d4 + 2] = kv4.z; Ks[r * TS + d4 + 3] = kv4.w;
            float4 vv4 = *(const float4*)&V[g];
            Vst[(d4 + 0) * TS + r] = vv4.x; Vst[(d4 + 1) * TS + r] = vv4.y;
            Vst[(d4 + 2) * TS + r] = vv4.z; Vst[(d4 + 3) * TS + r] = vv4.w;
        }
        __syncthreads();

        // ---- scores s = (Q K^T) * scale ----
        float s_[4][4] = {};
        #pragma unroll
        for (int k4 = 0; k4 < 16; k4++) {
            float4 a4[4], b4[4];
            #pragma unroll
            for (int i = 0; i < 4; i++)
                a4[i] = *(const float4*)&Qs[(ty * 4 + i) * TS + k4 * 4];
            #pragma unroll
            for (int j = 0; j < 4; j++)
                b4[j] = *(const float4*)&Ks[(tx * 4 + j) * TS + k4 * 4];
            #pragma unroll
            for (int i = 0; i < 4; i++)
                #pragma unroll
                for (int j = 0; j < 4; j++)
                    s_[i][j] += a4[i].x * b4[j].x + a4[i].y * b4[j].y
                              + a4[i].z * b4[j].z + a4[i].w * b4[j].w;
        }
        #pragma unroll
        for (int i = 0; i < 4; i++)
            #pragma unroll
            for (int j = 0; j < 4; j++)
                s_[i][j] *= 0.125f;           // 1/sqrt(64)

        // ---- row max (partial then cross-tx reduce) ----
        #pragma unroll
        for (int i = 0; i < 4; i++) {
            float lm = fmaxf(fmaxf(s_[i][0], s_[i][1]), fmaxf(s_[i][2], s_[i][3]));
            red[(ty * 4 + i) * 17 + tx] = lm;
        }
        __syncthreads();
        if (tx == 0) {
            #pragma unroll
            for (int i = 0; i < 4; i++) {
                int row = ty * 4 + i;
                float tm = red[row * 17];
                #pragma unroll
                for (int t = 1; t < 16; t++) tm = fmaxf(tm, red[row * 17 + t]);
                float mo = mrow[row];
                float mn = fmaxf(mo, tm);
                corr[row] = __expf(mo - mn);
                mrow[row] = mn;
            }
        }
        __syncthreads();

        // ---- exp, write P, partial row sums ----
        #pragma unroll
        for (int i = 0; i < 4; i++) {
            int row = ty * 4 + i;
            float mn = mrow[row];
            float ls = 0.f;
            #pragma unroll
            for (int j = 0; j < 4; j++) {
                float p = __expf(s_[i][j] - mn);
                Ps[row * TS + tx * 4 + j] = p;
                ls += p;
            }
            red[row * 17 + tx] = ls;
        }
        __syncthreads();
        if (tx == 0) {
            #pragma unroll
            for (int i = 0; i < 4; i++) {
                int row = ty * 4 + i;
                float ss = 0.f;
                #pragma unroll
                for (int t = 0; t < 16; t++) ss += red[row * 17 + t];
                lrow[row] = lrow[row] * corr[row] + ss;
            }
        }

        // ---- acc = acc*corr + P @ V ----
        #pragma unroll
        for (int i = 0; i < 4; i++) {
            float cr = corr[ty * 4 + i];
            #pragma unroll
            for (int j = 0; j < 4; j++) acc[i][j] *= cr;
        }
        #pragma unroll
        for (int k4 = 0; k4 < 16; k4++) {
            float4 p4[4], v4[4];
            #pragma unroll
            for (int i = 0; i < 4; i++)
                p4[i] = *(const float4*)&Ps[(ty * 4 + i) * TS + k4 * 4];
            #pragma unroll
            for (int j = 0; j < 4; j++)
                v4[j] = *(const float4*)&Vst[(tx * 4 + j) * TS + k4 * 4];
            #pragma unroll
            for (int i = 0; i < 4; i++)
                #pragma unroll
                for (int j = 0; j < 4; j++)
                    acc[i][j] += p4[i].x * v4[j].x + p4[i].y * v4[j].y
                               + p4[i].z * v4[j].z + p4[i].w * v4[j].w;
        }
        __syncthreads();   // protect Ks/Vst/red/Ps + lrow for next tile / epilogue
    }

    // ---- epilogue: normalize, write ctx in [B,S,H*D] ----
    #pragma unroll
    for (int i = 0; i < 4; i++) {
        int row = ty * 4 + i;
        float inv = 1.f / lrow[row];
        #pragma unroll
        for (int j = 0; j < 4; j++) {
            O[(size_t)(b * SEQ + qt * 64 + row) * D_MODEL + col0 + tx * 4 + j]
                = acc[i][j] * inv;
        }
    }
}

// =================================================================
extern "C" void kernel_launch(void* const* d_in, const int* in_sizes, int n_in,
                              void* d_out, int out_size)
{
    const float* x    = (const float*)d_in[0];
    const float* cosp = (const float*)d_in[1];
    const float* sinp = (const float*)d_in[2];
    const float* Wq   = (const float*)d_in[3];
    const float* bq   = (const float*)d_in[4];
    const float* Wk   = (const float*)d_in[5];
    const float* bk   = (const float*)d_in[6];
    const float* Wv   = (const float*)d_in[7];
    const float* bv   = (const float*)d_in[8];
    const float* Wo   = (const float*)d_in[9];
    const float* bo   = (const float*)d_in[10];
    float* out = (float*)d_out;

    float *q, *k, *v, *ctx;
    cudaGetSymbolAddress((void**)&q,   g_q);
    cudaGetSymbolAddress((void**)&k,   g_k);
    cudaGetSymbolAddress((void**)&v,   g_v);
    cudaGetSymbolAddress((void**)&ctx, g_ctx);

    dim3 ggrid(D_MODEL / 64, MTOT / 64);   // (16, 64)
    gemm_bias_kernel<<<ggrid, 256>>>(x, Wq, bq, q, MTOT, D_MODEL, D_MODEL);
    gemm_bias_kernel<<<ggrid, 256>>>(x, Wk, bk, k, MTOT, D_MODEL, D_MODEL);
    gemm_bias_kernel<<<ggrid, 256>>>(x, Wv, bv, v, MTOT, D_MODEL, D_MODEL);

    rope_kernel<<<(MTOT * NHEAD * 32) / 256, 256>>>(q, k, cosp, sinp);

    cudaFuncSetAttribute(attn_kernel,
                         cudaFuncAttributeMaxDynamicSharedMemorySize,
                         ATTN_SMEM_BYTES);
    attn_kernel<<<dim3(SEQ / 64, NHEAD, BATCH), 256, ATTN_SMEM_BYTES>>>(q, k, v, ctx);

    gemm_bias_kernel<<<ggrid, 256>>>(ctx, Wo, bo, out, MTOT, D_MODEL, D_MODEL);
}

// round 3
// speedup vs baseline: 4.7923x; 4.7923x over previous
#include <cuda_runtime.h>
#include <math.h>
#include <stdint.h>

#define D_MODEL 1024
#define NHEAD   16
#define HEAD_DIM 64
#define BATCH   2
#define SEQ     2048
#define MTOT    (BATCH*SEQ)          // 4096

// ---------------- scratch (no allocations allowed) ----------------
__device__ float g_q[MTOT*D_MODEL];
__device__ float g_k[MTOT*D_MODEL];
__device__ float g_v[MTOT*D_MODEL];
__device__ float g_ctx[MTOT*D_MODEL];

// ---------------- helpers ----------------
__device__ __forceinline__ uint32_t f2t(float x) {
    uint32_t u;
    asm("cvt.rna.tf32.f32 %0, %1;" : "=r"(u) : "f"(x));
    return u;
}

__device__ __forceinline__ void mma8(float4& d,
                                     uint32_t a0, uint32_t a1, uint32_t a2, uint32_t a3,
                                     uint32_t b0, uint32_t b1) {
    asm volatile(
        "mma.sync.aligned.m16n8k8.row.col.f32.tf32.tf32.f32 "
        "{%0,%1,%2,%3},{%4,%5,%6,%7},{%8,%9},{%0,%1,%2,%3};"
        : "+f"(d.x), "+f"(d.y), "+f"(d.z), "+f"(d.w)
        : "r"(a0), "r"(a1), "r"(a2), "r"(a3), "r"(b0), "r"(b1));
}

// =================================================================
// tf32 GEMM:  C[m][n] = sum_k A[m][k]*W[n][k] + bias[n]
// 128x128 tile, BK=16, 256 threads (8 warps, 2x4), warp tile 64x32.
// =================================================================
#define GSA 20   // smem row stride (words) — conflict-free frag loads

__global__ __launch_bounds__(256, 2)
void gemm_tf32(const float* __restrict__ A, const float* __restrict__ W,
               const float* __restrict__ bias, float* __restrict__ C,
               int M, int N, int K)
{
    __shared__ uint32_t sA[2][128 * GSA];
    __shared__ uint32_t sB[2][128 * GSA];

    const int tid  = threadIdx.x;
    const int lane = tid & 31;
    const int warp = tid >> 5;
    const int wm   = warp >> 2;      // 0..1
    const int wn   = warp & 3;       // 0..3
    const int m0   = blockIdx.y * 128;
    const int n0   = blockIdx.x * 128;

    const int r0 = tid >> 2;         // 0..63
    const int c4 = (tid & 3) * 4;    // 0,4,8,12

    float4 pa0, pa1, pb0, pb1;

    // prefetch tile 0
    {
        int k0 = 0;
        pa0 = *(const float4*)&A[(size_t)(m0 + r0     ) * K + k0 + c4];
        pa1 = *(const float4*)&A[(size_t)(m0 + r0 + 64) * K + k0 + c4];
        pb0 = *(const float4*)&W[(size_t)(n0 + r0     ) * K + k0 + c4];
        pb1 = *(const float4*)&W[(size_t)(n0 + r0 + 64) * K + k0 + c4];
    }
    {
        uint32_t* a = &sA[0][r0 * GSA + c4];
        a[0]=f2t(pa0.x); a[1]=f2t(pa0.y); a[2]=f2t(pa0.z); a[3]=f2t(pa0.w);
        a += 64 * GSA;
        a[0]=f2t(pa1.x); a[1]=f2t(pa1.y); a[2]=f2t(pa1.z); a[3]=f2t(pa1.w);
        uint32_t* b = &sB[0][r0 * GSA + c4];
        b[0]=f2t(pb0.x); b[1]=f2t(pb0.y); b[2]=f2t(pb0.z); b[3]=f2t(pb0.w);
        b += 64 * GSA;
        b[0]=f2t(pb1.x); b[1]=f2t(pb1.y); b[2]=f2t(pb1.z); b[3]=f2t(pb1.w);
    }
    __syncthreads();

    float4 acc[4][4] = {};
    const int nIter = K / 16;

    for (int it = 0; it < nIter; it++) {
        if (it + 1 < nIter) {
            int k0 = (it + 1) * 16;
            pa0 = *(const float4*)&A[(size_t)(m0 + r0     ) * K + k0 + c4];
            pa1 = *(const float4*)&A[(size_t)(m0 + r0 + 64) * K + k0 + c4];
            pb0 = *(const float4*)&W[(size_t)(n0 + r0     ) * K + k0 + c4];
            pb1 = *(const float4*)&W[(size_t)(n0 + r0 + 64) * K + k0 + c4];
        }
        const uint32_t* cA = sA[it & 1];
        const uint32_t* cB = sB[it & 1];

        #pragma unroll
        for (int ks = 0; ks < 16; ks += 8) {
            uint32_t af[4][4], bf[4][2];
            #pragma unroll
            for (int mt = 0; mt < 4; mt++) {
                int rb = wm * 64 + mt * 16 + (lane >> 2);
                af[mt][0] = cA[ rb      * GSA + ks + (lane & 3)];
                af[mt][1] = cA[(rb + 8) * GSA + ks + (lane & 3)];
                af[mt][2] = cA[ rb      * GSA + ks + (lane & 3) + 4];
                af[mt][3] = cA[(rb + 8) * GSA + ks + (lane & 3) + 4];
            }
            #pragma unroll
            for (int nt = 0; nt < 4; nt++) {
                int nb = wn * 32 + nt * 8 + (lane >> 2);
                bf[nt][0] = cB[nb * GSA + ks + (lane & 3)];
                bf[nt][1] = cB[nb * GSA + ks + (lane & 3) + 4];
            }
            #pragma unroll
            for (int mt = 0; mt < 4; mt++)
                #pragma unroll
                for (int nt = 0; nt < 4; nt++)
                    mma8(acc[mt][nt], af[mt][0], af[mt][1], af[mt][2], af[mt][3],
                         bf[nt][0], bf[nt][1]);
        }

        if (it + 1 < nIter) {
            int bsel = (it + 1) & 1;
            uint32_t* a = &sA[bsel][r0 * GSA + c4];
            a[0]=f2t(pa0.x); a[1]=f2t(pa0.y); a[2]=f2t(pa0.z); a[3]=f2t(pa0.w);
            a += 64 * GSA;
            a[0]=f2t(pa1.x); a[1]=f2t(pa1.y); a[2]=f2t(pa1.z); a[3]=f2t(pa1.w);
            uint32_t* b = &sB[bsel][r0 * GSA + c4];
            b[0]=f2t(pb0.x); b[1]=f2t(pb0.y); b[2]=f2t(pb0.z); b[3]=f2t(pb0.w);
            b += 64 * GSA;
            b[0]=f2t(pb1.x); b[1]=f2t(pb1.y); b[2]=f2t(pb1.z); b[3]=f2t(pb1.w);
        }
        __syncthreads();
    }

    // epilogue + bias
    #pragma unroll
    for (int nt = 0; nt < 4; nt++) {
        int col = n0 + wn * 32 + nt * 8 + 2 * (lane & 3);
        float2 bz = *(const float2*)&bias[col];
        #pragma unroll
        for (int mt = 0; mt < 4; mt++) {
            int row = m0 + wm * 64 + mt * 16 + (lane >> 2);
            float2 v0 = { acc[mt][nt].x + bz.x, acc[mt][nt].y + bz.y };
            float2 v1 = { acc[mt][nt].z + bz.x, acc[mt][nt].w + bz.y };
            *(float2*)&C[(size_t)row * N + col]       = v0;
            *(float2*)&C[(size_t)(row + 8) * N + col] = v1;
        }
    }
}

// =================================================================
// RoPE (in-place on Q and K).
// =================================================================
__global__ void rope_kernel(float* __restrict__ q, float* __restrict__ k,
                            const float* __restrict__ cosp,
                            const float* __restrict__ sinp)
{
    int idx = blockIdx.x * blockDim.x + threadIdx.x;
    int d  = idx & 31;
    int h  = (idx >> 5) & (NHEAD - 1);
    int bs = idx >> 9;
    int s  = bs & (SEQ - 1);

    int base = bs * D_MODEL + h * HEAD_DIM + d;
    float c1 = cosp[s * HEAD_DIM + d];
    float s1 = sinp[s * HEAD_DIM + d];
    float c2 = cosp[s * HEAD_DIM + d + 32];
    float s2 = sinp[s * HEAD_DIM + d + 32];

    float q1 = q[base], q2 = q[base + 32];
    q[base]      = q1 * c1 - q2 * s1;
    q[base + 32] = q2 * c2 + q1 * s2;

    float k1 = k[base], k2 = k[base + 32];
    k[base]      = k1 * c1 - k2 * s1;
    k[base + 32] = k2 * c2 + k1 * s2;
}

// =================================================================
// Flash attention with tf32 mma.sync.
// CTA = 128 q-rows of one (b,h), 256 threads (8 warps, 16 rows each).
// KV tiles of 64.  smem stride 68 (conflict-free frag loads).
// =================================================================
#define AS 68
#define ATTN_SMEM_WORDS ((128 + 64 + 64 + 128) * AS)
#define ATTN_SMEM_BYTES (ATTN_SMEM_WORDS * 4)

__global__ __launch_bounds__(256, 2)
void attn_tf32(const float* __restrict__ Q, const float* __restrict__ K,
               const float* __restrict__ V, float* __restrict__ O)
{
    extern __shared__ uint32_t smu[];
    uint32_t* sQ = smu;                    // [128][AS]
    uint32_t* sK = sQ + 128 * AS;          // [64][AS]   (s, d)
    uint32_t* sV = sK + 64 * AS;           // [64][AS]   (s, d)
    uint32_t* sP = sV + 64 * AS;           // [128][AS]  (q, s)

    const int b    = blockIdx.z;
    const int h    = blockIdx.y;
    const int qt   = blockIdx.x;
    const int tid  = threadIdx.x;
    const int lane = tid & 31;
    const int warp = tid >> 5;           // 0..7
    const int r    = warp * 16 + (lane >> 2);   // q row (this thread, lower half)
    const int cgrp = lane & 3;

    const float* Qb = Q + ((size_t)(b * SEQ + qt * 128) * D_MODEL + h * 64);
    const float* Kb = K + ((size_t)(b * SEQ) * D_MODEL + h * 64);
    const float* Vb = V + ((size_t)(b * SEQ) * D_MODEL + h * 64);

    // ---- load Q tile (128x64) ----
    #pragma unroll
    for (int i = 0; i < 8; i++) {
        int f   = tid + i * 256;
        int row = f >> 4;
        int cc  = (f & 15) * 4;
        float4 v4 = *(const float4*)&Qb[(size_t)row * D_MODEL + cc];
        uint32_t* p = &sQ[row * AS + cc];
        p[0]=f2t(v4.x); p[1]=f2t(v4.y); p[2]=f2t(v4.z); p[3]=f2t(v4.w);
    }

    float m0 = -1e30f, m1 = -1e30f, l0 = 0.f, l1 = 0.f;
    float4 oacc[8] = {};

    for (int kt = 0; kt < SEQ / 64; kt++) {
        // ---- load K, V tiles (64x64 each) ----
        const float* Kt = Kb + (size_t)(kt * 64) * D_MODEL;
        const float* Vt = Vb + (size_t)(kt * 64) * D_MODEL;
        #pragma unroll
        for (int i = 0; i < 4; i++) {
            int f   = tid + i * 256;
            int row = f >> 4;
            int cc  = (f & 15) * 4;
            float4 k4 = *(const float4*)&Kt[(size_t)row * D_MODEL + cc];
            uint32_t* pk = &sK[row * AS + cc];
            pk[0]=f2t(k4.x); pk[1]=f2t(k4.y); pk[2]=f2t(k4.z); pk[3]=f2t(k4.w);
            float4 v4 = *(const float4*)&Vt[(size_t)row * D_MODEL + cc];
            uint32_t* pv = &sV[row * AS + cc];
            pv[0]=f2t(v4.x); pv[1]=f2t(v4.y); pv[2]=f2t(v4.z); pv[3]=f2t(v4.w);
        }
        __syncthreads();

        // ---- scores = Q K^T (rows r, r+8; all 64 kv cols) ----
        float4 s[8] = {};
        #pragma unroll
        for (int ks = 0; ks < 8; ks++) {
            int kk = ks * 8;
            uint32_t a0 = sQ[ r      * AS + kk + cgrp];
            uint32_t a1 = sQ[(r + 8) * AS + kk + cgrp];
            uint32_t a2 = sQ[ r      * AS + kk + cgrp + 4];
            uint32_t a3 = sQ[(r + 8) * AS + kk + cgrp + 4];
            #pragma unroll
            for (int nt = 0; nt < 8; nt++) {
                uint32_t b0 = sK[(nt * 8 + (lane >> 2)) * AS + kk + cgrp];
                uint32_t b1 = sK[(nt * 8 + (lane >> 2)) * AS + kk + cgrp + 4];
                mma8(s[nt], a0, a1, a2, a3, b0, b1);
            }
        }

        // ---- online softmax ----
        float rm0 = -1e30f, rm1 = -1e30f;
        #pragma unroll
        for (int nt = 0; nt < 8; nt++) {
            s[nt].x *= 0.125f; s[nt].y *= 0.125f;
            s[nt].z *= 0.125f; s[nt].w *= 0.125f;
            rm0 = fmaxf(rm0, fmaxf(s[nt].x, s[nt].y));
            rm1 = fmaxf(rm1, fmaxf(s[nt].z, s[nt].w));
        }
        rm0 = fmaxf(rm0, __shfl_xor_sync(0xffffffff, rm0, 1));
        rm0 = fmaxf(rm0, __shfl_xor_sync(0xffffffff, rm0, 2));
        rm1 = fmaxf(rm1, __shfl_xor_sync(0xffffffff, rm1, 1));
        rm1 = fmaxf(rm1, __shfl_xor_sync(0xffffffff, rm1, 2));

        float mn0 = fmaxf(m0, rm0);
        float mn1 = fmaxf(m1, rm1);
        float al0 = __expf(m0 - mn0);
        float al1 = __expf(m1 - mn1);
        m0 = mn0; m1 = mn1;

        float rs0 = 0.f, rs1 = 0.f;
        #pragma unroll
        for (int nt = 0; nt < 8; nt++) {
            float px = __expf(s[nt].x - mn0);
            float py = __expf(s[nt].y - mn0);
            float pz = __expf(s[nt].z - mn1);
            float pw = __expf(s[nt].w - mn1);
            rs0 += px + py;
            rs1 += pz + pw;
            int col = nt * 8 + 2 * cgrp;
            uint2 u0 = { f2t(px), f2t(py) };
            uint2 u1 = { f2t(pz), f2t(pw) };
            *(uint2*)&sP[ r      * AS + col] = u0;
            *(uint2*)&sP[(r + 8) * AS + col] = u1;
        }
        rs0 += __shfl_xor_sync(0xffffffff, rs0, 1);
        rs0 += __shfl_xor_sync(0xffffffff, rs0, 2);
        rs1 += __shfl_xor_sync(0xffffffff, rs1, 1);
        rs1 += __shfl_xor_sync(0xffffffff, rs1, 2);

        l0 = l0 * al0 + rs0;
        l1 = l1 * al1 + rs1;

        #pragma unroll
        for (int nt = 0; nt < 8; nt++) {
            oacc[nt].x *= al0; oacc[nt].y *= al0;
            oacc[nt].z *= al1; oacc[nt].w *= al1;
        }
        __syncwarp();

        // ---- oacc += P @ V ----
        #pragma unroll
        for (int ks = 0; ks < 8; ks++) {
            int kk = ks * 8;
            uint32_t a0 = sP[ r      * AS + kk + cgrp];
            uint32_t a1 = sP[(r + 8) * AS + kk + cgrp];
            uint32_t a2 = sP[ r      * AS + kk + cgrp + 4];
            uint32_t a3 = sP[(r + 8) * AS + kk + cgrp + 4];
            #pragma unroll
            for (int nt = 0; nt < 8; nt++) {
                uint32_t b0 = sV[(kk + cgrp    ) * AS + nt * 8 + (lane >> 2)];
                uint32_t b1 = sV[(kk + cgrp + 4) * AS + nt * 8 + (lane >> 2)];
                mma8(oacc[nt], a0, a1, a2, a3, b0, b1);
            }
        }
        __syncthreads();
    }

    // ---- epilogue ----
    float inv0 = 1.f / l0;
    float inv1 = 1.f / l1;
    float* Ob = O + ((size_t)(b * SEQ + qt * 128) * D_MODEL + h * 64);
    #pragma unroll
    for (int nt = 0; nt < 8; nt++) {
        int col = nt * 8 + 2 * cgrp;
        float2 v0 = { oacc[nt].x * inv0, oacc[nt].y * inv0 };
        float2 v1 = { oacc[nt].z * inv1, oacc[nt].w * inv1 };
        *(float2*)&Ob[(size_t) r      * D_MODEL + col] = v0;
        *(float2*)&Ob[(size_t)(r + 8) * D_MODEL + col] = v1;
    }
}

// =================================================================
extern "C" void kernel_launch(void* const* d_in, const int* in_sizes, int n_in,
                              void* d_out, int out_size)
{
    const float* x    = (const float*)d_in[0];
    const float* cosp = (const float*)d_in[1];
    const float* sinp = (const float*)d_in[2];
    const float* Wq   = (const float*)d_in[3];
    const float* bq   = (const float*)d_in[4];
    const float* Wk   = (const float*)d_in[5];
    const float* bk   = (const float*)d_in[6];
    const float* Wv   = (const float*)d_in[7];
    const float* bv   = (const float*)d_in[8];
    const float* Wo   = (const float*)d_in[9];
    const float* bo   = (const float*)d_in[10];
    float* out = (float*)d_out;

    float *q, *k, *v, *ctx;
    cudaGetSymbolAddress((void**)&q,   g_q);
    cudaGetSymbolAddress((void**)&k,   g_k);
    cudaGetSymbolAddress((void**)&v,   g_v);
    cudaGetSymbolAddress((void**)&ctx, g_ctx);

    dim3 ggrid(D_MODEL / 128, MTOT / 128);   // (8, 32)
    gemm_tf32<<<ggrid, 256>>>(x, Wq, bq, q, MTOT, D_MODEL, D_MODEL);
    gemm_tf32<<<ggrid, 256>>>(x, Wk, bk, k, MTOT, D_MODEL, D_MODEL);
    gemm_tf32<<<ggrid, 256>>>(x, Wv, bv, v, MTOT, D_MODEL, D_MODEL);

    rope_kernel<<<(MTOT * NHEAD * 32) / 256, 256>>>(q, k, cosp, sinp);

    cudaFuncSetAttribute(attn_tf32,
                         cudaFuncAttributeMaxDynamicSharedMemorySize,
                         ATTN_SMEM_BYTES);
    attn_tf32<<<dim3(SEQ / 128, NHEAD, BATCH), 256, ATTN_SMEM_BYTES>>>(q, k, v, ctx);

    gemm_tf32<<<ggrid, 256>>>(ctx, Wo, bo, out, MTOT, D_MODEL, D_MODEL);
}

// round 7
// speedup vs baseline: 4.9468x; 1.0323x over previous
#include <cuda_runtime.h>
#include <math.h>
#include <stdint.h>

#define D_MODEL 1024
#define NHEAD   16
#define HEAD_DIM 64
#define BATCH   2
#define SEQ     2048
#define MTOT    (BATCH*SEQ)          // 4096

// ---------------- scratch (no allocations allowed) ----------------
__device__ float g_q[MTOT*D_MODEL];
__device__ float g_k[MTOT*D_MODEL];
__device__ float g_v[MTOT*D_MODEL];
__device__ float g_ctx[MTOT*D_MODEL];

// ---------------- helpers ----------------
__device__ __forceinline__ uint32_t f2t(float x) {
    uint32_t u;
    asm("cvt.rna.tf32.f32 %0, %1;" : "=r"(u) : "f"(x));
    return u;
}

__device__ __forceinline__ void mma8(float4& d,
                                     uint32_t a0, uint32_t a1, uint32_t a2, uint32_t a3,
                                     uint32_t b0, uint32_t b1) {
    asm volatile(
        "mma.sync.aligned.m16n8k8.row.col.f32.tf32.tf32.f32 "
        "{%0,%1,%2,%3},{%4,%5,%6,%7},{%8,%9},{%0,%1,%2,%3};"
        : "+f"(d.x), "+f"(d.y), "+f"(d.z), "+f"(d.w)
        : "r"(a0), "r"(a1), "r"(a2), "r"(a3), "r"(b0), "r"(b1));
}

// =================================================================
// tf32 GEMM (fused over gridDim.z):  C[m][n] = sum_k A[m][k]*W[n][k] + b[n]
// 128x128 tile, BK=16, 256 threads (8 warps, 2x4), warp tile 64x32.
// =================================================================
#define GSA 20   // smem row stride (words) — conflict-free frag loads

__global__ __launch_bounds__(256, 2)
void gemm3_tf32(const float* __restrict__ A,
                const float* __restrict__ W0, const float* __restrict__ W1,
                const float* __restrict__ W2,
                const float* __restrict__ B0, const float* __restrict__ B1,
                const float* __restrict__ B2,
                float* __restrict__ C0, float* __restrict__ C1,
                float* __restrict__ C2,
                int M, int N, int K)
{
    __shared__ uint32_t sA[2][128 * GSA];
    __shared__ uint32_t sB[2][128 * GSA];

    const int z = blockIdx.z;
    const float* W    = (z == 0) ? W0 : (z == 1) ? W1 : W2;
    const float* bias = (z == 0) ? B0 : (z == 1) ? B1 : B2;
    float*       C    = (z == 0) ? C0 : (z == 1) ? C1 : C2;

    const int tid  = threadIdx.x;
    const int lane = tid & 31;
    const int warp = tid >> 5;
    const int wm   = warp >> 2;      // 0..1
    const int wn   = warp & 3;       // 0..3
    const int m0   = blockIdx.y * 128;
    const int n0   = blockIdx.x * 128;

    const int r0 = tid >> 2;         // 0..63
    const int c4 = (tid & 3) * 4;    // 0,4,8,12

    float4 pa0, pa1, pb0, pb1;

    // prefetch tile 0
    {
        pa0 = *(const float4*)&A[(size_t)(m0 + r0     ) * K + c4];
        pa1 = *(const float4*)&A[(size_t)(m0 + r0 + 64) * K + c4];
        pb0 = *(const float4*)&W[(size_t)(n0 + r0     ) * K + c4];
        pb1 = *(const float4*)&W[(size_t)(n0 + r0 + 64) * K + c4];
    }
    {
        uint32_t* a = &sA[0][r0 * GSA + c4];
        a[0]=f2t(pa0.x); a[1]=f2t(pa0.y); a[2]=f2t(pa0.z); a[3]=f2t(pa0.w);
        a += 64 * GSA;
        a[0]=f2t(pa1.x); a[1]=f2t(pa1.y); a[2]=f2t(pa1.z); a[3]=f2t(pa1.w);
        uint32_t* b = &sB[0][r0 * GSA + c4];
        b[0]=f2t(pb0.x); b[1]=f2t(pb0.y); b[2]=f2t(pb0.z); b[3]=f2t(pb0.w);
        b += 64 * GSA;
        b[0]=f2t(pb1.x); b[1]=f2t(pb1.y); b[2]=f2t(pb1.z); b[3]=f2t(pb1.w);
    }
    __syncthreads();

    float4 acc[4][4] = {};
    const int nIter = K / 16;

    for (int it = 0; it < nIter; it++) {
        if (it + 1 < nIter) {
            int k0 = (it + 1) * 16;
            pa0 = *(const float4*)&A[(size_t)(m0 + r0     ) * K + k0 + c4];
            pa1 = *(const float4*)&A[(size_t)(m0 + r0 + 64) * K + k0 + c4];
            pb0 = *(const float4*)&W[(size_t)(n0 + r0     ) * K + k0 + c4];
            pb1 = *(const float4*)&W[(size_t)(n0 + r0 + 64) * K + k0 + c4];
        }
        const uint32_t* cA = sA[it & 1];
        const uint32_t* cB = sB[it & 1];

        #pragma unroll
        for (int ks = 0; ks < 16; ks += 8) {
            uint32_t af[4][4], bf[4][2];
            #pragma unroll
            for (int mt = 0; mt < 4; mt++) {
                int rb = wm * 64 + mt * 16 + (lane >> 2);
                af[mt][0] = cA[ rb      * GSA + ks + (lane & 3)];
                af[mt][1] = cA[(rb + 8) * GSA + ks + (lane & 3)];
                af[mt][2] = cA[ rb      * GSA + ks + (lane & 3) + 4];
                af[mt][3] = cA[(rb + 8) * GSA + ks + (lane & 3) + 4];
            }
            #pragma unroll
            for (int nt = 0; nt < 4; nt++) {
                int nb = wn * 32 + nt * 8 + (lane >> 2);
                bf[nt][0] = cB[nb * GSA + ks + (lane & 3)];
                bf[nt][1] = cB[nb * GSA + ks + (lane & 3) + 4];
            }
            #pragma unroll
            for (int mt = 0; mt < 4; mt++)
                #pragma unroll
                for (int nt = 0; nt < 4; nt++)
                    mma8(acc[mt][nt], af[mt][0], af[mt][1], af[mt][2], af[mt][3],
                         bf[nt][0], bf[nt][1]);
        }

        if (it + 1 < nIter) {
            int bsel = (it + 1) & 1;
            uint32_t* a = &sA[bsel][r0 * GSA + c4];
            a[0]=f2t(pa0.x); a[1]=f2t(pa0.y); a[2]=f2t(pa0.z); a[3]=f2t(pa0.w);
            a += 64 * GSA;
            a[0]=f2t(pa1.x); a[1]=f2t(pa1.y); a[2]=f2t(pa1.z); a[3]=f2t(pa1.w);
            uint32_t* b = &sB[bsel][r0 * GSA + c4];
            b[0]=f2t(pb0.x); b[1]=f2t(pb0.y); b[2]=f2t(pb0.z); b[3]=f2t(pb0.w);
            b += 64 * GSA;
            b[0]=f2t(pb1.x); b[1]=f2t(pb1.y); b[2]=f2t(pb1.z); b[3]=f2t(pb1.w);
        }
        __syncthreads();
    }

    // epilogue + bias
    #pragma unroll
    for (int nt = 0; nt < 4; nt++) {
        int col = n0 + wn * 32 + nt * 8 + 2 * (lane & 3);
        float2 bz = *(const float2*)&bias[col];
        #pragma unroll
        for (int mt = 0; mt < 4; mt++) {
            int row = m0 + wm * 64 + mt * 16 + (lane >> 2);
            float2 v0 = { acc[mt][nt].x + bz.x, acc[mt][nt].y + bz.y };
            float2 v1 = { acc[mt][nt].z + bz.x, acc[mt][nt].w + bz.y };
            *(float2*)&C[(size_t)row * N + col]       = v0;
            *(float2*)&C[(size_t)(row + 8) * N + col] = v1;
        }
    }
}

// =================================================================
// RoPE (in-place on Q and K).
// =================================================================
__global__ void rope_kernel(float* __restrict__ q, float* __restrict__ k,
                            const float* __restrict__ cosp,
                            const float* __restrict__ sinp)
{
    int idx = blockIdx.x * blockDim.x + threadIdx.x;
    int d  = idx & 31;
    int h  = (idx >> 5) & (NHEAD - 1);
    int bs = idx >> 9;
    int s  = bs & (SEQ - 1);

    int base = bs * D_MODEL + h * HEAD_DIM + d;
    float c1 = cosp[s * HEAD_DIM + d];
    float s1 = sinp[s * HEAD_DIM + d];
    float c2 = cosp[s * HEAD_DIM + d + 32];
    float s2 = sinp[s * HEAD_DIM + d + 32];

    float q1 = q[base], q2 = q[base + 32];
    q[base]      = q1 * c1 - q2 * s1;
    q[base + 32] = q2 * c2 + q1 * s2;

    float k1 = k[base], k2 = k[base + 32];
    k[base]      = k1 * c1 - k2 * s1;
    k[base + 32] = k2 * c2 + k1 * s2;
}

// =================================================================
// Flash attention with tf32 mma.sync + register-prefetched K/V tiles.
// CTA = 128 q-rows of one (b,h), 256 threads (8 warps, 16 rows each).
// KV tiles of 64.  smem stride 68 (conflict-free frag loads).
// exp2-domain softmax (scores pre-scaled by 0.125*log2e).
// =================================================================
#define AS 68
#define ATTN_SMEM_WORDS ((128 + 64 + 64 + 128) * AS)
#define ATTN_SMEM_BYTES (ATTN_SMEM_WORDS * 4)

__global__ __launch_bounds__(256, 2)
void attn_tf32(const float* __restrict__ Q, const float* __restrict__ K,
               const float* __restrict__ V, float* __restrict__ O)
{
    extern __shared__ uint32_t smu[];
    uint32_t* sQ = smu;                    // [128][AS]
    uint32_t* sK = sQ + 128 * AS;          // [64][AS]   (s, d)
    uint32_t* sV = sK + 64 * AS;           // [64][AS]   (s, d)
    uint32_t* sP = sV + 64 * AS;           // [128][AS]  (q, s)

    const int b    = blockIdx.z;
    const int h    = blockIdx.y;
    const int qt   = blockIdx.x;
    const int tid  = threadIdx.x;
    const int lane = tid & 31;
    const int warp = tid >> 5;
    const int r    = warp * 16 + (lane >> 2);
    const int cgrp = lane & 3;

    const int lcc  = (tid & 15) * 4;       // K/V tile col group owned by this thread

    const float* Qb = Q + ((size_t)(b * SEQ + qt * 128) * D_MODEL + h * 64);
    const float* Kb = K + ((size_t)(b * SEQ) * D_MODEL + h * 64);
    const float* Vb = V + ((size_t)(b * SEQ) * D_MODEL + h * 64);

    // ---- load Q tile (128x64) ----
    #pragma unroll
    for (int i = 0; i < 8; i++) {
        int f   = tid + i * 256;
        int row = f >> 4;
        int cc  = (f & 15) * 4;
        float4 v4 = *(const float4*)&Qb[(size_t)row * D_MODEL + cc];
        uint32_t* p = &sQ[row * AS + cc];
        p[0]=f2t(v4.x); p[1]=f2t(v4.y); p[2]=f2t(v4.z); p[3]=f2t(v4.w);
    }

    const float SC = 0.125f * 1.44269504088896340736f;  // 1/sqrt(64) * log2(e)

    float m0 = -1e30f, m1 = -1e30f, l0 = 0.f, l1 = 0.f;
    float4 oacc[8] = {};

    // ---- prefetch tile 0 K+V into registers ----
    float4 kp[4], vp[4];
    #pragma unroll
    for (int i = 0; i < 4; i++) {
        int row = (tid + i * 256) >> 4;
        kp[i] = *(const float4*)&Kb[(size_t)row * D_MODEL + lcc];
        vp[i] = *(const float4*)&Vb[(size_t)row * D_MODEL + lcc];
    }

    for (int kt = 0; kt < SEQ / 64; kt++) {
        // ---- store prefetched K,V into smem ----
        #pragma unroll
        for (int i = 0; i < 4; i++) {
            int row = (tid + i * 256) >> 4;
            uint32_t* pk = &sK[row * AS + lcc];
            pk[0]=f2t(kp[i].x); pk[1]=f2t(kp[i].y); pk[2]=f2t(kp[i].z); pk[3]=f2t(kp[i].w);
            uint32_t* pv = &sV[row * AS + lcc];
            pv[0]=f2t(vp[i].x); pv[1]=f2t(vp[i].y); pv[2]=f2t(vp[i].z); pv[3]=f2t(vp[i].w);
        }
        __syncthreads();

        // ---- prefetch next tile's K (wrap to 0 on last iter; harmless) ----
        const int ktn = (kt + 1) & (SEQ / 64 - 1);
        const float* Ktn = Kb + (size_t)(ktn * 64) * D_MODEL;
        #pragma unroll
        for (int i = 0; i < 4; i++) {
            int row = (tid + i * 256) >> 4;
            kp[i] = *(const float4*)&Ktn[(size_t)row * D_MODEL + lcc];
        }

        // ---- scores = Q K^T ----
        float4 s[8] = {};
        #pragma unroll
        for (int ks = 0; ks < 8; ks++) {
            int kk = ks * 8;
            uint32_t a0 = sQ[ r      * AS + kk + cgrp];
            uint32_t a1 = sQ[(r + 8) * AS + kk + cgrp];
            uint32_t a2 = sQ[ r      * AS + kk + cgrp + 4];
            uint32_t a3 = sQ[(r + 8) * AS + kk + cgrp + 4];
            #pragma unroll
            for (int nt = 0; nt < 8; nt++) {
                uint32_t b0 = sK[(nt * 8 + (lane >> 2)) * AS + kk + cgrp];
                uint32_t b1 = sK[(nt * 8 + (lane >> 2)) * AS + kk + cgrp + 4];
                mma8(s[nt], a0, a1, a2, a3, b0, b1);
            }
        }

        // ---- online softmax (base-2 domain) ----
        float rm0 = -1e30f, rm1 = -1e30f;
        #pragma unroll
        for (int nt = 0; nt < 8; nt++) {
            s[nt].x *= SC; s[nt].y *= SC;
            s[nt].z *= SC; s[nt].w *= SC;
            rm0 = fmaxf(rm0, fmaxf(s[nt].x, s[nt].y));
            rm1 = fmaxf(rm1, fmaxf(s[nt].z, s[nt].w));
        }
        rm0 = fmaxf(rm0, __shfl_xor_sync(0xffffffff, rm0, 1));
        rm0 = fmaxf(rm0, __shfl_xor_sync(0xffffffff, rm0, 2));
        rm1 = fmaxf(rm1, __shfl_xor_sync(0xffffffff, rm1, 1));
        rm1 = fmaxf(rm1, __shfl_xor_sync(0xffffffff, rm1, 2));

        float mn0 = fmaxf(m0, rm0);
        float mn1 = fmaxf(m1, rm1);
        float al0 = exp2f(m0 - mn0);
        float al1 = exp2f(m1 - mn1);
        m0 = mn0; m1 = mn1;

        float rs0 = 0.f, rs1 = 0.f;
        #pragma unroll
        for (int nt = 0; nt < 8; nt++) {
            float px = exp2f(s[nt].x - mn0);
            float py = exp2f(s[nt].y - mn0);
            float pz = exp2f(s[nt].z - mn1);
            float pw = exp2f(s[nt].w - mn1);
            rs0 += px + py;
            rs1 += pz + pw;
            int col = nt * 8 + 2 * cgrp;
            uint2 u0 = { f2t(px), f2t(py) };
            uint2 u1 = { f2t(pz), f2t(pw) };
            *(uint2*)&sP[ r      * AS + col] = u0;
            *(uint2*)&sP[(r + 8) * AS + col] = u1;
        }
        rs0 += __shfl_xor_sync(0xffffffff, rs0, 1);
        rs0 += __shfl_xor_sync(0xffffffff, rs0, 2);
        rs1 += __shfl_xor_sync(0xffffffff, rs1, 1);
        rs1 += __shfl_xor_sync(0xffffffff, rs1, 2);

        l0 = l0 * al0 + rs0;
        l1 = l1 * al1 + rs1;

        #pragma unroll
        for (int nt = 0; nt < 8; nt++) {
            oacc[nt].x *= al0; oacc[nt].y *= al0;
            oacc[nt].z *= al1; oacc[nt].w *= al1;
        }

        // ---- prefetch next tile's V (s[] registers are dead now) ----
        const float* Vtn = Vb + (size_t)(ktn * 64) * D_MODEL;
        #pragma unroll
        for (int i = 0; i < 4; i++) {
            int row = (tid + i * 256) >> 4;
            vp[i] = *(const float4*)&Vtn[(size_t)row * D_MODEL + lcc];
        }
        __syncwarp();

        // ---- oacc += P @ V ----
        #pragma unroll
        for (int ks = 0; ks < 8; ks++) {
            int kk = ks * 8;
            uint32_t a0 = sP[ r      * AS + kk + cgrp];
            uint32_t a1 = sP[(r + 8) * AS + kk + cgrp];
            uint32_t a2 = sP[ r      * AS + kk + cgrp + 4];
            uint32_t a3 = sP[(r + 8) * AS + kk + cgrp + 4];
            #pragma unroll
            for (int nt = 0; nt < 8; nt++) {
                uint32_t b0 = sV[(kk + cgrp    ) * AS + nt * 8 + (lane >> 2)];
                uint32_t b1 = sV[(kk + cgrp + 4) * AS + nt * 8 + (lane >> 2)];
                mma8(oacc[nt], a0, a1, a2, a3, b0, b1);
            }
        }
        __syncthreads();
    }

    // ---- epilogue ----
    float inv0 = 1.f / l0;
    float inv1 = 1.f / l1;
    float* Ob = O + ((size_t)(b * SEQ + qt * 128) * D_MODEL + h * 64);
    #pragma unroll
    for (int nt = 0; nt < 8; nt++) {
        int col = nt * 8 + 2 * cgrp;
        float2 v0 = { oacc[nt].x * inv0, oacc[nt].y * inv0 };
        float2 v1 = { oacc[nt].z * inv1, oacc[nt].w * inv1 };
        *(float2*)&Ob[(size_t) r      * D_MODEL + col] = v0;
        *(float2*)&Ob[(size_t)(r + 8) * D_MODEL + col] = v1;
    }
}

// =================================================================
extern "C" void kernel_launch(void* const* d_in, const int* in_sizes, int n_in,
                              void* d_out, int out_size)
{
    const float* x    = (const float*)d_in[0];
    const float* cosp = (const float*)d_in[1];
    const float* sinp = (const float*)d_in[2];
    const float* Wq   = (const float*)d_in[3];
    const float* bq   = (const float*)d_in[4];
    const float* Wk   = (const float*)d_in[5];
    const float* bk   = (const float*)d_in[6];
    const float* Wv   = (const float*)d_in[7];
    const float* bv   = (const float*)d_in[8];
    const float* Wo   = (const float*)d_in[9];
    const float* bo   = (const float*)d_in[10];
    float* out = (float*)d_out;

    float *q, *k, *v, *ctx;
    cudaGetSymbolAddress((void**)&q,   g_q);
    cudaGetSymbolAddress((void**)&k,   g_k);
    cudaGetSymbolAddress((void**)&v,   g_v);
    cudaGetSymbolAddress((void**)&ctx, g_ctx);

    // fused Q/K/V projections: grid.z selects the weight/bias/output triple
    dim3 g3(D_MODEL / 128, MTOT / 128, 3);   // (8, 32, 3)
    gemm3_tf32<<<g3, 256>>>(x, Wq, Wk, Wv, bq, bk, bv, q, k, v,
                            MTOT, D_MODEL, D_MODEL);

    rope_kernel<<<(MTOT * NHEAD * 32) / 256, 256>>>(q, k, cosp, sinp);

    cudaFuncSetAttribute(attn_tf32,
                         cudaFuncAttributeMaxDynamicSharedMemorySize,
                         ATTN_SMEM_BYTES);
    attn_tf32<<<dim3(SEQ / 128, NHEAD, BATCH), 256, ATTN_SMEM_BYTES>>>(q, k, v, ctx);

    dim3 g1(D_MODEL / 128, MTOT / 128, 1);
    gemm3_tf32<<<g1, 256>>>(ctx, Wo, Wo, Wo, bo, bo, bo, out, out, out,
                            MTOT, D_MODEL, D_MODEL);
}

// round 8
// speedup vs baseline: 5.5206x; 1.1160x over previous
#include <cuda_runtime.h>
#include <math.h>
#include <stdint.h>

#define D_MODEL 1024
#define NHEAD   16
#define HEAD_DIM 64
#define BATCH   2
#define SEQ     2048
#define MTOT    (BATCH*SEQ)          // 4096

// ---------------- scratch (no allocations allowed) ----------------
__device__ float g_q[MTOT*D_MODEL];
__device__ float g_k[MTOT*D_MODEL];
__device__ float g_v[MTOT*D_MODEL];
__device__ float g_ctx[MTOT*D_MODEL];

// ---------------- helpers ----------------
__device__ __forceinline__ uint32_t f2t(float x) {
    uint32_t u;
    asm("cvt.rna.tf32.f32 %0, %1;" : "=r"(u) : "f"(x));
    return u;
}

__device__ __forceinline__ void mma8(float4& d,
                                     uint32_t a0, uint32_t a1, uint32_t a2, uint32_t a3,
                                     uint32_t b0, uint32_t b1) {
    asm volatile(
        "mma.sync.aligned.m16n8k8.row.col.f32.tf32.tf32.f32 "
        "{%0,%1,%2,%3},{%4,%5,%6,%7},{%8,%9},{%0,%1,%2,%3};"
        : "+f"(d.x), "+f"(d.y), "+f"(d.z), "+f"(d.w)
        : "r"(a0), "r"(a1), "r"(a2), "r"(a3), "r"(b0), "r"(b1));
}

__device__ __forceinline__ void ldsm4(uint32_t& r0, uint32_t& r1,
                                      uint32_t& r2, uint32_t& r3, uint32_t addr) {
    asm volatile("ldmatrix.sync.aligned.m8n8.x4.shared.b16 {%0,%1,%2,%3}, [%4];"
                 : "=r"(r0), "=r"(r1), "=r"(r2), "=r"(r3) : "r"(addr));
}

// =================================================================
// tf32 GEMM (fused over gridDim.z):  C[m][n] = sum_k A[m][k]*W[n][k] + b[n]
// 128x128 tile, BK=16, 256 threads (8 warps, 2x4), warp tile 64x32.
// Fragment loads via ldmatrix (LDSM) — GSA=20 layout is conflict-free.
// =================================================================
#define GSA 20   // smem row stride (words)

__global__ __launch_bounds__(256, 2)
void gemm3_tf32(const float* __restrict__ A,
                const float* __restrict__ W0, const float* __restrict__ W1,
                const float* __restrict__ W2,
                const float* __restrict__ B0, const float* __restrict__ B1,
                const float* __restrict__ B2,
                float* __restrict__ C0, float* __restrict__ C1,
                float* __restrict__ C2,
                int M, int N, int K)
{
    __shared__ uint32_t sA[2][128 * GSA];
    __shared__ uint32_t sB[2][128 * GSA];

    const int z = blockIdx.z;
    const float* W    = (z == 0) ? W0 : (z == 1) ? W1 : W2;
    const float* bias = (z == 0) ? B0 : (z == 1) ? B1 : B2;
    float*       C    = (z == 0) ? C0 : (z == 1) ? C1 : C2;

    const int tid  = threadIdx.x;
    const int lane = tid & 31;
    const int warp = tid >> 5;
    const int wm   = warp >> 2;      // 0..1
    const int wn   = warp & 3;       // 0..3
    const int m0   = blockIdx.y * 128;
    const int n0   = blockIdx.x * 128;

    const int r0 = tid >> 2;         // 0..63
    const int c4 = (tid & 3) * 4;    // 0,4,8,12

    // ldmatrix per-lane source coordinates
    const int aRow = lane & 15;                       // A x4: rows 0..15
    const int aCol = (lane >> 4) * 4;                 // k half
    const int bRow = (lane & 7) + ((lane >> 4) * 8);  // B paired x4: nt offset
    const int bCol = ((lane >> 3) & 1) * 4;           // k half

    const uint32_t sA0 = (uint32_t)__cvta_generic_to_shared(&sA[0][0]);
    const uint32_t sA1 = (uint32_t)__cvta_generic_to_shared(&sA[1][0]);
    const uint32_t sB0 = (uint32_t)__cvta_generic_to_shared(&sB[0][0]);
    const uint32_t sB1 = (uint32_t)__cvta_generic_to_shared(&sB[1][0]);

    float4 pa0, pa1, pb0, pb1;

    // prefetch tile 0
    {
        pa0 = *(const float4*)&A[(size_t)(m0 + r0     ) * K + c4];
        pa1 = *(const float4*)&A[(size_t)(m0 + r0 + 64) * K + c4];
        pb0 = *(const float4*)&W[(size_t)(n0 + r0     ) * K + c4];
        pb1 = *(const float4*)&W[(size_t)(n0 + r0 + 64) * K + c4];
    }
    {
        uint32_t* a = &sA[0][r0 * GSA + c4];
        a[0]=f2t(pa0.x); a[1]=f2t(pa0.y); a[2]=f2t(pa0.z); a[3]=f2t(pa0.w);
        a += 64 * GSA;
        a[0]=f2t(pa1.x); a[1]=f2t(pa1.y); a[2]=f2t(pa1.z); a[3]=f2t(pa1.w);
        uint32_t* b = &sB[0][r0 * GSA + c4];
        b[0]=f2t(pb0.x); b[1]=f2t(pb0.y); b[2]=f2t(pb0.z); b[3]=f2t(pb0.w);
        b += 64 * GSA;
        b[0]=f2t(pb1.x); b[1]=f2t(pb1.y); b[2]=f2t(pb1.z); b[3]=f2t(pb1.w);
    }
    __syncthreads();

    float4 acc[4][4] = {};
    const int nIter = K / 16;

    for (int it = 0; it < nIter; it++) {
        if (it + 1 < nIter) {
            int k0 = (it + 1) * 16;
            pa0 = *(const float4*)&A[(size_t)(m0 + r0     ) * K + k0 + c4];
            pa1 = *(const float4*)&A[(size_t)(m0 + r0 + 64) * K + k0 + c4];
            pb0 = *(const float4*)&W[(size_t)(n0 + r0     ) * K + k0 + c4];
            pb1 = *(const float4*)&W[(size_t)(n0 + r0 + 64) * K + k0 + c4];
        }
        const uint32_t cAu = (it & 1) ? sA1 : sA0;
        const uint32_t cBu = (it & 1) ? sB1 : sB0;

        #pragma unroll
        for (int ks = 0; ks < 16; ks += 8) {
            uint32_t af[4][4], bf[4][2];
            #pragma unroll
            for (int mt = 0; mt < 4; mt++) {
                uint32_t addr = cAu + 4u * ((wm * 64 + mt * 16 + aRow) * GSA + ks + aCol);
                ldsm4(af[mt][0], af[mt][1], af[mt][2], af[mt][3], addr);
            }
            #pragma unroll
            for (int t = 0; t < 2; t++) {
                uint32_t addr = cBu + 4u * ((wn * 32 + t * 16 + bRow) * GSA + ks + bCol);
                ldsm4(bf[2*t][0], bf[2*t][1], bf[2*t+1][0], bf[2*t+1][1], addr);
            }
            #pragma unroll
            for (int mt = 0; mt < 4; mt++)
                #pragma unroll
                for (int nt = 0; nt < 4; nt++)
                    mma8(acc[mt][nt], af[mt][0], af[mt][1], af[mt][2], af[mt][3],
                         bf[nt][0], bf[nt][1]);
        }

        if (it + 1 < nIter) {
            int bsel = (it + 1) & 1;
            uint32_t* a = &sA[bsel][r0 * GSA + c4];
            a[0]=f2t(pa0.x); a[1]=f2t(pa0.y); a[2]=f2t(pa0.z); a[3]=f2t(pa0.w);
            a += 64 * GSA;
            a[0]=f2t(pa1.x); a[1]=f2t(pa1.y); a[2]=f2t(pa1.z); a[3]=f2t(pa1.w);
            uint32_t* b = &sB[bsel][r0 * GSA + c4];
            b[0]=f2t(pb0.x); b[1]=f2t(pb0.y); b[2]=f2t(pb0.z); b[3]=f2t(pb0.w);
            b += 64 * GSA;
            b[0]=f2t(pb1.x); b[1]=f2t(pb1.y); b[2]=f2t(pb1.z); b[3]=f2t(pb1.w);
        }
        __syncthreads();
    }

    // epilogue + bias
    #pragma unroll
    for (int nt = 0; nt < 4; nt++) {
        int col = n0 + wn * 32 + nt * 8 + 2 * (lane & 3);
        float2 bz = *(const float2*)&bias[col];
        #pragma unroll
        for (int mt = 0; mt < 4; mt++) {
            int row = m0 + wm * 64 + mt * 16 + (lane >> 2);
            float2 v0 = { acc[mt][nt].x + bz.x, acc[mt][nt].y + bz.y };
            float2 v1 = { acc[mt][nt].z + bz.x, acc[mt][nt].w + bz.y };
            *(float2*)&C[(size_t)row * N + col]       = v0;
            *(float2*)&C[(size_t)(row + 8) * N + col] = v1;
        }
    }
}

// =================================================================
// RoPE (in-place on Q and K).
// =================================================================
__global__ void rope_kernel(float* __restrict__ q, float* __restrict__ k,
                            const float* __restrict__ cosp,
                            const float* __restrict__ sinp)
{
    int idx = blockIdx.x * blockDim.x + threadIdx.x;
    int d  = idx & 31;
    int h  = (idx >> 5) & (NHEAD - 1);
    int bs = idx >> 9;
    int s  = bs & (SEQ - 1);

    int base = bs * D_MODEL + h * HEAD_DIM + d;
    float c1 = cosp[s * HEAD_DIM + d];
    float s1 = sinp[s * HEAD_DIM + d];
    float c2 = cosp[s * HEAD_DIM + d + 32];
    float s2 = sinp[s * HEAD_DIM + d + 32];

    float q1 = q[base], q2 = q[base + 32];
    q[base]      = q1 * c1 - q2 * s1;
    q[base + 32] = q2 * c2 + q1 * s2;

    float k1 = k[base], k2 = k[base + 32];
    k[base]      = k1 * c1 - k2 * s1;
    k[base + 32] = k2 * c2 + k1 * s2;
}

// =================================================================
// Flash attention: tf32 mma.sync + register-prefetched K/V + LDSM frags.
// CTA = 128 q-rows of one (b,h), 256 threads (8 warps).
// =================================================================
#define AS 68
#define ATTN_SMEM_WORDS ((128 + 64 + 64 + 128) * AS)
#define ATTN_SMEM_BYTES (ATTN_SMEM_WORDS * 4)

__global__ __launch_bounds__(256, 2)
void attn_tf32(const float* __restrict__ Q, const float* __restrict__ K,
               const float* __restrict__ V, float* __restrict__ O)
{
    extern __shared__ uint32_t smu[];
    uint32_t* sQ = smu;                    // [128][AS]
    uint32_t* sK = sQ + 128 * AS;          // [64][AS]   (s, d)
    uint32_t* sV = sK + 64 * AS;           // [64][AS]   (s, d)
    uint32_t* sP = sV + 64 * AS;           // [128][AS]  (q, s)

    const int b    = blockIdx.z;
    const int h    = blockIdx.y;
    const int qt   = blockIdx.x;
    const int tid  = threadIdx.x;
    const int lane = tid & 31;
    const int warp = tid >> 5;
    const int r    = warp * 16 + (lane >> 2);
    const int cgrp = lane & 3;

    const int lcc  = (tid & 15) * 4;       // K/V tile col group owned by this thread

    // ldmatrix per-lane source coordinates
    const int qRow = warp * 16 + (lane & 15);          // a-frags (sQ, sP)
    const int qCol = (lane >> 4) * 4;
    const int kRow = (lane & 7) + ((lane >> 4) * 8);   // b-frag pairs (sK)
    const int kCol = ((lane >> 3) & 1) * 4;

    const uint32_t sQu = (uint32_t)__cvta_generic_to_shared(sQ);
    const uint32_t sKu = (uint32_t)__cvta_generic_to_shared(sK);
    const uint32_t sPu = (uint32_t)__cvta_generic_to_shared(sP);

    const float* Qb = Q + ((size_t)(b * SEQ + qt * 128) * D_MODEL + h * 64);
    const float* Kb = K + ((size_t)(b * SEQ) * D_MODEL + h * 64);
    const float* Vb = V + ((size_t)(b * SEQ) * D_MODEL + h * 64);

    // ---- load Q tile (128x64) ----
    #pragma unroll
    for (int i = 0; i < 8; i++) {
        int f   = tid + i * 256;
        int row = f >> 4;
        int cc  = (f & 15) * 4;
        float4 v4 = *(const float4*)&Qb[(size_t)row * D_MODEL + cc];
        uint32_t* p = &sQ[row * AS + cc];
        p[0]=f2t(v4.x); p[1]=f2t(v4.y); p[2]=f2t(v4.z); p[3]=f2t(v4.w);
    }

    const float SC = 0.125f * 1.44269504088896340736f;  // 1/sqrt(64) * log2(e)

    float m0 = -1e30f, m1 = -1e30f, l0 = 0.f, l1 = 0.f;
    float4 oacc[8] = {};

    // ---- prefetch tile 0 K+V into registers ----
    float4 kp[4], vp[4];
    #pragma unroll
    for (int i = 0; i < 4; i++) {
        int row = (tid + i * 256) >> 4;
        kp[i] = *(const float4*)&Kb[(size_t)row * D_MODEL + lcc];
        vp[i] = *(const float4*)&Vb[(size_t)row * D_MODEL + lcc];
    }

    for (int kt = 0; kt < SEQ / 64; kt++) {
        // ---- store prefetched K,V into smem ----
        #pragma unroll
        for (int i = 0; i < 4; i++) {
            int row = (tid + i * 256) >> 4;
            uint32_t* pk = &sK[row * AS + lcc];
            pk[0]=f2t(kp[i].x); pk[1]=f2t(kp[i].y); pk[2]=f2t(kp[i].z); pk[3]=f2t(kp[i].w);
            uint32_t* pv = &sV[row * AS + lcc];
            pv[0]=f2t(vp[i].x); pv[1]=f2t(vp[i].y); pv[2]=f2t(vp[i].z); pv[3]=f2t(vp[i].w);
        }
        __syncthreads();

        // ---- prefetch next tile's K (wrap on last iter; harmless) ----
        const int ktn = (kt + 1) & (SEQ / 64 - 1);
        const float* Ktn = Kb + (size_t)(ktn * 64) * D_MODEL;
        #pragma unroll
        for (int i = 0; i < 4; i++) {
            int row = (tid + i * 256) >> 4;
            kp[i] = *(const float4*)&Ktn[(size_t)row * D_MODEL + lcc];
        }

        // ---- scores = Q K^T ----
        float4 s[8] = {};
        #pragma unroll
        for (int ks = 0; ks < 8; ks++) {
            int kk = ks * 8;
            uint32_t a0, a1, a2, a3;
            ldsm4(a0, a1, a2, a3, sQu + 4u * (qRow * AS + kk + qCol));
            uint32_t bfr[8][2];
            #pragma unroll
            for (int t = 0; t < 4; t++) {
                uint32_t addr = sKu + 4u * ((t * 16 + kRow) * AS + kk + kCol);
                ldsm4(bfr[2*t][0], bfr[2*t][1], bfr[2*t+1][0], bfr[2*t+1][1], addr);
            }
            #pragma unroll
            for (int nt = 0; nt < 8; nt++)
                mma8(s[nt], a0, a1, a2, a3, bfr[nt][0], bfr[nt][1]);
        }

        // ---- online softmax (base-2 domain) ----
        float rm0 = -1e30f, rm1 = -1e30f;
        #pragma unroll
        for (int nt = 0; nt < 8; nt++) {
            s[nt].x *= SC; s[nt].y *= SC;
            s[nt].z *= SC; s[nt].w *= SC;
            rm0 = fmaxf(rm0, fmaxf(s[nt].x, s[nt].y));
            rm1 = fmaxf(rm1, fmaxf(s[nt].z, s[nt].w));
        }
        rm0 = fmaxf(rm0, __shfl_xor_sync(0xffffffff, rm0, 1));
        rm0 = fmaxf(rm0, __shfl_xor_sync(0xffffffff, rm0, 2));
        rm1 = fmaxf(rm1, __shfl_xor_sync(0xffffffff, rm1, 1));
        rm1 = fmaxf(rm1, __shfl_xor_sync(0xffffffff, rm1, 2));

        float mn0 = fmaxf(m0, rm0);
        float mn1 = fmaxf(m1, rm1);
        float al0 = exp2f(m0 - mn0);
        float al1 = exp2f(m1 - mn1);
        m0 = mn0; m1 = mn1;

        float rs0 = 0.f, rs1 = 0.f;
        #pragma unroll
        for (int nt = 0; nt < 8; nt++) {
            float px = exp2f(s[nt].x - mn0);
            float py = exp2f(s[nt].y - mn0);
            float pz = exp2f(s[nt].z - mn1);
            float pw = exp2f(s[nt].w - mn1);
            rs0 += px + py;
            rs1 += pz + pw;
            int col = nt * 8 + 2 * cgrp;
            uint2 u0 = { f2t(px), f2t(py) };
            uint2 u1 = { f2t(pz), f2t(pw) };
            *(uint2*)&sP[ r      * AS + col] = u0;
            *(uint2*)&sP[(r + 8) * AS + col] = u1;
        }
        rs0 += __shfl_xor_sync(0xffffffff, rs0, 1);
        rs0 += __shfl_xor_sync(0xffffffff, rs0, 2);
        rs1 += __shfl_xor_sync(0xffffffff, rs1, 1);
        rs1 += __shfl_xor_sync(0xffffffff, rs1, 2);

        l0 = l0 * al0 + rs0;
        l1 = l1 * al1 + rs1;

        #pragma unroll
        for (int nt = 0; nt < 8; nt++) {
            oacc[nt].x *= al0; oacc[nt].y *= al0;
            oacc[nt].z *= al1; oacc[nt].w *= al1;
        }

        // ---- prefetch next tile's V (s[] registers are dead now) ----
        const float* Vtn = Vb + (size_t)(ktn * 64) * D_MODEL;
        #pragma unroll
        for (int i = 0; i < 4; i++) {
            int row = (tid + i * 256) >> 4;
            vp[i] = *(const float4*)&Vtn[(size_t)row * D_MODEL + lcc];
        }
        __syncwarp();

        // ---- oacc += P @ V ----
        #pragma unroll
        for (int ks = 0; ks < 8; ks++) {
            int kk = ks * 8;
            uint32_t a0, a1, a2, a3;
            ldsm4(a0, a1, a2, a3, sPu + 4u * (qRow * AS + kk + qCol));
            #pragma unroll
            for (int nt = 0; nt < 8; nt++) {
                uint32_t b0 = sV[(kk + cgrp    ) * AS + nt * 8 + (lane >> 2)];
                uint32_t b1 = sV[(kk + cgrp + 4) * AS + nt * 8 + (lane >> 2)];
                mma8(oacc[nt], a0, a1, a2, a3, b0, b1);
            }
        }
        __syncthreads();
    }

    // ---- epilogue ----
    float inv0 = 1.f / l0;
    float inv1 = 1.f / l1;
    float* Ob = O + ((size_t)(b * SEQ + qt * 128) * D_MODEL + h * 64);
    #pragma unroll
    for (int nt = 0; nt < 8; nt++) {
        int col = nt * 8 + 2 * cgrp;
        float2 v0 = { oacc[nt].x * inv0, oacc[nt].y * inv0 };
        float2 v1 = { oacc[nt].z * inv1, oacc[nt].w * inv1 };
        *(float2*)&Ob[(size_t) r      * D_MODEL + col] = v0;
        *(float2*)&Ob[(size_t)(r + 8) * D_MODEL + col] = v1;
    }
}

// =================================================================
extern "C" void kernel_launch(void* const* d_in, const int* in_sizes, int n_in,
                              void* d_out, int out_size)
{
    const float* x    = (const float*)d_in[0];
    const float* cosp = (const float*)d_in[1];
    const float* sinp = (const float*)d_in[2];
    const float* Wq   = (const float*)d_in[3];
    const float* bq   = (const float*)d_in[4];
    const float* Wk   = (const float*)d_in[5];
    const float* bk   = (const float*)d_in[6];
    const float* Wv   = (const float*)d_in[7];
    const float* bv   = (const float*)d_in[8];
    const float* Wo   = (const float*)d_in[9];
    const float* bo   = (const float*)d_in[10];
    float* out = (float*)d_out;

    float *q, *k, *v, *ctx;
    cudaGetSymbolAddress((void**)&q,   g_q);
    cudaGetSymbolAddress((void**)&k,   g_k);
    cudaGetSymbolAddress((void**)&v,   g_v);
    cudaGetSymbolAddress((void**)&ctx, g_ctx);

    // fused Q/K/V projections: grid.z selects the weight/bias/output triple
    dim3 g3(D_MODEL / 128, MTOT / 128, 3);   // (8, 32, 3)
    gemm3_tf32<<<g3, 256>>>(x, Wq, Wk, Wv, bq, bk, bv, q, k, v,
                            MTOT, D_MODEL, D_MODEL);

    rope_kernel<<<(MTOT * NHEAD * 32) / 256, 256>>>(q, k, cosp, sinp);

    cudaFuncSetAttribute(attn_tf32,
                         cudaFuncAttributeMaxDynamicSharedMemorySize,
                         ATTN_SMEM_BYTES);
    attn_tf32<<<dim3(SEQ / 128, NHEAD, BATCH), 256, ATTN_SMEM_BYTES>>>(q, k, v, ctx);

    dim3 g1(D_MODEL / 128, MTOT / 128, 1);
    gemm3_tf32<<<g1, 256>>>(ctx, Wo, Wo, Wo, bo, bo, bo, out, out, out,
                            MTOT, D_MODEL, D_MODEL);
}

// round 9
// speedup vs baseline: 6.0658x; 1.0988x over previous
#include <cuda_runtime.h>
#include <math.h>
#include <stdint.h>

#define D_MODEL 1024
#define NHEAD   16
#define HEAD_DIM 64
#define BATCH   2
#define SEQ     2048
#define MTOT    (BATCH*SEQ)          // 4096

// ---------------- scratch (no allocations allowed) ----------------
__device__ float g_q[MTOT*D_MODEL];      // Q proj (f32) -> rope writes rounded
__device__ float g_k[MTOT*D_MODEL];      // K proj (f32) -> rope writes rounded
__device__ float g_vt[D_MODEL*MTOT];     // V proj, TRANSPOSED [d][m], pre-rounded
__device__ float g_ctx[MTOT*D_MODEL];    // attention out, pre-rounded
__device__ float g_xr[MTOT*D_MODEL];     // x pre-rounded
__device__ float g_wq[D_MODEL*D_MODEL];
__device__ float g_wk[D_MODEL*D_MODEL];
__device__ float g_wv[D_MODEL*D_MODEL];
__device__ float g_wo[D_MODEL*D_MODEL];

// ---------------- helpers ----------------
__device__ __forceinline__ uint32_t f2t(float x) {
    uint32_t u;
    asm("cvt.rna.tf32.f32 %0, %1;" : "=r"(u) : "f"(x));
    return u;
}
__device__ __forceinline__ float f2tf(float x) { return __uint_as_float(f2t(x)); }

__device__ __forceinline__ void mma8(float4& d,
                                     uint32_t a0, uint32_t a1, uint32_t a2, uint32_t a3,
                                     uint32_t b0, uint32_t b1) {
    asm volatile(
        "mma.sync.aligned.m16n8k8.row.col.f32.tf32.tf32.f32 "
        "{%0,%1,%2,%3},{%4,%5,%6,%7},{%8,%9},{%0,%1,%2,%3};"
        : "+f"(d.x), "+f"(d.y), "+f"(d.z), "+f"(d.w)
        : "r"(a0), "r"(a1), "r"(a2), "r"(a3), "r"(b0), "r"(b1));
}

__device__ __forceinline__ void ldsm4(uint32_t& r0, uint32_t& r1,
                                      uint32_t& r2, uint32_t& r3, uint32_t addr) {
    asm volatile("ldmatrix.sync.aligned.m8n8.x4.shared.b16 {%0,%1,%2,%3}, [%4];"
                 : "=r"(r0), "=r"(r1), "=r"(r2), "=r"(r3) : "r"(addr));
}

// =================================================================
// Pre-round x and the four weight matrices to tf32 (rna) once.
// =================================================================
__global__ void preround_kernel(const float* __restrict__ x,
                                const float* __restrict__ Wq,
                                const float* __restrict__ Wk,
                                const float* __restrict__ Wv,
                                const float* __restrict__ Wo)
{
    int i = blockIdx.x * blockDim.x + threadIdx.x;   // float4 index
    const int NX = MTOT * D_MODEL / 4;               // 1M float4
    const int NW = D_MODEL * D_MODEL / 4;            // 256K float4
    if (i < NX) {
        float4 v = ((const float4*)x)[i];
        float4 o = { f2tf(v.x), f2tf(v.y), f2tf(v.z), f2tf(v.w) };
        ((float4*)g_xr)[i] = o;
    }
    if (i < NW) {
        float4 v = ((const float4*)Wq)[i];
        ((float4*)g_wq)[i] = make_float4(f2tf(v.x), f2tf(v.y), f2tf(v.z), f2tf(v.w));
        v = ((const float4*)Wk)[i];
        ((float4*)g_wk)[i] = make_float4(f2tf(v.x), f2tf(v.y), f2tf(v.z), f2tf(v.w));
        v = ((const float4*)Wv)[i];
        ((float4*)g_wv)[i] = make_float4(f2tf(v.x), f2tf(v.y), f2tf(v.z), f2tf(v.w));
        v = ((const float4*)Wo)[i];
        ((float4*)g_wo)[i] = make_float4(f2tf(v.x), f2tf(v.y), f2tf(v.z), f2tf(v.w));
    }
}

// =================================================================
// tf32 GEMM (fused over gridDim.z), pre-rounded operands.
// z==2 (V projection): epilogue writes ROUNDED + TRANSPOSED to Ct[d][m].
// 128x128 tile, BK=16, 256 threads (8 warps, 2x4), warp tile 64x32.
// =================================================================
#define GSA 20   // smem row stride (words)

__global__ __launch_bounds__(256, 2)
void gemm3_tf32(const float* __restrict__ A,
                const float* __restrict__ W0, const float* __restrict__ W1,
                const float* __restrict__ W2,
                const float* __restrict__ B0, const float* __restrict__ B1,
                const float* __restrict__ B2,
                float* __restrict__ C0, float* __restrict__ C1,
                float* __restrict__ C2t,
                int M, int N, int K)
{
    __shared__ uint32_t sA[2][128 * GSA];
    __shared__ uint32_t sB[2][128 * GSA];

    const int z = blockIdx.z;
    const float* W    = (z == 0) ? W0 : (z == 1) ? W1 : W2;
    const float* bias = (z == 0) ? B0 : (z == 1) ? B1 : B2;

    const int tid  = threadIdx.x;
    const int lane = tid & 31;
    const int warp = tid >> 5;
    const int wm   = warp >> 2;      // 0..1
    const int wn   = warp & 3;       // 0..3
    const int m0   = blockIdx.y * 128;
    const int n0   = blockIdx.x * 128;

    const int r0 = tid >> 2;         // 0..63
    const int c4 = (tid & 3) * 4;    // 0,4,8,12

    const int aRow = lane & 15;
    const int aCol = (lane >> 4) * 4;
    const int bRow = (lane & 7) + ((lane >> 4) * 8);
    const int bCol = ((lane >> 3) & 1) * 4;

    const uint32_t sA0 = (uint32_t)__cvta_generic_to_shared(&sA[0][0]);
    const uint32_t sA1 = (uint32_t)__cvta_generic_to_shared(&sA[1][0]);
    const uint32_t sB0 = (uint32_t)__cvta_generic_to_shared(&sB[0][0]);
    const uint32_t sB1 = (uint32_t)__cvta_generic_to_shared(&sB[1][0]);

    float4 pa0, pa1, pb0, pb1;

    // prefetch tile 0
    pa0 = *(const float4*)&A[(size_t)(m0 + r0     ) * K + c4];
    pa1 = *(const float4*)&A[(size_t)(m0 + r0 + 64) * K + c4];
    pb0 = *(const float4*)&W[(size_t)(n0 + r0     ) * K + c4];
    pb1 = *(const float4*)&W[(size_t)(n0 + r0 + 64) * K + c4];
    *(float4*)&sA[0][ r0       * GSA + c4] = pa0;
    *(float4*)&sA[0][(r0 + 64) * GSA + c4] = pa1;
    *(float4*)&sB[0][ r0       * GSA + c4] = pb0;
    *(float4*)&sB[0][(r0 + 64) * GSA + c4] = pb1;
    __syncthreads();

    float4 acc[4][4] = {};
    const int nIter = K / 16;

    for (int it = 0; it < nIter; it++) {
        if (it + 1 < nIter) {
            int k0 = (it + 1) * 16;
            pa0 = *(const float4*)&A[(size_t)(m0 + r0     ) * K + k0 + c4];
            pa1 = *(const float4*)&A[(size_t)(m0 + r0 + 64) * K + k0 + c4];
            pb0 = *(const float4*)&W[(size_t)(n0 + r0     ) * K + k0 + c4];
            pb1 = *(const float4*)&W[(size_t)(n0 + r0 + 64) * K + k0 + c4];
        }
        const uint32_t cAu = (it & 1) ? sA1 : sA0;
        const uint32_t cBu = (it & 1) ? sB1 : sB0;

        #pragma unroll
        for (int ks = 0; ks < 16; ks += 8) {
            uint32_t af[4][4], bf[4][2];
            #pragma unroll
            for (int mt = 0; mt < 4; mt++) {
                uint32_t addr = cAu + 4u * ((wm * 64 + mt * 16 + aRow) * GSA + ks + aCol);
                ldsm4(af[mt][0], af[mt][1], af[mt][2], af[mt][3], addr);
            }
            #pragma unroll
            for (int t = 0; t < 2; t++) {
                uint32_t addr = cBu + 4u * ((wn * 32 + t * 16 + bRow) * GSA + ks + bCol);
                ldsm4(bf[2*t][0], bf[2*t][1], bf[2*t+1][0], bf[2*t+1][1], addr);
            }
            #pragma unroll
            for (int mt = 0; mt < 4; mt++)
                #pragma unroll
                for (int nt = 0; nt < 4; nt++)
                    mma8(acc[mt][nt], af[mt][0], af[mt][1], af[mt][2], af[mt][3],
                         bf[nt][0], bf[nt][1]);
        }

        if (it + 1 < nIter) {
            int bsel = (it + 1) & 1;
            *(float4*)&sA[bsel][ r0       * GSA + c4] = pa0;
            *(float4*)&sA[bsel][(r0 + 64) * GSA + c4] = pa1;
            *(float4*)&sB[bsel][ r0       * GSA + c4] = pb0;
            *(float4*)&sB[bsel][(r0 + 64) * GSA + c4] = pb1;
        }
        __syncthreads();
    }

    // epilogue + bias
    if (z == 2) {
        // V: write rounded + transposed: Ct[n][m]
        #pragma unroll
        for (int nt = 0; nt < 4; nt++) {
            int col = n0 + wn * 32 + nt * 8 + 2 * (lane & 3);
            float2 bz = *(const float2*)&bias[col];
            #pragma unroll
            for (int mt = 0; mt < 4; mt++) {
                int row = m0 + wm * 64 + mt * 16 + (lane >> 2);
                C2t[(size_t) col      * M + row    ] = f2tf(acc[mt][nt].x + bz.x);
                C2t[(size_t)(col + 1) * M + row    ] = f2tf(acc[mt][nt].y + bz.y);
                C2t[(size_t) col      * M + row + 8] = f2tf(acc[mt][nt].z + bz.x);
                C2t[(size_t)(col + 1) * M + row + 8] = f2tf(acc[mt][nt].w + bz.y);
            }
        }
    } else {
        float* C = (z == 0) ? C0 : C1;
        #pragma unroll
        for (int nt = 0; nt < 4; nt++) {
            int col = n0 + wn * 32 + nt * 8 + 2 * (lane & 3);
            float2 bz = *(const float2*)&bias[col];
            #pragma unroll
            for (int mt = 0; mt < 4; mt++) {
                int row = m0 + wm * 64 + mt * 16 + (lane >> 2);
                float2 v0 = { acc[mt][nt].x + bz.x, acc[mt][nt].y + bz.y };
                float2 v1 = { acc[mt][nt].z + bz.x, acc[mt][nt].w + bz.y };
                *(float2*)&C[(size_t)row * N + col]       = v0;
                *(float2*)&C[(size_t)(row + 8) * N + col] = v1;
            }
        }
    }
}

// =================================================================
// RoPE (in-place on Q and K) — writes tf32-rounded outputs.
// =================================================================
__global__ void rope_kernel(float* __restrict__ q, float* __restrict__ k,
                            const float* __restrict__ cosp,
                            const float* __restrict__ sinp)
{
    int idx = blockIdx.x * blockDim.x + threadIdx.x;
    int d  = idx & 31;
    int h  = (idx >> 5) & (NHEAD - 1);
    int bs = idx >> 9;
    int s  = bs & (SEQ - 1);

    int base = bs * D_MODEL + h * HEAD_DIM + d;
    float c1 = cosp[s * HEAD_DIM + d];
    float s1 = sinp[s * HEAD_DIM + d];
    float c2 = cosp[s * HEAD_DIM + d + 32];
    float s2 = sinp[s * HEAD_DIM + d + 32];

    float q1 = q[base], q2 = q[base + 32];
    q[base]      = f2tf(q1 * c1 - q2 * s1);
    q[base + 32] = f2tf(q2 * c2 + q1 * s2);

    float k1 = k[base], k2 = k[base + 32];
    k[base]      = f2tf(k1 * c1 - k2 * s1);
    k[base + 32] = f2tf(k2 * c2 + k1 * s2);
}

// =================================================================
// Flash attention: tf32 mma.sync, register-prefetched K/V, LDSM frags,
// pre-rounded Q/K (rope) and transposed pre-rounded V (g_vt).
// CTA = 128 q-rows of one (b,h), 256 threads (8 warps).
// =================================================================
#define AS 68
#define ATTN_SMEM_WORDS ((128 + 64 + 64 + 128) * AS)
#define ATTN_SMEM_BYTES (ATTN_SMEM_WORDS * 4)

__global__ __launch_bounds__(256, 2)
void attn_tf32(const float* __restrict__ Q, const float* __restrict__ K,
               const float* __restrict__ Vt, float* __restrict__ O)
{
    extern __shared__ uint32_t smu[];
    uint32_t* sQ  = smu;                   // [128][AS]  (q, d)
    uint32_t* sK  = sQ + 128 * AS;         // [64][AS]   (s, d)
    uint32_t* sVt = sK + 64 * AS;          // [64][AS]   (d, s)  TRANSPOSED
    uint32_t* sP  = sVt + 64 * AS;         // [128][AS]  (q, s)

    const int b    = blockIdx.z;
    const int h    = blockIdx.y;
    const int qt   = blockIdx.x;
    const int tid  = threadIdx.x;
    const int lane = tid & 31;
    const int warp = tid >> 5;
    const int r    = warp * 16 + (lane >> 2);
    const int cgrp = lane & 3;

    const int lcc  = (tid & 15) * 4;       // tile col group owned by this thread

    // ldmatrix per-lane source coordinates
    const int qRow = warp * 16 + (lane & 15);          // a-frags (sQ, sP)
    const int qCol = (lane >> 4) * 4;
    const int kRow = (lane & 7) + ((lane >> 4) * 8);   // b-frag pairs (sK, sVt)
    const int kCol = ((lane >> 3) & 1) * 4;

    const uint32_t sQu = (uint32_t)__cvta_generic_to_shared(sQ);
    const uint32_t sKu = (uint32_t)__cvta_generic_to_shared(sK);
    const uint32_t sVu = (uint32_t)__cvta_generic_to_shared(sVt);
    const uint32_t sPu = (uint32_t)__cvta_generic_to_shared(sP);

    const float* Qb  = Q  + ((size_t)(b * SEQ + qt * 128) * D_MODEL + h * 64);
    const float* Kb  = K  + ((size_t)(b * SEQ) * D_MODEL + h * 64);
    const float* Vtb = Vt + ((size_t)(h * 64) * MTOT + b * SEQ);   // rows d, cols s

    // ---- load Q tile (128x64), already rounded ----
    #pragma unroll
    for (int i = 0; i < 8; i++) {
        int f   = tid + i * 256;
        int row = f >> 4;
        int cc  = (f & 15) * 4;
        *(float4*)&sQ[row * AS + cc] =
            *(const float4*)&Qb[(size_t)row * D_MODEL + cc];
    }

    const float SC = 0.125f * 1.44269504088896340736f;  // 1/sqrt(64) * log2(e)

    float m0 = -1e30f, m1 = -1e30f, l0 = 0.f, l1 = 0.f;
    float4 oacc[8] = {};

    // ---- prefetch tile 0 K (row s, col d) + Vt (row d, col s) ----
    float4 kp[4], vp[4];
    #pragma unroll
    for (int i = 0; i < 4; i++) {
        int row = (tid + i * 256) >> 4;
        kp[i] = *(const float4*)&Kb [(size_t)row * D_MODEL + lcc];
        vp[i] = *(const float4*)&Vtb[(size_t)row * MTOT    + lcc];
    }

    for (int kt = 0; kt < SEQ / 64; kt++) {
        // ---- store prefetched K, Vt into smem (pre-rounded: raw float4) ----
        #pragma unroll
        for (int i = 0; i < 4; i++) {
            int row = (tid + i * 256) >> 4;
            *(float4*)&sK [row * AS + lcc] = kp[i];
            *(float4*)&sVt[row * AS + lcc] = vp[i];
        }
        __syncthreads();

        // ---- prefetch next tile (wrap on last iter; harmless) ----
        const int ktn = (kt + 1) & (SEQ / 64 - 1);
        const float* Ktn  = Kb  + (size_t)(ktn * 64) * D_MODEL;
        const float* Vtn  = Vtb + ktn * 64;
        #pragma unroll
        for (int i = 0; i < 4; i++) {
            int row = (tid + i * 256) >> 4;
            kp[i] = *(const float4*)&Ktn[(size_t)row * D_MODEL + lcc];
            vp[i] = *(const float4*)&Vtn[(size_t)row * MTOT    + lcc];
        }

        // ---- scores = Q K^T ----
        float4 s[8] = {};
        #pragma unroll
        for (int ks = 0; ks < 8; ks++) {
            int kk = ks * 8;
            uint32_t a0, a1, a2, a3;
            ldsm4(a0, a1, a2, a3, sQu + 4u * (qRow * AS + kk + qCol));
            uint32_t bfr[8][2];
            #pragma unroll
            for (int t = 0; t < 4; t++) {
                uint32_t addr = sKu + 4u * ((t * 16 + kRow) * AS + kk + kCol);
                ldsm4(bfr[2*t][0], bfr[2*t][1], bfr[2*t+1][0], bfr[2*t+1][1], addr);
            }
            #pragma unroll
            for (int nt = 0; nt < 8; nt++)
                mma8(s[nt], a0, a1, a2, a3, bfr[nt][0], bfr[nt][1]);
        }

        // ---- online softmax (base-2 domain) ----
        float rm0 = -1e30f, rm1 = -1e30f;
        #pragma unroll
        for (int nt = 0; nt < 8; nt++) {
            s[nt].x *= SC; s[nt].y *= SC;
            s[nt].z *= SC; s[nt].w *= SC;
            rm0 = fmaxf(rm0, fmaxf(s[nt].x, s[nt].y));
            rm1 = fmaxf(rm1, fmaxf(s[nt].z, s[nt].w));
        }
        rm0 = fmaxf(rm0, __shfl_xor_sync(0xffffffff, rm0, 1));
        rm0 = fmaxf(rm0, __shfl_xor_sync(0xffffffff, rm0, 2));
        rm1 = fmaxf(rm1, __shfl_xor_sync(0xffffffff, rm1, 1));
        rm1 = fmaxf(rm1, __shfl_xor_sync(0xffffffff, rm1, 2));

        float mn0 = fmaxf(m0, rm0);
        float mn1 = fmaxf(m1, rm1);
        float al0 = exp2f(m0 - mn0);
        float al1 = exp2f(m1 - mn1);
        m0 = mn0; m1 = mn1;

        float rs0 = 0.f, rs1 = 0.f;
        #pragma unroll
        for (int nt = 0; nt < 8; nt++) {
            float px = exp2f(s[nt].x - mn0);
            float py = exp2f(s[nt].y - mn0);
            float pz = exp2f(s[nt].z - mn1);
            float pw = exp2f(s[nt].w - mn1);
            rs0 += px + py;
            rs1 += pz + pw;
            int col = nt * 8 + 2 * cgrp;
            uint2 u0 = { f2t(px), f2t(py) };
            uint2 u1 = { f2t(pz), f2t(pw) };
            *(uint2*)&sP[ r      * AS + col] = u0;
            *(uint2*)&sP[(r + 8) * AS + col] = u1;
        }
        rs0 += __shfl_xor_sync(0xffffffff, rs0, 1);
        rs0 += __shfl_xor_sync(0xffffffff, rs0, 2);
        rs1 += __shfl_xor_sync(0xffffffff, rs1, 1);
        rs1 += __shfl_xor_sync(0xffffffff, rs1, 2);

        l0 = l0 * al0 + rs0;
        l1 = l1 * al1 + rs1;

        #pragma unroll
        for (int nt = 0; nt < 8; nt++) {
            oacc[nt].x *= al0; oacc[nt].y *= al0;
            oacc[nt].z *= al1; oacc[nt].w *= al1;
        }
        __syncwarp();

        // ---- oacc += P @ V  (b-frags via LDSM from transposed V) ----
        #pragma unroll
        for (int ks = 0; ks < 8; ks++) {
            int kk = ks * 8;
            uint32_t a0, a1, a2, a3;
            ldsm4(a0, a1, a2, a3, sPu + 4u * (qRow * AS + kk + qCol));
            uint32_t bfr[8][2];
            #pragma unroll
            for (int t = 0; t < 4; t++) {
                uint32_t addr = sVu + 4u * ((t * 16 + kRow) * AS + kk + kCol);
                ldsm4(bfr[2*t][0], bfr[2*t][1], bfr[2*t+1][0], bfr[2*t+1][1], addr);
            }
            #pragma unroll
            for (int nt = 0; nt < 8; nt++)
                mma8(oacc[nt], a0, a1, a2, a3, bfr[nt][0], bfr[nt][1]);
        }
        __syncthreads();
    }

    // ---- epilogue: normalize + pre-round for the O projection ----
    float inv0 = 1.f / l0;
    float inv1 = 1.f / l1;
    float* Ob = O + ((size_t)(b * SEQ + qt * 128) * D_MODEL + h * 64);
    #pragma unroll
    for (int nt = 0; nt < 8; nt++) {
        int col = nt * 8 + 2 * cgrp;
        float2 v0 = { f2tf(oacc[nt].x * inv0), f2tf(oacc[nt].y * inv0) };
        float2 v1 = { f2tf(oacc[nt].z * inv1), f2tf(oacc[nt].w * inv1) };
        *(float2*)&Ob[(size_t) r      * D_MODEL + col] = v0;
        *(float2*)&Ob[(size_t)(r + 8) * D_MODEL + col] = v1;
    }
}

// =================================================================
extern "C" void kernel_launch(void* const* d_in, const int* in_sizes, int n_in,
                              void* d_out, int out_size)
{
    const float* x    = (const float*)d_in[0];
    const float* cosp = (const float*)d_in[1];
    const float* sinp = (const float*)d_in[2];
    const float* Wq   = (const float*)d_in[3];
    const float* bq   = (const float*)d_in[4];
    const float* Wk   = (const float*)d_in[5];
    const float* bk   = (const float*)d_in[6];
    const float* Wv   = (const float*)d_in[7];
    const float* bv   = (const float*)d_in[8];
    const float* Wo   = (const float*)d_in[9];
    const float* bo   = (const float*)d_in[10];
    float* out = (float*)d_out;

    float *q, *k, *vt, *ctx, *xr, *wq, *wk, *wv, *wo;
    cudaGetSymbolAddress((void**)&q,   g_q);
    cudaGetSymbolAddress((void**)&k,   g_k);
    cudaGetSymbolAddress((void**)&vt,  g_vt);
    cudaGetSymbolAddress((void**)&ctx, g_ctx);
    cudaGetSymbolAddress((void**)&xr,  g_xr);
    cudaGetSymbolAddress((void**)&wq,  g_wq);
    cudaGetSymbolAddress((void**)&wk,  g_wk);
    cudaGetSymbolAddress((void**)&wv,  g_wv);
    cudaGetSymbolAddress((void**)&wo,  g_wo);

    // pre-round x and all weights (tf32 rna)
    preround_kernel<<<(MTOT * D_MODEL / 4 + 255) / 256, 256>>>(x, Wq, Wk, Wv, Wo);

    // fused Q/K/V projections (z==2 writes V transposed+rounded)
    dim3 g3(D_MODEL / 128, MTOT / 128, 3);   // (8, 32, 3)
    gemm3_tf32<<<g3, 256>>>(xr, wq, wk, wv, bq, bk, bv, q, k, vt,
                            MTOT, D_MODEL, D_MODEL);

    rope_kernel<<<(MTOT * NHEAD * 32) / 256, 256>>>(q, k, cosp, sinp);

    cudaFuncSetAttribute(attn_tf32,
                         cudaFuncAttributeMaxDynamicSharedMemorySize,
                         ATTN_SMEM_BYTES);
    attn_tf32<<<dim3(SEQ / 128, NHEAD, BATCH), 256, ATTN_SMEM_BYTES>>>(q, k, vt, ctx);

    dim3 g1(D_MODEL / 128, MTOT / 128, 1);
    gemm3_tf32<<<g1, 256>>>(ctx, wo, wo, wo, bo, bo, bo, out, out, out,
                            MTOT, D_MODEL, D_MODEL);
}

// round 10
// speedup vs baseline: 6.2658x; 1.0330x over previous
#include <cuda_runtime.h>
#include <math.h>
#include <stdint.h>

#define D_MODEL 1024
#define NHEAD   16
#define HEAD_DIM 64
#define BATCH   2
#define SEQ     2048
#define MTOT    (BATCH*SEQ)          // 4096

// ---------------- scratch (no allocations allowed) ----------------
__device__ float g_q[MTOT*D_MODEL];      // Q proj -> rope writes rounded
__device__ float g_k[MTOT*D_MODEL];      // K proj -> rope writes rounded
__device__ float g_vt[D_MODEL*MTOT];     // V proj, TRANSPOSED [d][m], pre-rounded
__device__ float g_ctx[MTOT*D_MODEL];    // attention out, pre-rounded
__device__ float g_xr[MTOT*D_MODEL];     // x pre-rounded
__device__ float g_wq[D_MODEL*D_MODEL];
__device__ float g_wk[D_MODEL*D_MODEL];
__device__ float g_wv[D_MODEL*D_MODEL];
__device__ float g_wo[D_MODEL*D_MODEL];

// ---------------- helpers ----------------
__device__ __forceinline__ uint32_t f2t(float x) {
    uint32_t u;
    asm("cvt.rna.tf32.f32 %0, %1;" : "=r"(u) : "f"(x));
    return u;
}
__device__ __forceinline__ float f2tf(float x) { return __uint_as_float(f2t(x)); }

__device__ __forceinline__ void mma8(float4& d,
                                     uint32_t a0, uint32_t a1, uint32_t a2, uint32_t a3,
                                     uint32_t b0, uint32_t b1) {
    asm volatile(
        "mma.sync.aligned.m16n8k8.row.col.f32.tf32.tf32.f32 "
        "{%0,%1,%2,%3},{%4,%5,%6,%7},{%8,%9},{%0,%1,%2,%3};"
        : "+f"(d.x), "+f"(d.y), "+f"(d.z), "+f"(d.w)
        : "r"(a0), "r"(a1), "r"(a2), "r"(a3), "r"(b0), "r"(b1));
}

__device__ __forceinline__ void ldsm4(uint32_t& r0, uint32_t& r1,
                                      uint32_t& r2, uint32_t& r3, uint32_t addr) {
    asm volatile("ldmatrix.sync.aligned.m8n8.x4.shared.b16 {%0,%1,%2,%3}, [%4];"
                 : "=r"(r0), "=r"(r1), "=r"(r2), "=r"(r3) : "r"(addr));
}

__device__ __forceinline__ void cpa16(uint32_t dst_smem, const void* src) {
    asm volatile("cp.async.cg.shared.global [%0], [%1], 16;"
                 :: "r"(dst_smem), "l"(src));
}
#define CPA_COMMIT() asm volatile("cp.async.commit_group;" ::: "memory")
#define CPA_WAIT(n)  asm volatile("cp.async.wait_group %0;" :: "n"(n) : "memory")

// =================================================================
// Pre-round x and the four weight matrices to tf32 (rna) once.
// =================================================================
__global__ void preround_kernel(const float* __restrict__ x,
                                const float* __restrict__ Wq,
                                const float* __restrict__ Wk,
                                const float* __restrict__ Wv,
                                const float* __restrict__ Wo)
{
    int i = blockIdx.x * blockDim.x + threadIdx.x;   // float4 index
    const int NX = MTOT * D_MODEL / 4;
    const int NW = D_MODEL * D_MODEL / 4;
    if (i < NX) {
        float4 v = ((const float4*)x)[i];
        ((float4*)g_xr)[i] = make_float4(f2tf(v.x), f2tf(v.y), f2tf(v.z), f2tf(v.w));
    }
    if (i < NW) {
        float4 v = ((const float4*)Wq)[i];
        ((float4*)g_wq)[i] = make_float4(f2tf(v.x), f2tf(v.y), f2tf(v.z), f2tf(v.w));
        v = ((const float4*)Wk)[i];
        ((float4*)g_wk)[i] = make_float4(f2tf(v.x), f2tf(v.y), f2tf(v.z), f2tf(v.w));
        v = ((const float4*)Wv)[i];
        ((float4*)g_wv)[i] = make_float4(f2tf(v.x), f2tf(v.y), f2tf(v.z), f2tf(v.w));
        v = ((const float4*)Wo)[i];
        ((float4*)g_wo)[i] = make_float4(f2tf(v.x), f2tf(v.y), f2tf(v.z), f2tf(v.w));
    }
}

// =================================================================
// tf32 GEMM (fused over gridDim.z), pre-rounded operands.
// z==2 (V projection): epilogue writes ROUNDED + TRANSPOSED to Ct[d][m].
// =================================================================
#define GSA 20   // smem row stride (words)

__global__ __launch_bounds__(256, 2)
void gemm3_tf32(const float* __restrict__ A,
                const float* __restrict__ W0, const float* __restrict__ W1,
                const float* __restrict__ W2,
                const float* __restrict__ B0, const float* __restrict__ B1,
                const float* __restrict__ B2,
                float* __restrict__ C0, float* __restrict__ C1,
                float* __restrict__ C2t,
                int M, int N, int K)
{
    __shared__ uint32_t sA[2][128 * GSA];
    __shared__ uint32_t sB[2][128 * GSA];

    const int z = blockIdx.z;
    const float* W    = (z == 0) ? W0 : (z == 1) ? W1 : W2;
    const float* bias = (z == 0) ? B0 : (z == 1) ? B1 : B2;

    const int tid  = threadIdx.x;
    const int lane = tid & 31;
    const int warp = tid >> 5;
    const int wm   = warp >> 2;
    const int wn   = warp & 3;
    const int m0   = blockIdx.y * 128;
    const int n0   = blockIdx.x * 128;

    const int r0 = tid >> 2;
    const int c4 = (tid & 3) * 4;

    const int aRow = lane & 15;
    const int aCol = (lane >> 4) * 4;
    const int bRow = (lane & 7) + ((lane >> 4) * 8);
    const int bCol = ((lane >> 3) & 1) * 4;

    const uint32_t sA0 = (uint32_t)__cvta_generic_to_shared(&sA[0][0]);
    const uint32_t sA1 = (uint32_t)__cvta_generic_to_shared(&sA[1][0]);
    const uint32_t sB0 = (uint32_t)__cvta_generic_to_shared(&sB[0][0]);
    const uint32_t sB1 = (uint32_t)__cvta_generic_to_shared(&sB[1][0]);

    float4 pa0, pa1, pb0, pb1;

    pa0 = *(const float4*)&A[(size_t)(m0 + r0     ) * K + c4];
    pa1 = *(const float4*)&A[(size_t)(m0 + r0 + 64) * K + c4];
    pb0 = *(const float4*)&W[(size_t)(n0 + r0     ) * K + c4];
    pb1 = *(const float4*)&W[(size_t)(n0 + r0 + 64) * K + c4];
    *(float4*)&sA[0][ r0       * GSA + c4] = pa0;
    *(float4*)&sA[0][(r0 + 64) * GSA + c4] = pa1;
    *(float4*)&sB[0][ r0       * GSA + c4] = pb0;
    *(float4*)&sB[0][(r0 + 64) * GSA + c4] = pb1;
    __syncthreads();

    float4 acc[4][4] = {};
    const int nIter = K / 16;

    for (int it = 0; it < nIter; it++) {
        if (it + 1 < nIter) {
            int k0 = (it + 1) * 16;
            pa0 = *(const float4*)&A[(size_t)(m0 + r0     ) * K + k0 + c4];
            pa1 = *(const float4*)&A[(size_t)(m0 + r0 + 64) * K + k0 + c4];
            pb0 = *(const float4*)&W[(size_t)(n0 + r0     ) * K + k0 + c4];
            pb1 = *(const float4*)&W[(size_t)(n0 + r0 + 64) * K + k0 + c4];
        }
        const uint32_t cAu = (it & 1) ? sA1 : sA0;
        const uint32_t cBu = (it & 1) ? sB1 : sB0;

        #pragma unroll
        for (int ks = 0; ks < 16; ks += 8) {
            uint32_t af[4][4], bf[4][2];
            #pragma unroll
            for (int mt = 0; mt < 4; mt++) {
                uint32_t addr = cAu + 4u * ((wm * 64 + mt * 16 + aRow) * GSA + ks + aCol);
                ldsm4(af[mt][0], af[mt][1], af[mt][2], af[mt][3], addr);
            }
            #pragma unroll
            for (int t = 0; t < 2; t++) {
                uint32_t addr = cBu + 4u * ((wn * 32 + t * 16 + bRow) * GSA + ks + bCol);
                ldsm4(bf[2*t][0], bf[2*t][1], bf[2*t+1][0], bf[2*t+1][1], addr);
            }
            #pragma unroll
            for (int mt = 0; mt < 4; mt++)
                #pragma unroll
                for (int nt = 0; nt < 4; nt++)
                    mma8(acc[mt][nt], af[mt][0], af[mt][1], af[mt][2], af[mt][3],
                         bf[nt][0], bf[nt][1]);
        }

        if (it + 1 < nIter) {
            int bsel = (it + 1) & 1;
            *(float4*)&sA[bsel][ r0       * GSA + c4] = pa0;
            *(float4*)&sA[bsel][(r0 + 64) * GSA + c4] = pa1;
            *(float4*)&sB[bsel][ r0       * GSA + c4] = pb0;
            *(float4*)&sB[bsel][(r0 + 64) * GSA + c4] = pb1;
        }
        __syncthreads();
    }

    if (z == 2) {
        #pragma unroll
        for (int nt = 0; nt < 4; nt++) {
            int col = n0 + wn * 32 + nt * 8 + 2 * (lane & 3);
            float2 bz = *(const float2*)&bias[col];
            #pragma unroll
            for (int mt = 0; mt < 4; mt++) {
                int row = m0 + wm * 64 + mt * 16 + (lane >> 2);
                C2t[(size_t) col      * M + row    ] = f2tf(acc[mt][nt].x + bz.x);
                C2t[(size_t)(col + 1) * M + row    ] = f2tf(acc[mt][nt].y + bz.y);
                C2t[(size_t) col      * M + row + 8] = f2tf(acc[mt][nt].z + bz.x);
                C2t[(size_t)(col + 1) * M + row + 8] = f2tf(acc[mt][nt].w + bz.y);
            }
        }
    } else {
        float* C = (z == 0) ? C0 : C1;
        #pragma unroll
        for (int nt = 0; nt < 4; nt++) {
            int col = n0 + wn * 32 + nt * 8 + 2 * (lane & 3);
            float2 bz = *(const float2*)&bias[col];
            #pragma unroll
            for (int mt = 0; mt < 4; mt++) {
                int row = m0 + wm * 64 + mt * 16 + (lane >> 2);
                float2 v0 = { acc[mt][nt].x + bz.x, acc[mt][nt].y + bz.y };
                float2 v1 = { acc[mt][nt].z + bz.x, acc[mt][nt].w + bz.y };
                *(float2*)&C[(size_t)row * N + col]       = v0;
                *(float2*)&C[(size_t)(row + 8) * N + col] = v1;
            }
        }
    }
}

// =================================================================
// RoPE (in-place on Q and K) — writes tf32-rounded outputs.
// =================================================================
__global__ void rope_kernel(float* __restrict__ q, float* __restrict__ k,
                            const float* __restrict__ cosp,
                            const float* __restrict__ sinp)
{
    int idx = blockIdx.x * blockDim.x + threadIdx.x;
    int d  = idx & 31;
    int h  = (idx >> 5) & (NHEAD - 1);
    int bs = idx >> 9;
    int s  = bs & (SEQ - 1);

    int base = bs * D_MODEL + h * HEAD_DIM + d;
    float c1 = cosp[s * HEAD_DIM + d];
    float s1 = sinp[s * HEAD_DIM + d];
    float c2 = cosp[s * HEAD_DIM + d + 32];
    float s2 = sinp[s * HEAD_DIM + d + 32];

    float q1 = q[base], q2 = q[base + 32];
    q[base]      = f2tf(q1 * c1 - q2 * s1);
    q[base + 32] = f2tf(q2 * c2 + q1 * s2);

    float k1 = k[base], k2 = k[base + 32];
    k[base]      = f2tf(k1 * c1 - k2 * s1);
    k[base + 32] = f2tf(k2 * c2 + k1 * s2);
}

// =================================================================
// Flash attention: tf32 mma.sync, Q fragments resident in registers,
// cp.async double-buffered K/V tiles, LDSM everywhere.
// CTA = 128 q-rows of one (b,h), 256 threads (8 warps).
// smem: sK[2], sVt[2] (64xAS each), sP (128xAS; doubles as Q staging).
// =================================================================
#define AS 68
#define NT_KV (SEQ / 64)                       // 32 tiles
#define ATTN_SMEM_WORDS ((2*64 + 2*64 + 128) * AS)
#define ATTN_SMEM_BYTES (ATTN_SMEM_WORDS * 4)  // 104448

__global__ __launch_bounds__(256, 2)
void attn_tf32(const float* __restrict__ Q, const float* __restrict__ K,
               const float* __restrict__ Vt, float* __restrict__ O)
{
    extern __shared__ uint32_t smu[];
    uint32_t* sK0 = smu;                    // [64][AS]
    uint32_t* sK1 = sK0 + 64 * AS;
    uint32_t* sV0 = sK1 + 64 * AS;          // [64][AS]  (d, s)
    uint32_t* sV1 = sV0 + 64 * AS;
    uint32_t* sP  = sV1 + 64 * AS;          // [128][AS] (q, s); Q staging at start

    const int b    = blockIdx.z;
    const int h    = blockIdx.y;
    const int qt   = blockIdx.x;
    const int tid  = threadIdx.x;
    const int lane = tid & 31;
    const int warp = tid >> 5;
    const int r    = warp * 16 + (lane >> 2);
    const int cgrp = lane & 3;

    const int lcc  = (tid & 15) * 4;        // tile col group owned by this thread

    const int qRow = warp * 16 + (lane & 15);          // a-frags (sP)
    const int qCol = (lane >> 4) * 4;
    const int kRow = (lane & 7) + ((lane >> 4) * 8);   // b-frag pairs (sK, sVt)
    const int kCol = ((lane >> 3) & 1) * 4;

    const uint32_t sKu[2] = { (uint32_t)__cvta_generic_to_shared(sK0),
                              (uint32_t)__cvta_generic_to_shared(sK1) };
    const uint32_t sVu[2] = { (uint32_t)__cvta_generic_to_shared(sV0),
                              (uint32_t)__cvta_generic_to_shared(sV1) };
    const uint32_t sPu    = (uint32_t)__cvta_generic_to_shared(sP);

    const float* Qb  = Q  + ((size_t)(b * SEQ + qt * 128) * D_MODEL + h * 64);
    const float* Kb  = K  + ((size_t)(b * SEQ) * D_MODEL + h * 64);
    const float* Vtb = Vt + ((size_t)(h * 64) * MTOT + b * SEQ);

    // row indices this thread stages (same for K and Vt)
    const int srow0 = tid >> 4;             // rows 0..15, +16 per i

    // ---- issue cp.async for tiles 0 and 1 ----
    #pragma unroll
    for (int i = 0; i < 4; i++) {
        int row = srow0 + i * 16;
        cpa16(sKu[0] + 4u * (row * AS + lcc), &Kb [(size_t)row * D_MODEL + lcc]);
        cpa16(sVu[0] + 4u * (row * AS + lcc), &Vtb[(size_t)row * MTOT    + lcc]);
    }
    CPA_COMMIT();
    #pragma unroll
    for (int i = 0; i < 4; i++) {
        int row = srow0 + i * 16;
        cpa16(sKu[1] + 4u * (row * AS + lcc), &Kb [(size_t)(64 + row) * D_MODEL + lcc]);
        cpa16(sVu[1] + 4u * (row * AS + lcc), &Vtb[(size_t)row * MTOT + 64     + lcc]);
    }
    CPA_COMMIT();

    // ---- stage Q tile into sP, load persistent a-fragments ----
    #pragma unroll
    for (int i = 0; i < 8; i++) {
        int f   = tid + i * 256;
        int row = f >> 4;
        int cc  = (f & 15) * 4;
        *(float4*)&sP[row * AS + cc] =
            *(const float4*)&Qb[(size_t)row * D_MODEL + cc];
    }
    __syncthreads();
    uint32_t qf[8][4];
    #pragma unroll
    for (int ks = 0; ks < 8; ks++)
        ldsm4(qf[ks][0], qf[ks][1], qf[ks][2], qf[ks][3],
              sPu + 4u * (qRow * AS + ks * 8 + qCol));

    const float SC = 0.125f * 1.44269504088896340736f;  // 1/sqrt(64) * log2(e)

    float m0 = -1e30f, m1 = -1e30f, l0 = 0.f, l1 = 0.f;
    float4 oacc[8] = {};

    for (int kt = 0; kt < NT_KV; kt++) {
        const uint32_t cK = sKu[kt & 1];
        const uint32_t cV = sVu[kt & 1];
        if (kt < NT_KV - 1) { CPA_WAIT(1); } else { CPA_WAIT(0); }
        __syncthreads();   // tile kt visible to all; also retires sP reuse from prev iter

        // ---- scores = Q K^T (Q from registers) ----
        float4 s[8] = {};
        #pragma unroll
        for (int ks = 0; ks < 8; ks++) {
            int kk = ks * 8;
            uint32_t bfr[8][2];
            #pragma unroll
            for (int t = 0; t < 4; t++) {
                uint32_t addr = cK + 4u * ((t * 16 + kRow) * AS + kk + kCol);
                ldsm4(bfr[2*t][0], bfr[2*t][1], bfr[2*t+1][0], bfr[2*t+1][1], addr);
            }
            #pragma unroll
            for (int nt = 0; nt < 8; nt++)
                mma8(s[nt], qf[ks][0], qf[ks][1], qf[ks][2], qf[ks][3],
                     bfr[nt][0], bfr[nt][1]);
        }

        // ---- online softmax (base-2 domain) ----
        float rm0 = -1e30f, rm1 = -1e30f;
        #pragma unroll
        for (int nt = 0; nt < 8; nt++) {
            s[nt].x *= SC; s[nt].y *= SC;
            s[nt].z *= SC; s[nt].w *= SC;
            rm0 = fmaxf(rm0, fmaxf(s[nt].x, s[nt].y));
            rm1 = fmaxf(rm1, fmaxf(s[nt].z, s[nt].w));
        }
        rm0 = fmaxf(rm0, __shfl_xor_sync(0xffffffff, rm0, 1));
        rm0 = fmaxf(rm0, __shfl_xor_sync(0xffffffff, rm0, 2));
        rm1 = fmaxf(rm1, __shfl_xor_sync(0xffffffff, rm1, 1));
        rm1 = fmaxf(rm1, __shfl_xor_sync(0xffffffff, rm1, 2));

        float mn0 = fmaxf(m0, rm0);
        float mn1 = fmaxf(m1, rm1);
        float al0 = exp2f(m0 - mn0);
        float al1 = exp2f(m1 - mn1);
        m0 = mn0; m1 = mn1;

        float rs0 = 0.f, rs1 = 0.f;
        #pragma unroll
        for (int nt = 0; nt < 8; nt++) {
            float px = exp2f(s[nt].x - mn0);
            float py = exp2f(s[nt].y - mn0);
            float pz = exp2f(s[nt].z - mn1);
            float pw = exp2f(s[nt].w - mn1);
            rs0 += px + py;
            rs1 += pz + pw;
            int col = nt * 8 + 2 * cgrp;
            uint2 u0 = { f2t(px), f2t(py) };
            uint2 u1 = { f2t(pz), f2t(pw) };
            *(uint2*)&sP[ r      * AS + col] = u0;
            *(uint2*)&sP[(r + 8) * AS + col] = u1;
        }
        rs0 += __shfl_xor_sync(0xffffffff, rs0, 1);
        rs0 += __shfl_xor_sync(0xffffffff, rs0, 2);
        rs1 += __shfl_xor_sync(0xffffffff, rs1, 1);
        rs1 += __shfl_xor_sync(0xffffffff, rs1, 2);

        l0 = l0 * al0 + rs0;
        l1 = l1 * al1 + rs1;

        #pragma unroll
        for (int nt = 0; nt < 8; nt++) {
            oacc[nt].x *= al0; oacc[nt].y *= al0;
            oacc[nt].z *= al1; oacc[nt].w *= al1;
        }
        __syncwarp();   // sP writes visible within warp (a-frags read own rows only)

        // ---- oacc += P @ V  (b-frags from transposed V) ----
        #pragma unroll
        for (int ks = 0; ks < 8; ks++) {
            int kk = ks * 8;
            uint32_t a0, a1, a2, a3;
            ldsm4(a0, a1, a2, a3, sPu + 4u * (qRow * AS + kk + qCol));
            uint32_t bfr[8][2];
            #pragma unroll
            for (int t = 0; t < 4; t++) {
                uint32_t addr = cV + 4u * ((t * 16 + kRow) * AS + kk + kCol);
                ldsm4(bfr[2*t][0], bfr[2*t][1], bfr[2*t+1][0], bfr[2*t+1][1], addr);
            }
            #pragma unroll
            for (int nt = 0; nt < 8; nt++)
                mma8(oacc[nt], a0, a1, a2, a3, bfr[nt][0], bfr[nt][1]);
        }
        __syncthreads();   // all warps done with buffer (kt&1) before refill

        // ---- issue cp.async for tile kt+2 into the just-freed buffer ----
        if (kt + 2 < NT_KV) {
            const float* Ktn = Kb  + (size_t)((kt + 2) * 64) * D_MODEL;
            const float* Vtn = Vtb + (kt + 2) * 64;
            #pragma unroll
            for (int i = 0; i < 4; i++) {
                int row = srow0 + i * 16;
                cpa16(cK + 4u * (row * AS + lcc), &Ktn[(size_t)row * D_MODEL + lcc]);
                cpa16(cV + 4u * (row * AS + lcc), &Vtn[(size_t)row * MTOT    + lcc]);
            }
        }
        CPA_COMMIT();   // commit every iter (possibly empty) to keep group count aligned
    }

    // ---- epilogue: normalize + pre-round for the O projection ----
    float inv0 = 1.f / l0;
    float inv1 = 1.f / l1;
    float* Ob = O + ((size_t)(b * SEQ + qt * 128) * D_MODEL + h * 64);
    #pragma unroll
    for (int nt = 0; nt < 8; nt++) {
        int col = nt * 8 + 2 * cgrp;
        float2 v0 = { f2tf(oacc[nt].x * inv0), f2tf(oacc[nt].y * inv0) };
        float2 v1 = { f2tf(oacc[nt].z * inv1), f2tf(oacc[nt].w * inv1) };
        *(float2*)&Ob[(size_t) r      * D_MODEL + col] = v0;
        *(float2*)&Ob[(size_t)(r + 8) * D_MODEL + col] = v1;
    }
}

// =================================================================
extern "C" void kernel_launch(void* const* d_in, const int* in_sizes, int n_in,
                              void* d_out, int out_size)
{
    const float* x    = (const float*)d_in[0];
    const float* cosp = (const float*)d_in[1];
    const float* sinp = (const float*)d_in[2];
    const float* Wq   = (const float*)d_in[3];
    const float* bq   = (const float*)d_in[4];
    const float* Wk   = (const float*)d_in[5];
    const float* bk   = (const float*)d_in[6];
    const float* Wv   = (const float*)d_in[7];
    const float* bv   = (const float*)d_in[8];
    const float* Wo   = (const float*)d_in[9];
    const float* bo   = (const float*)d_in[10];
    float* out = (float*)d_out;

    float *q, *k, *vt, *ctx, *xr, *wq, *wk, *wv, *wo;
    cudaGetSymbolAddress((void**)&q,   g_q);
    cudaGetSymbolAddress((void**)&k,   g_k);
    cudaGetSymbolAddress((void**)&vt,  g_vt);
    cudaGetSymbolAddress((void**)&ctx, g_ctx);
    cudaGetSymbolAddress((void**)&xr,  g_xr);
    cudaGetSymbolAddress((void**)&wq,  g_wq);
    cudaGetSymbolAddress((void**)&wk,  g_wk);
    cudaGetSymbolAddress((void**)&wv,  g_wv);
    cudaGetSymbolAddress((void**)&wo,  g_wo);

    preround_kernel<<<(MTOT * D_MODEL / 4 + 255) / 256, 256>>>(x, Wq, Wk, Wv, Wo);

    dim3 g3(D_MODEL / 128, MTOT / 128, 3);   // (8, 32, 3)
    gemm3_tf32<<<g3, 256>>>(xr, wq, wk, wv, bq, bk, bv, q, k, vt,
                            MTOT, D_MODEL, D_MODEL);

    rope_kernel<<<(MTOT * NHEAD * 32) / 256, 256>>>(q, k, cosp, sinp);

    cudaFuncSetAttribute(attn_tf32,
                         cudaFuncAttributeMaxDynamicSharedMemorySize,
                         ATTN_SMEM_BYTES);
    attn_tf32<<<dim3(SEQ / 128, NHEAD, BATCH), 256, ATTN_SMEM_BYTES>>>(q, k, vt, ctx);

    dim3 g1(D_MODEL / 128, MTOT / 128, 1);
    gemm3_tf32<<<g1, 256>>>(ctx, wo, wo, wo, bo, bo, bo, out, out, out,
                            MTOT, D_MODEL, D_MODEL);
}

// round 11
// speedup vs baseline: 11.2856x; 1.8011x over previous
#include <cuda_runtime.h>
#include <cuda_fp16.h>
#include <math.h>
#include <stdint.h>

#define D_MODEL 1024
#define NHEAD   16
#define HEAD_DIM 64
#define BATCH   2
#define SEQ     2048
#define MTOT    (BATCH*SEQ)          // 4096

// ---------------- scratch (no allocations allowed) ----------------
__device__ float  g_q [MTOT*D_MODEL];     // Q proj f32 (pre-rope)
__device__ float  g_k [MTOT*D_MODEL];     // K proj f32 (pre-rope)
__device__ __half g_qh[MTOT*D_MODEL];     // rope out, half
__device__ __half g_kh[MTOT*D_MODEL];
__device__ __half g_vth[D_MODEL*MTOT];    // V proj TRANSPOSED [d][m], half
__device__ __half g_ctxh[MTOT*D_MODEL];   // attention out, half
__device__ __half g_xh [MTOT*D_MODEL];    // x -> half
__device__ __half g_wqh[D_MODEL*D_MODEL];
__device__ __half g_wkh[D_MODEL*D_MODEL];
__device__ __half g_wvh[D_MODEL*D_MODEL];
__device__ __half g_woh[D_MODEL*D_MODEL];

// ---------------- helpers ----------------
__device__ __forceinline__ uint32_t pk2(float a, float b) {
    __half2 h = __floats2half2_rn(a, b);
    return *(uint32_t*)&h;
}

__device__ __forceinline__ void mma16(float4& d, const uint32_t a[4],
                                      uint32_t b0, uint32_t b1) {
    asm volatile(
        "mma.sync.aligned.m16n8k16.row.col.f32.f16.f16.f32 "
        "{%0,%1,%2,%3},{%4,%5,%6,%7},{%8,%9},{%0,%1,%2,%3};"
        : "+f"(d.x), "+f"(d.y), "+f"(d.z), "+f"(d.w)
        : "r"(a[0]), "r"(a[1]), "r"(a[2]), "r"(a[3]), "r"(b0), "r"(b1));
}

__device__ __forceinline__ void ldsm4(uint32_t& r0, uint32_t& r1,
                                      uint32_t& r2, uint32_t& r3, uint32_t addr) {
    asm volatile("ldmatrix.sync.aligned.m8n8.x4.shared.b16 {%0,%1,%2,%3}, [%4];"
                 : "=r"(r0), "=r"(r1), "=r"(r2), "=r"(r3) : "r"(addr));
}

__device__ __forceinline__ void cpa16(uint32_t dst_smem, const void* src) {
    asm volatile("cp.async.cg.shared.global [%0], [%1], 16;"
                 :: "r"(dst_smem), "l"(src));
}
#define CPA_COMMIT() asm volatile("cp.async.commit_group;" ::: "memory")
#define CPA_WAIT(n)  asm volatile("cp.async.wait_group %0;" :: "n"(n) : "memory")

// =================================================================
// Convert x and the four weight matrices to fp16 (rn) once.
// =================================================================
__global__ void tohalf_kernel(const float* __restrict__ x,
                              const float* __restrict__ Wq,
                              const float* __restrict__ Wk,
                              const float* __restrict__ Wv,
                              const float* __restrict__ Wo)
{
    int i = blockIdx.x * blockDim.x + threadIdx.x;   // float4 index
    const int NX = MTOT * D_MODEL / 4;
    const int NW = D_MODEL * D_MODEL / 4;
    if (i < NX) {
        float4 v = ((const float4*)x)[i];
        ((uint2*)g_xh)[i] = make_uint2(pk2(v.x, v.y), pk2(v.z, v.w));
    }
    if (i < NW) {
        float4 v = ((const float4*)Wq)[i];
        ((uint2*)g_wqh)[i] = make_uint2(pk2(v.x, v.y), pk2(v.z, v.w));
        v = ((const float4*)Wk)[i];
        ((uint2*)g_wkh)[i] = make_uint2(pk2(v.x, v.y), pk2(v.z, v.w));
        v = ((const float4*)Wv)[i];
        ((uint2*)g_wvh)[i] = make_uint2(pk2(v.x, v.y), pk2(v.z, v.w));
        v = ((const float4*)Wo)[i];
        ((uint2*)g_woh)[i] = make_uint2(pk2(v.x, v.y), pk2(v.z, v.w));
    }
}

// =================================================================
// fp16 GEMM (fused over gridDim.z):  C = A @ W^T + b, f32 accumulate.
// 128x128 tile, BK=32 halves, 256 threads (8 warps 2x4), warp 64x32.
// cp.async double-buffered staging; ldmatrix fragments.
// z==2 (V projection): epilogue writes half TRANSPOSED to C2t[d][m].
// =================================================================
#define GSH 40   // smem row stride (halves) — conflict-free (20-word rows)

__global__ __launch_bounds__(256, 2)
void gemm3_f16(const __half* __restrict__ A,
               const __half* __restrict__ W0, const __half* __restrict__ W1,
               const __half* __restrict__ W2,
               const float* __restrict__ B0, const float* __restrict__ B1,
               const float* __restrict__ B2,
               float* __restrict__ C0, float* __restrict__ C1,
               __half* __restrict__ C2t,
               int M, int N, int K)
{
    __shared__ __half sA[2][128 * GSH];
    __shared__ __half sB[2][128 * GSH];

    const int z = blockIdx.z;
    const __half* W   = (z == 0) ? W0 : (z == 1) ? W1 : W2;
    const float* bias = (z == 0) ? B0 : (z == 1) ? B1 : B2;

    const int tid  = threadIdx.x;
    const int lane = tid & 31;
    const int warp = tid >> 5;
    const int wm   = warp >> 2;
    const int wn   = warp & 3;
    const int m0   = blockIdx.y * 128;
    const int n0   = blockIdx.x * 128;

    // cp.async assignments: row pair + 16B chunk
    const int srow  = tid >> 2;          // 0..63 (+64 second)
    const int schk  = (tid & 3) * 8;     // halves offset 0,8,16,24

    // ldmatrix lane coords (identical mapping to validated tf32 version)
    const int aRow = lane & 15;
    const int aChk = (lane >> 4) * 8;                 // halves
    const int bRow = (lane & 7) + ((lane >> 4) * 8);
    const int bChk = ((lane >> 3) & 1) * 8;           // halves

    const uint32_t sAu[2] = { (uint32_t)__cvta_generic_to_shared(&sA[0][0]),
                              (uint32_t)__cvta_generic_to_shared(&sA[1][0]) };
    const uint32_t sBu[2] = { (uint32_t)__cvta_generic_to_shared(&sB[0][0]),
                              (uint32_t)__cvta_generic_to_shared(&sB[1][0]) };

    const int nIter = K / 32;            // 32

    // preload tiles 0 and 1
    #pragma unroll
    for (int t = 0; t < 2; t++) {
        int k0 = t * 32;
        #pragma unroll
        for (int i = 0; i < 2; i++) {
            int row = srow + i * 64;
            cpa16(sAu[t] + 2u * (row * GSH + schk),
                  &A[(size_t)(m0 + row) * K + k0 + schk]);
            cpa16(sBu[t] + 2u * (row * GSH + schk),
                  &W[(size_t)(n0 + row) * K + k0 + schk]);
        }
        CPA_COMMIT();
    }

    float4 acc[4][4] = {};

    for (int it = 0; it < nIter; it++) {
        if (it < nIter - 1) { CPA_WAIT(1); } else { CPA_WAIT(0); }
        __syncthreads();
        const uint32_t cAu = sAu[it & 1];
        const uint32_t cBu = sBu[it & 1];

        #pragma unroll
        for (int ks = 0; ks < 2; ks++) {
            int kk = ks * 16;
            uint32_t af[4][4], bf[4][2];
            #pragma unroll
            for (int mt = 0; mt < 4; mt++)
                ldsm4(af[mt][0], af[mt][1], af[mt][2], af[mt][3],
                      cAu + 2u * ((wm * 64 + mt * 16 + aRow) * GSH + kk + aChk));
            #pragma unroll
            for (int t = 0; t < 2; t++)
                ldsm4(bf[2*t][0], bf[2*t][1], bf[2*t+1][0], bf[2*t+1][1],
                      cBu + 2u * ((wn * 32 + t * 16 + bRow) * GSH + kk + bChk));
            #pragma unroll
            for (int mt = 0; mt < 4; mt++)
                #pragma unroll
                for (int nt = 0; nt < 4; nt++)
                    mma16(acc[mt][nt], af[mt], bf[nt][0], bf[nt][1]);
        }
        __syncthreads();

        if (it + 2 < nIter) {
            int k0 = (it + 2) * 32;
            #pragma unroll
            for (int i = 0; i < 2; i++) {
                int row = srow + i * 64;
                cpa16(cAu + 2u * (row * GSH + schk),
                      &A[(size_t)(m0 + row) * K + k0 + schk]);
                cpa16(cBu + 2u * (row * GSH + schk),
                      &W[(size_t)(n0 + row) * K + k0 + schk]);
            }
        }
        CPA_COMMIT();
    }

    // epilogue + bias (f32)
    if (z == 2) {
        #pragma unroll
        for (int nt = 0; nt < 4; nt++) {
            int col = n0 + wn * 32 + nt * 8 + 2 * (lane & 3);
            float2 bz = *(const float2*)&bias[col];
            #pragma unroll
            for (int mt = 0; mt < 4; mt++) {
                int row = m0 + wm * 64 + mt * 16 + (lane >> 2);
                C2t[(size_t) col      * M + row    ] = __float2half_rn(acc[mt][nt].x + bz.x);
                C2t[(size_t)(col + 1) * M + row    ] = __float2half_rn(acc[mt][nt].y + bz.y);
                C2t[(size_t) col      * M + row + 8] = __float2half_rn(acc[mt][nt].z + bz.x);
                C2t[(size_t)(col + 1) * M + row + 8] = __float2half_rn(acc[mt][nt].w + bz.y);
            }
        }
    } else {
        float* C = (z == 0) ? C0 : C1;
        #pragma unroll
        for (int nt = 0; nt < 4; nt++) {
            int col = n0 + wn * 32 + nt * 8 + 2 * (lane & 3);
            float2 bz = *(const float2*)&bias[col];
            #pragma unroll
            for (int mt = 0; mt < 4; mt++) {
                int row = m0 + wm * 64 + mt * 16 + (lane >> 2);
                float2 v0 = { acc[mt][nt].x + bz.x, acc[mt][nt].y + bz.y };
                float2 v1 = { acc[mt][nt].z + bz.x, acc[mt][nt].w + bz.y };
                *(float2*)&C[(size_t)row * N + col]       = v0;
                *(float2*)&C[(size_t)(row + 8) * N + col] = v1;
            }
        }
    }
}

// =================================================================
// RoPE: reads f32 Q/K projections, writes half Q/K.
// =================================================================
__global__ void rope_kernel(const float* __restrict__ q, const float* __restrict__ k,
                            __half* __restrict__ qh, __half* __restrict__ kh,
                            const float* __restrict__ cosp,
                            const float* __restrict__ sinp)
{
    int idx = blockIdx.x * blockDim.x + threadIdx.x;
    int d  = idx & 31;
    int h  = (idx >> 5) & (NHEAD - 1);
    int bs = idx >> 9;
    int s  = bs & (SEQ - 1);

    int base = bs * D_MODEL + h * HEAD_DIM + d;
    float c1 = cosp[s * HEAD_DIM + d];
    float s1 = sinp[s * HEAD_DIM + d];
    float c2 = cosp[s * HEAD_DIM + d + 32];
    float s2 = sinp[s * HEAD_DIM + d + 32];

    float q1 = q[base], q2 = q[base + 32];
    qh[base]      = __float2half_rn(q1 * c1 - q2 * s1);
    qh[base + 32] = __float2half_rn(q2 * c2 + q1 * s2);

    float k1 = k[base], k2 = k[base + 32];
    kh[base]      = __float2half_rn(k1 * c1 - k2 * s1);
    kh[base + 32] = __float2half_rn(k2 * c2 + k1 * s2);
}

// =================================================================
// Flash attention, fp16 m16n8k16: Q frags in registers, cp.async
// double-buffered K/V, LDSM everywhere, exp2-domain softmax.
// CTA = 128 q-rows of one (b,h), 256 threads (8 warps).
// =================================================================
#define PS 72                                   // smem row stride (halves)
#define NT_KV (SEQ / 64)                        // 32 tiles
#define ATTN_SMEM_HALVES ((4*64 + 128) * PS)    // K0,K1,V0,V1 + P
#define ATTN_SMEM_BYTES  (ATTN_SMEM_HALVES * 2) // 55296

__global__ __launch_bounds__(256, 2)
void attn_f16(const __half* __restrict__ Q, const __half* __restrict__ K,
              const __half* __restrict__ Vt, __half* __restrict__ O)
{
    extern __shared__ __half smh[];
    __half* sK0 = smh;                    // [64][PS]  (s, d)
    __half* sK1 = sK0 + 64 * PS;
    __half* sV0 = sK1 + 64 * PS;          // [64][PS]  (d, s)
    __half* sV1 = sV0 + 64 * PS;
    __half* sP  = sV1 + 64 * PS;          // [128][PS] (q, s); Q staging first

    const int b    = blockIdx.z;
    const int h    = blockIdx.y;
    const int qt   = blockIdx.x;
    const int tid  = threadIdx.x;
    const int lane = tid & 31;
    const int warp = tid >> 5;
    const int r    = warp * 16 + (lane >> 2);
    const int cgrp = lane & 3;

    // cp.async: 8 chunks/row, 32 row-threads
    const int srow = tid >> 3;             // 0..31 (+32 second)
    const int schk = (tid & 7) * 8;        // halves 0..56

    // ldmatrix lane coords
    const int qRow = warp * 16 + (lane & 15);          // a-frags (sP)
    const int qChk = (lane >> 4) * 8;
    const int kRow = (lane & 7) + ((lane >> 4) * 8);   // b-frag pairs (sK, sV)
    const int kChk = ((lane >> 3) & 1) * 8;

    const uint32_t sKu[2] = { (uint32_t)__cvta_generic_to_shared(sK0),
                              (uint32_t)__cvta_generic_to_shared(sK1) };
    const uint32_t sVu[2] = { (uint32_t)__cvta_generic_to_shared(sV0),
                              (uint32_t)__cvta_generic_to_shared(sV1) };
    const uint32_t sPu    = (uint32_t)__cvta_generic_to_shared(sP);

    const __half* Qb  = Q  + ((size_t)(b * SEQ + qt * 128) * D_MODEL + h * 64);
    const __half* Kb  = K  + ((size_t)(b * SEQ) * D_MODEL + h * 64);
    const __half* Vtb = Vt + ((size_t)(h * 64) * MTOT + b * SEQ);

    // ---- issue cp.async for tiles 0 and 1 ----
    #pragma unroll
    for (int t = 0; t < 2; t++) {
        #pragma unroll
        for (int i = 0; i < 2; i++) {
            int row = srow + i * 32;
            cpa16(sKu[t] + 2u * (row * PS + schk),
                  &Kb [(size_t)(t * 64 + row) * D_MODEL + schk]);
            cpa16(sVu[t] + 2u * (row * PS + schk),
                  &Vtb[(size_t)row * MTOT + t * 64 + schk]);
        }
        CPA_COMMIT();
    }

    // ---- stage Q tile into sP, hoist a-fragments ----
    #pragma unroll
    for (int i = 0; i < 4; i++) {
        int f   = tid + i * 256;           // uint4 index: 8 per row
        int row = f >> 3;
        int cc  = (f & 7) * 8;
        *(uint4*)&sP[row * PS + cc] = *(const uint4*)&Qb[(size_t)row * D_MODEL + cc];
    }
    __syncthreads();
    uint32_t qf[4][4];
    #pragma unroll
    for (int ks = 0; ks < 4; ks++)
        ldsm4(qf[ks][0], qf[ks][1], qf[ks][2], qf[ks][3],
              sPu + 2u * (qRow * PS + ks * 16 + qChk));

    const float SC = 0.125f * 1.44269504088896340736f;  // 1/sqrt(64)*log2(e)

    float m0 = -1e30f, m1 = -1e30f, l0 = 0.f, l1 = 0.f;
    float4 oacc[8] = {};

    for (int kt = 0; kt < NT_KV; kt++) {
        const uint32_t cK = sKu[kt & 1];
        const uint32_t cV = sVu[kt & 1];
        if (kt < NT_KV - 1) { CPA_WAIT(1); } else { CPA_WAIT(0); }
        __syncthreads();

        // ---- scores = Q K^T ----
        float4 s[8] = {};
        #pragma unroll
        for (int ks = 0; ks < 4; ks++) {
            int kk = ks * 16;
            uint32_t bfr[8][2];
            #pragma unroll
            for (int t = 0; t < 4; t++)
                ldsm4(bfr[2*t][0], bfr[2*t][1], bfr[2*t+1][0], bfr[2*t+1][1],
                      cK + 2u * ((t * 16 + kRow) * PS + kk + kChk));
            #pragma unroll
            for (int nt = 0; nt < 8; nt++)
                mma16(s[nt], qf[ks], bfr[nt][0], bfr[nt][1]);
        }

        // ---- online softmax (base-2, scale folded into FFMA) ----
        float rm0 = -1e30f, rm1 = -1e30f;
        #pragma unroll
        for (int nt = 0; nt < 8; nt++) {
            rm0 = fmaxf(rm0, fmaxf(s[nt].x, s[nt].y));
            rm1 = fmaxf(rm1, fmaxf(s[nt].z, s[nt].w));
        }
        rm0 = fmaxf(rm0, __shfl_xor_sync(0xffffffff, rm0, 1));
        rm0 = fmaxf(rm0, __shfl_xor_sync(0xffffffff, rm0, 2));
        rm1 = fmaxf(rm1, __shfl_xor_sync(0xffffffff, rm1, 1));
        rm1 = fmaxf(rm1, __shfl_xor_sync(0xffffffff, rm1, 2));

        float mn0 = fmaxf(m0, rm0 * SC);
        float mn1 = fmaxf(m1, rm1 * SC);
        float al0 = exp2f(m0 - mn0);
        float al1 = exp2f(m1 - mn1);
        m0 = mn0; m1 = mn1;

        float rs0 = 0.f, rs1 = 0.f;
        #pragma unroll
        for (int nt = 0; nt < 8; nt++) {
            float px = exp2f(fmaf(s[nt].x, SC, -mn0));
            float py = exp2f(fmaf(s[nt].y, SC, -mn0));
            float pz = exp2f(fmaf(s[nt].z, SC, -mn1));
            float pw = exp2f(fmaf(s[nt].w, SC, -mn1));
            rs0 += px + py;
            rs1 += pz + pw;
            int col = nt * 8 + 2 * cgrp;
            *(uint32_t*)&sP[ r      * PS + col] = pk2(px, py);
            *(uint32_t*)&sP[(r + 8) * PS + col] = pk2(pz, pw);
        }
        rs0 += __shfl_xor_sync(0xffffffff, rs0, 1);
        rs0 += __shfl_xor_sync(0xffffffff, rs0, 2);
        rs1 += __shfl_xor_sync(0xffffffff, rs1, 1);
        rs1 += __shfl_xor_sync(0xffffffff, rs1, 2);

        l0 = l0 * al0 + rs0;
        l1 = l1 * al1 + rs1;

        #pragma unroll
        for (int nt = 0; nt < 8; nt++) {
            oacc[nt].x *= al0; oacc[nt].y *= al0;
            oacc[nt].z *= al1; oacc[nt].w *= al1;
        }
        __syncwarp();   // sP writes visible (warp reads own rows only)

        // ---- oacc += P @ V ----
        #pragma unroll
        for (int ks = 0; ks < 4; ks++) {
            int kk = ks * 16;
            uint32_t af[4];
            ldsm4(af[0], af[1], af[2], af[3],
                  sPu + 2u * (qRow * PS + kk + qChk));
            uint32_t bfr[8][2];
            #pragma unroll
            for (int t = 0; t < 4; t++)
                ldsm4(bfr[2*t][0], bfr[2*t][1], bfr[2*t+1][0], bfr[2*t+1][1],
                      cV + 2u * ((t * 16 + kRow) * PS + kk + kChk));
            #pragma unroll
            for (int nt = 0; nt < 8; nt++)
                mma16(oacc[nt], af, bfr[nt][0], bfr[nt][1]);
        }
        __syncthreads();   // buffer (kt&1) free before refill

        if (kt + 2 < NT_KV) {
            #pragma unroll
            for (int i = 0; i < 2; i++) {
                int row = srow + i * 32;
                cpa16(cK + 2u * (row * PS + schk),
                      &Kb [(size_t)((kt + 2) * 64 + row) * D_MODEL + schk]);
                cpa16(cV + 2u * (row * PS + schk),
                      &Vtb[(size_t)row * MTOT + (kt + 2) * 64 + schk]);
            }
        }
        CPA_COMMIT();
    }

    // ---- epilogue: normalize, write half ctx ----
    float inv0 = 1.f / l0;
    float inv1 = 1.f / l1;
    __half* Ob = O + ((size_t)(b * SEQ + qt * 128) * D_MODEL + h * 64);
    #pragma unroll
    for (int nt = 0; nt < 8; nt++) {
        int col = nt * 8 + 2 * cgrp;
        *(uint32_t*)&Ob[(size_t) r      * D_MODEL + col] =
            pk2(oacc[nt].x * inv0, oacc[nt].y * inv0);
        *(uint32_t*)&Ob[(size_t)(r + 8) * D_MODEL + col] =
            pk2(oacc[nt].z * inv1, oacc[nt].w * inv1);
    }
}

// =================================================================
extern "C" void kernel_launch(void* const* d_in, const int* in_sizes, int n_in,
                              void* d_out, int out_size)
{
    const float* x    = (const float*)d_in[0];
    const float* cosp = (const float*)d_in[1];
    const float* sinp = (const float*)d_in[2];
    const float* Wq   = (const float*)d_in[3];
    const float* bq   = (const float*)d_in[4];
    const float* Wk   = (const float*)d_in[5];
    const float* bk   = (const float*)d_in[6];
    const float* Wv   = (const float*)d_in[7];
    const float* bv   = (const float*)d_in[8];
    const float* Wo   = (const float*)d_in[9];
    const float* bo   = (const float*)d_in[10];
    float* out = (float*)d_out;

    float *q, *k;
    __half *qh, *kh, *vth, *ctxh, *xh, *wqh, *wkh, *wvh, *woh;
    cudaGetSymbolAddress((void**)&q,    g_q);
    cudaGetSymbolAddress((void**)&k,    g_k);
    cudaGetSymbolAddress((void**)&qh,   g_qh);
    cudaGetSymbolAddress((void**)&kh,   g_kh);
    cudaGetSymbolAddress((void**)&vth,  g_vth);
    cudaGetSymbolAddress((void**)&ctxh, g_ctxh);
    cudaGetSymbolAddress((void**)&xh,   g_xh);
    cudaGetSymbolAddress((void**)&wqh,  g_wqh);
    cudaGetSymbolAddress((void**)&wkh,  g_wkh);
    cudaGetSymbolAddress((void**)&wvh,  g_wvh);
    cudaGetSymbolAddress((void**)&woh,  g_woh);

    tohalf_kernel<<<(MTOT * D_MODEL / 4 + 255) / 256, 256>>>(x, Wq, Wk, Wv, Wo);

    dim3 g3(D_MODEL / 128, MTOT / 128, 3);   // (8, 32, 3)
    gemm3_f16<<<g3, 256>>>(xh, wqh, wkh, wvh, bq, bk, bv, q, k, vth,
                           MTOT, D_MODEL, D_MODEL);

    rope_kernel<<<(MTOT * NHEAD * 32) / 256, 256>>>(q, k, qh, kh, cosp, sinp);

    cudaFuncSetAttribute(attn_f16,
                         cudaFuncAttributeMaxDynamicSharedMemorySize,
                         ATTN_SMEM_BYTES);
    attn_f16<<<dim3(SEQ / 128, NHEAD, BATCH), 256, ATTN_SMEM_BYTES>>>(qh, kh, vth, ctxh);

    dim3 g1(D_MODEL / 128, MTOT / 128, 1);
    gemm3_f16<<<g1, 256>>>(ctxh, woh, woh, woh, bo, bo, bo, out, out, (__half*)out,
                           MTOT, D_MODEL, D_MODEL);
}

// round 12
// speedup vs baseline: 12.0609x; 1.0687x over previous
#include <cuda_runtime.h>
#include <cuda_fp16.h>
#include <math.h>
#include <stdint.h>

#define D_MODEL 1024
#define NHEAD   16
#define HEAD_DIM 64
#define BATCH   2
#define SEQ     2048
#define MTOT    (BATCH*SEQ)          // 4096

// ---------------- scratch (no allocations allowed) ----------------
__device__ __half g_qh[MTOT*D_MODEL];     // Q proj (half) -> rope in-place
__device__ __half g_kh[MTOT*D_MODEL];
__device__ __half g_vth[D_MODEL*MTOT];    // V proj TRANSPOSED [d][m], half
__device__ __half g_ctxh[MTOT*D_MODEL];   // attention out, half
__device__ __half g_xh [MTOT*D_MODEL];    // x -> half
__device__ __half g_wqh[D_MODEL*D_MODEL];
__device__ __half g_wkh[D_MODEL*D_MODEL];
__device__ __half g_wvh[D_MODEL*D_MODEL];
__device__ __half g_woh[D_MODEL*D_MODEL];

// ---------------- helpers ----------------
__device__ __forceinline__ uint32_t pk2(float a, float b) {
    __half2 h = __floats2half2_rn(a, b);
    return *(uint32_t*)&h;
}

__device__ __forceinline__ void mma16(float4& d, const uint32_t a[4],
                                      uint32_t b0, uint32_t b1) {
    asm volatile(
        "mma.sync.aligned.m16n8k16.row.col.f32.f16.f16.f32 "
        "{%0,%1,%2,%3},{%4,%5,%6,%7},{%8,%9},{%0,%1,%2,%3};"
        : "+f"(d.x), "+f"(d.y), "+f"(d.z), "+f"(d.w)
        : "r"(a[0]), "r"(a[1]), "r"(a[2]), "r"(a[3]), "r"(b0), "r"(b1));
}

__device__ __forceinline__ void ldsm4(uint32_t& r0, uint32_t& r1,
                                      uint32_t& r2, uint32_t& r3, uint32_t addr) {
    asm volatile("ldmatrix.sync.aligned.m8n8.x4.shared.b16 {%0,%1,%2,%3}, [%4];"
                 : "=r"(r0), "=r"(r1), "=r"(r2), "=r"(r3) : "r"(addr));
}

__device__ __forceinline__ void cpa16(uint32_t dst_smem, const void* src) {
    asm volatile("cp.async.cg.shared.global [%0], [%1], 16;"
                 :: "r"(dst_smem), "l"(src));
}
#define CPA_COMMIT() asm volatile("cp.async.commit_group;" ::: "memory")
#define CPA_WAIT(n)  asm volatile("cp.async.wait_group %0;" :: "n"(n) : "memory")

// =================================================================
// Convert x and the four weight matrices to fp16 (rn) once.
// =================================================================
__global__ void tohalf_kernel(const float* __restrict__ x,
                              const float* __restrict__ Wq,
                              const float* __restrict__ Wk,
                              const float* __restrict__ Wv,
                              const float* __restrict__ Wo)
{
    int i = blockIdx.x * blockDim.x + threadIdx.x;   // float4 index
    const int NX = MTOT * D_MODEL / 4;
    const int NW = D_MODEL * D_MODEL / 4;
    if (i < NX) {
        float4 v = ((const float4*)x)[i];
        ((uint2*)g_xh)[i] = make_uint2(pk2(v.x, v.y), pk2(v.z, v.w));
    }
    if (i < NW) {
        float4 v = ((const float4*)Wq)[i];
        ((uint2*)g_wqh)[i] = make_uint2(pk2(v.x, v.y), pk2(v.z, v.w));
        v = ((const float4*)Wk)[i];
        ((uint2*)g_wkh)[i] = make_uint2(pk2(v.x, v.y), pk2(v.z, v.w));
        v = ((const float4*)Wv)[i];
        ((uint2*)g_wvh)[i] = make_uint2(pk2(v.x, v.y), pk2(v.z, v.w));
        v = ((const float4*)Wo)[i];
        ((uint2*)g_woh)[i] = make_uint2(pk2(v.x, v.y), pk2(v.z, v.w));
    }
}

// =================================================================
// fp16 GEMM (fused over gridDim.z):  C = A @ W^T + b, f32 accumulate.
// halfout: z<2 outputs are written as half (Q/K proj); else f32 (O proj).
// z==2 (V projection): epilogue writes half TRANSPOSED to C2t[d][m].
// =================================================================
#define GSH 40   // smem row stride (halves)

__global__ __launch_bounds__(256, 2)
void gemm3_f16(const __half* __restrict__ A,
               const __half* __restrict__ W0, const __half* __restrict__ W1,
               const __half* __restrict__ W2,
               const float* __restrict__ B0, const float* __restrict__ B1,
               const float* __restrict__ B2,
               float* __restrict__ C0f,
               __half* __restrict__ H0, __half* __restrict__ H1,
               __half* __restrict__ C2t,
               int halfout, int M, int N, int K)
{
    __shared__ __half sA[2][128 * GSH];
    __shared__ __half sB[2][128 * GSH];

    const int z = blockIdx.z;
    const __half* W   = (z == 0) ? W0 : (z == 1) ? W1 : W2;
    const float* bias = (z == 0) ? B0 : (z == 1) ? B1 : B2;

    const int tid  = threadIdx.x;
    const int lane = tid & 31;
    const int warp = tid >> 5;
    const int wm   = warp >> 2;
    const int wn   = warp & 3;
    const int m0   = blockIdx.y * 128;
    const int n0   = blockIdx.x * 128;

    const int srow  = tid >> 2;          // 0..63 (+64 second)
    const int schk  = (tid & 3) * 8;     // halves 0,8,16,24

    const int aRow = lane & 15;
    const int aChk = (lane >> 4) * 8;
    const int bRow = (lane & 7) + ((lane >> 4) * 8);
    const int bChk = ((lane >> 3) & 1) * 8;

    const uint32_t sAu[2] = { (uint32_t)__cvta_generic_to_shared(&sA[0][0]),
                              (uint32_t)__cvta_generic_to_shared(&sA[1][0]) };
    const uint32_t sBu[2] = { (uint32_t)__cvta_generic_to_shared(&sB[0][0]),
                              (uint32_t)__cvta_generic_to_shared(&sB[1][0]) };

    const int nIter = K / 32;

    #pragma unroll
    for (int t = 0; t < 2; t++) {
        int k0 = t * 32;
        #pragma unroll
        for (int i = 0; i < 2; i++) {
            int row = srow + i * 64;
            cpa16(sAu[t] + 2u * (row * GSH + schk),
                  &A[(size_t)(m0 + row) * K + k0 + schk]);
            cpa16(sBu[t] + 2u * (row * GSH + schk),
                  &W[(size_t)(n0 + row) * K + k0 + schk]);
        }
        CPA_COMMIT();
    }

    float4 acc[4][4] = {};

    for (int it = 0; it < nIter; it++) {
        if (it < nIter - 1) { CPA_WAIT(1); } else { CPA_WAIT(0); }
        __syncthreads();
        const uint32_t cAu = sAu[it & 1];
        const uint32_t cBu = sBu[it & 1];

        #pragma unroll
        for (int ks = 0; ks < 2; ks++) {
            int kk = ks * 16;
            uint32_t af[4][4], bf[4][2];
            #pragma unroll
            for (int mt = 0; mt < 4; mt++)
                ldsm4(af[mt][0], af[mt][1], af[mt][2], af[mt][3],
                      cAu + 2u * ((wm * 64 + mt * 16 + aRow) * GSH + kk + aChk));
            #pragma unroll
            for (int t = 0; t < 2; t++)
                ldsm4(bf[2*t][0], bf[2*t][1], bf[2*t+1][0], bf[2*t+1][1],
                      cBu + 2u * ((wn * 32 + t * 16 + bRow) * GSH + kk + bChk));
            #pragma unroll
            for (int mt = 0; mt < 4; mt++)
                #pragma unroll
                for (int nt = 0; nt < 4; nt++)
                    mma16(acc[mt][nt], af[mt], bf[nt][0], bf[nt][1]);
        }
        __syncthreads();

        if (it + 2 < nIter) {
            int k0 = (it + 2) * 32;
            #pragma unroll
            for (int i = 0; i < 2; i++) {
                int row = srow + i * 64;
                cpa16(cAu + 2u * (row * GSH + schk),
                      &A[(size_t)(m0 + row) * K + k0 + schk]);
                cpa16(cBu + 2u * (row * GSH + schk),
                      &W[(size_t)(n0 + row) * K + k0 + schk]);
            }
        }
        CPA_COMMIT();
    }

    if (z == 2) {
        #pragma unroll
        for (int nt = 0; nt < 4; nt++) {
            int col = n0 + wn * 32 + nt * 8 + 2 * (lane & 3);
            float2 bz = *(const float2*)&bias[col];
            #pragma unroll
            for (int mt = 0; mt < 4; mt++) {
                int row = m0 + wm * 64 + mt * 16 + (lane >> 2);
                C2t[(size_t) col      * M + row    ] = __float2half_rn(acc[mt][nt].x + bz.x);
                C2t[(size_t)(col + 1) * M + row    ] = __float2half_rn(acc[mt][nt].y + bz.y);
                C2t[(size_t) col      * M + row + 8] = __float2half_rn(acc[mt][nt].z + bz.x);
                C2t[(size_t)(col + 1) * M + row + 8] = __float2half_rn(acc[mt][nt].w + bz.y);
            }
        }
    } else if (halfout) {
        __half* H = (z == 0) ? H0 : H1;
        #pragma unroll
        for (int nt = 0; nt < 4; nt++) {
            int col = n0 + wn * 32 + nt * 8 + 2 * (lane & 3);
            float2 bz = *(const float2*)&bias[col];
            #pragma unroll
            for (int mt = 0; mt < 4; mt++) {
                int row = m0 + wm * 64 + mt * 16 + (lane >> 2);
                *(uint32_t*)&H[(size_t)row * N + col] =
                    pk2(acc[mt][nt].x + bz.x, acc[mt][nt].y + bz.y);
                *(uint32_t*)&H[(size_t)(row + 8) * N + col] =
                    pk2(acc[mt][nt].z + bz.x, acc[mt][nt].w + bz.y);
            }
        }
    } else {
        #pragma unroll
        for (int nt = 0; nt < 4; nt++) {
            int col = n0 + wn * 32 + nt * 8 + 2 * (lane & 3);
            float2 bz = *(const float2*)&bias[col];
            #pragma unroll
            for (int mt = 0; mt < 4; mt++) {
                int row = m0 + wm * 64 + mt * 16 + (lane >> 2);
                float2 v0 = { acc[mt][nt].x + bz.x, acc[mt][nt].y + bz.y };
                float2 v1 = { acc[mt][nt].z + bz.x, acc[mt][nt].w + bz.y };
                *(float2*)&C0f[(size_t)row * N + col]       = v0;
                *(float2*)&C0f[(size_t)(row + 8) * N + col] = v1;
            }
        }
    }
}

// =================================================================
// RoPE (in-place on half Q and K).
// =================================================================
__global__ void rope_kernel(__half* __restrict__ q, __half* __restrict__ k,
                            const float* __restrict__ cosp,
                            const float* __restrict__ sinp)
{
    int idx = blockIdx.x * blockDim.x + threadIdx.x;
    int d  = idx & 31;
    int h  = (idx >> 5) & (NHEAD - 1);
    int bs = idx >> 9;
    int s  = bs & (SEQ - 1);

    int base = bs * D_MODEL + h * HEAD_DIM + d;
    float c1 = cosp[s * HEAD_DIM + d];
    float s1 = sinp[s * HEAD_DIM + d];
    float c2 = cosp[s * HEAD_DIM + d + 32];
    float s2 = sinp[s * HEAD_DIM + d + 32];

    float q1 = __half2float(q[base]), q2 = __half2float(q[base + 32]);
    q[base]      = __float2half_rn(q1 * c1 - q2 * s1);
    q[base + 32] = __float2half_rn(q2 * c2 + q1 * s2);

    float k1 = __half2float(k[base]), k2 = __half2float(k[base + 32]);
    k[base]      = __float2half_rn(k1 * c1 - k2 * s1);
    k[base + 32] = __float2half_rn(k2 * c2 + k1 * s2);
}

// =================================================================
// Flash attention, fp16 m16n8k16: Q frags in registers, P kept in
// registers (C-frag -> A-frag identity), cp.async double-buffered K/V.
// CTA = 128 q-rows of one (b,h), 256 threads (8 warps).
// =================================================================
#define PS 72                                   // smem row stride (halves)
#define NT_KV (SEQ / 64)                        // 32 tiles
#define ATTN_SMEM_HALVES ((4*64 + 128) * PS)    // K0,K1,V0,V1 + Q staging
#define ATTN_SMEM_BYTES  (ATTN_SMEM_HALVES * 2)

__global__ __launch_bounds__(256, 2)
void attn_f16(const __half* __restrict__ Q, const __half* __restrict__ K,
              const __half* __restrict__ Vt, __half* __restrict__ O)
{
    extern __shared__ __half smh[];
    __half* sK0 = smh;                    // [64][PS]  (s, d)
    __half* sK1 = sK0 + 64 * PS;
    __half* sV0 = sK1 + 64 * PS;          // [64][PS]  (d, s)
    __half* sV1 = sV0 + 64 * PS;
    __half* sQs = sV1 + 64 * PS;          // [128][PS] Q staging (prologue only)

    const int b    = blockIdx.z;
    const int h    = blockIdx.y;
    const int qt   = blockIdx.x;
    const int tid  = threadIdx.x;
    const int lane = tid & 31;
    const int warp = tid >> 5;
    const int r    = warp * 16 + (lane >> 2);
    const int cgrp = lane & 3;
    (void)r; (void)cgrp;

    const int srow = tid >> 3;             // 0..31 (+32 second)
    const int schk = (tid & 7) * 8;        // halves 0..56

    const int qRow = warp * 16 + (lane & 15);
    const int qChk = (lane >> 4) * 8;
    const int kRow = (lane & 7) + ((lane >> 4) * 8);
    const int kChk = ((lane >> 3) & 1) * 8;

    const uint32_t sKu[2] = { (uint32_t)__cvta_generic_to_shared(sK0),
                              (uint32_t)__cvta_generic_to_shared(sK1) };
    const uint32_t sVu[2] = { (uint32_t)__cvta_generic_to_shared(sV0),
                              (uint32_t)__cvta_generic_to_shared(sV1) };
    const uint32_t sQu    = (uint32_t)__cvta_generic_to_shared(sQs);

    const __half* Qb  = Q  + ((size_t)(b * SEQ + qt * 128) * D_MODEL + h * 64);
    const __half* Kb  = K  + ((size_t)(b * SEQ) * D_MODEL + h * 64);
    const __half* Vtb = Vt + ((size_t)(h * 64) * MTOT + b * SEQ);

    // ---- issue cp.async for tiles 0 and 1 ----
    #pragma unroll
    for (int t = 0; t < 2; t++) {
        #pragma unroll
        for (int i = 0; i < 2; i++) {
            int row = srow + i * 32;
            cpa16(sKu[t] + 2u * (row * PS + schk),
                  &Kb [(size_t)(t * 64 + row) * D_MODEL + schk]);
            cpa16(sVu[t] + 2u * (row * PS + schk),
                  &Vtb[(size_t)row * MTOT + t * 64 + schk]);
        }
        CPA_COMMIT();
    }

    // ---- stage Q tile, hoist a-fragments into registers ----
    #pragma unroll
    for (int i = 0; i < 4; i++) {
        int f   = tid + i * 256;
        int row = f >> 3;
        int cc  = (f & 7) * 8;
        *(uint4*)&sQs[row * PS + cc] = *(const uint4*)&Qb[(size_t)row * D_MODEL + cc];
    }
    __syncthreads();
    uint32_t qf[4][4];
    #pragma unroll
    for (int ks = 0; ks < 4; ks++)
        ldsm4(qf[ks][0], qf[ks][1], qf[ks][2], qf[ks][3],
              sQu + 2u * (qRow * PS + ks * 16 + qChk));

    const float SC = 0.125f * 1.44269504088896340736f;  // 1/sqrt(64)*log2(e)

    float m0 = -1e30f, m1 = -1e30f, l0 = 0.f, l1 = 0.f;
    float4 oacc[8] = {};

    for (int kt = 0; kt < NT_KV; kt++) {
        const uint32_t cK = sKu[kt & 1];
        const uint32_t cV = sVu[kt & 1];
        if (kt < NT_KV - 1) { CPA_WAIT(1); } else { CPA_WAIT(0); }
        __syncthreads();

        // ---- scores = Q K^T ----
        float4 s[8] = {};
        #pragma unroll
        for (int ks = 0; ks < 4; ks++) {
            int kk = ks * 16;
            uint32_t bfr[8][2];
            #pragma unroll
            for (int t = 0; t < 4; t++)
                ldsm4(bfr[2*t][0], bfr[2*t][1], bfr[2*t+1][0], bfr[2*t+1][1],
                      cK + 2u * ((t * 16 + kRow) * PS + kk + kChk));
            #pragma unroll
            for (int nt = 0; nt < 8; nt++)
                mma16(s[nt], qf[ks], bfr[nt][0], bfr[nt][1]);
        }

        // ---- online softmax (base-2, scale folded into FFMA) ----
        float rm0 = -1e30f, rm1 = -1e30f;
        #pragma unroll
        for (int nt = 0; nt < 8; nt++) {
            rm0 = fmaxf(rm0, fmaxf(s[nt].x, s[nt].y));
            rm1 = fmaxf(rm1, fmaxf(s[nt].z, s[nt].w));
        }
        rm0 = fmaxf(rm0, __shfl_xor_sync(0xffffffff, rm0, 1));
        rm0 = fmaxf(rm0, __shfl_xor_sync(0xffffffff, rm0, 2));
        rm1 = fmaxf(rm1, __shfl_xor_sync(0xffffffff, rm1, 1));
        rm1 = fmaxf(rm1, __shfl_xor_sync(0xffffffff, rm1, 2));

        float mn0 = fmaxf(m0, rm0 * SC);
        float mn1 = fmaxf(m1, rm1 * SC);
        float al0 = exp2f(m0 - mn0);
        float al1 = exp2f(m1 - mn1);
        m0 = mn0; m1 = mn1;

        // P stays in registers: C-frag (c0,c1|c2,c3) packs to A-frag halves
        uint32_t p[8][2];
        float rs0 = 0.f, rs1 = 0.f;
        #pragma unroll
        for (int nt = 0; nt < 8; nt++) {
            float px = exp2f(fmaf(s[nt].x, SC, -mn0));
            float py = exp2f(fmaf(s[nt].y, SC, -mn0));
            float pz = exp2f(fmaf(s[nt].z, SC, -mn1));
            float pw = exp2f(fmaf(s[nt].w, SC, -mn1));
            rs0 += px + py;
            rs1 += pz + pw;
            p[nt][0] = pk2(px, py);    // row g,   k pair
            p[nt][1] = pk2(pz, pw);    // row g+8, k pair
        }
        rs0 += __shfl_xor_sync(0xffffffff, rs0, 1);
        rs0 += __shfl_xor_sync(0xffffffff, rs0, 2);
        rs1 += __shfl_xor_sync(0xffffffff, rs1, 1);
        rs1 += __shfl_xor_sync(0xffffffff, rs1, 2);

        l0 = l0 * al0 + rs0;
        l1 = l1 * al1 + rs1;

        #pragma unroll
        for (int nt = 0; nt < 8; nt++) {
            oacc[nt].x *= al0; oacc[nt].y *= al0;
            oacc[nt].z *= al1; oacc[nt].w *= al1;
        }

        // ---- oacc += P @ V  (P a-frags straight from registers) ----
        #pragma unroll
        for (int ks = 0; ks < 4; ks++) {
            int kk = ks * 16;
            uint32_t af[4] = { p[2*ks][0], p[2*ks][1], p[2*ks+1][0], p[2*ks+1][1] };
            uint32_t bfr[8][2];
            #pragma unroll
            for (int t = 0; t < 4; t++)
                ldsm4(bfr[2*t][0], bfr[2*t][1], bfr[2*t+1][0], bfr[2*t+1][1],
                      cV + 2u * ((t * 16 + kRow) * PS + kk + kChk));
            #pragma unroll
            for (int nt = 0; nt < 8; nt++)
                mma16(oacc[nt], af, bfr[nt][0], bfr[nt][1]);
        }
        __syncthreads();   // buffer (kt&1) free before refill

        if (kt + 2 < NT_KV) {
            #pragma unroll
            for (int i = 0; i < 2; i++) {
                int row = srow + i * 32;
                cpa16(cK + 2u * (row * PS + schk),
                      &Kb [(size_t)((kt + 2) * 64 + row) * D_MODEL + schk]);
                cpa16(cV + 2u * (row * PS + schk),
                      &Vtb[(size_t)row * MTOT + (kt + 2) * 64 + schk]);
            }
        }
        CPA_COMMIT();
    }

    // ---- epilogue: normalize, write half ctx ----
    const int er = warp * 16 + (lane >> 2);
    float inv0 = 1.f / l0;
    float inv1 = 1.f / l1;
    __half* Ob = O + ((size_t)(b * SEQ + qt * 128) * D_MODEL + h * 64);
    #pragma unroll
    for (int nt = 0; nt < 8; nt++) {
        int col = nt * 8 + 2 * (lane & 3);
        *(uint32_t*)&Ob[(size_t) er      * D_MODEL + col] =
            pk2(oacc[nt].x * inv0, oacc[nt].y * inv0);
        *(uint32_t*)&Ob[(size_t)(er + 8) * D_MODEL + col] =
            pk2(oacc[nt].z * inv1, oacc[nt].w * inv1);
    }
}

// =================================================================
extern "C" void kernel_launch(void* const* d_in, const int* in_sizes, int n_in,
                              void* d_out, int out_size)
{
    const float* x    = (const float*)d_in[0];
    const float* cosp = (const float*)d_in[1];
    const float* sinp = (const float*)d_in[2];
    const float* Wq   = (const float*)d_in[3];
    const float* bq   = (const float*)d_in[4];
    const float* Wk   = (const float*)d_in[5];
    const float* bk   = (const float*)d_in[6];
    const float* Wv   = (const float*)d_in[7];
    const float* bv   = (const float*)d_in[8];
    const float* Wo   = (const float*)d_in[9];
    const float* bo   = (const float*)d_in[10];
    float* out = (float*)d_out;

    __half *qh, *kh, *vth, *ctxh, *xh, *wqh, *wkh, *wvh, *woh;
    cudaGetSymbolAddress((void**)&qh,   g_qh);
    cudaGetSymbolAddress((void**)&kh,   g_kh);
    cudaGetSymbolAddress((void**)&vth,  g_vth);
    cudaGetSymbolAddress((void**)&ctxh, g_ctxh);
    cudaGetSymbolAddress((void**)&xh,   g_xh);
    cudaGetSymbolAddress((void**)&wqh,  g_wqh);
    cudaGetSymbolAddress((void**)&wkh,  g_wkh);
    cudaGetSymbolAddress((void**)&wvh,  g_wvh);
    cudaGetSymbolAddress((void**)&woh,  g_woh);

    tohalf_kernel<<<(MTOT * D_MODEL / 4 + 255) / 256, 256>>>(x, Wq, Wk, Wv, Wo);

    dim3 g3(D_MODEL / 128, MTOT / 128, 3);   // (8, 32, 3)
    gemm3_f16<<<g3, 256>>>(xh, wqh, wkh, wvh, bq, bk, bv,
                           (float*)nullptr, qh, kh, vth, 1,
                           MTOT, D_MODEL, D_MODEL);

    rope_kernel<<<(MTOT * NHEAD * 32) / 256, 256>>>(qh, kh, cosp, sinp);

    cudaFuncSetAttribute(attn_f16,
                         cudaFuncAttributeMaxDynamicSharedMemorySize,
                         ATTN_SMEM_BYTES);
    attn_f16<<<dim3(SEQ / 128, NHEAD, BATCH), 256, ATTN_SMEM_BYTES>>>(qh, kh, vth, ctxh);

    dim3 g1(D_MODEL / 128, MTOT / 128, 1);
    gemm3_f16<<<g1, 256>>>(ctxh, woh, woh, woh, bo, bo, bo,
                           out, (__half*)nullptr, (__half*)nullptr, (__half*)nullptr, 0,
                           MTOT, D_MODEL, D_MODEL);
}

// round 14
// speedup vs baseline: 12.3965x; 1.0278x over previous
#include <cuda_runtime.h>
#include <cuda_fp16.h>
#include <math.h>
#include <stdint.h>

#define D_MODEL 1024
#define NHEAD   16
#define HEAD_DIM 64
#define BATCH   2
#define SEQ     2048
#define MTOT    (BATCH*SEQ)          // 4096

// ---------------- scratch (no allocations allowed) ----------------
__device__ __half g_qh[MTOT*D_MODEL];     // Q proj (half) -> rope in-place
__device__ __half g_kh[MTOT*D_MODEL];
__device__ __half g_vth[D_MODEL*MTOT];    // V proj TRANSPOSED [d][m], half
__device__ __half g_ctxh[MTOT*D_MODEL];   // attention out, half
__device__ __half g_xh [MTOT*D_MODEL];    // x -> half
__device__ __half g_wqh[D_MODEL*D_MODEL];
__device__ __half g_wkh[D_MODEL*D_MODEL];
__device__ __half g_wvh[D_MODEL*D_MODEL];
__device__ __half g_woh[D_MODEL*D_MODEL];

// ---------------- helpers ----------------
__device__ __forceinline__ uint32_t pk2(float a, float b) {
    __half2 h = __floats2half2_rn(a, b);
    return *(uint32_t*)&h;
}

__device__ __forceinline__ void mma16(float4& d, const uint32_t a[4],
                                      uint32_t b0, uint32_t b1) {
    asm volatile(
        "mma.sync.aligned.m16n8k16.row.col.f32.f16.f16.f32 "
        "{%0,%1,%2,%3},{%4,%5,%6,%7},{%8,%9},{%0,%1,%2,%3};"
        : "+f"(d.x), "+f"(d.y), "+f"(d.z), "+f"(d.w)
        : "r"(a[0]), "r"(a[1]), "r"(a[2]), "r"(a[3]), "r"(b0), "r"(b1));
}

__device__ __forceinline__ void ldsm4(uint32_t& r0, uint32_t& r1,
                                      uint32_t& r2, uint32_t& r3, uint32_t addr) {
    asm volatile("ldmatrix.sync.aligned.m8n8.x4.shared.b16 {%0,%1,%2,%3}, [%4];"
                 : "=r"(r0), "=r"(r1), "=r"(r2), "=r"(r3) : "r"(addr));
}

__device__ __forceinline__ void cpa16(uint32_t dst_smem, const void* src) {
    asm volatile("cp.async.cg.shared.global [%0], [%1], 16;"
                 :: "r"(dst_smem), "l"(src));
}
#define CPA_COMMIT() asm volatile("cp.async.commit_group;" ::: "memory")
#define CPA_WAIT(n)  asm volatile("cp.async.wait_group %0;" :: "n"(n) : "memory")

// =================================================================
// Convert x and the four weight matrices to fp16 (rn) once.
// =================================================================
__global__ void tohalf_kernel(const float* __restrict__ x,
                              const float* __restrict__ Wq,
                              const float* __restrict__ Wk,
                              const float* __restrict__ Wv,
                              const float* __restrict__ Wo)
{
    int i = blockIdx.x * blockDim.x + threadIdx.x;   // float4 index
    const int NX = MTOT * D_MODEL / 4;
    const int NW = D_MODEL * D_MODEL / 4;
    if (i < NX) {
        float4 v = ((const float4*)x)[i];
        ((uint2*)g_xh)[i] = make_uint2(pk2(v.x, v.y), pk2(v.z, v.w));
    }
    if (i < NW) {
        float4 v = ((const float4*)Wq)[i];
        ((uint2*)g_wqh)[i] = make_uint2(pk2(v.x, v.y), pk2(v.z, v.w));
        v = ((const float4*)Wk)[i];
        ((uint2*)g_wkh)[i] = make_uint2(pk2(v.x, v.y), pk2(v.z, v.w));
        v = ((const float4*)Wv)[i];
        ((uint2*)g_wvh)[i] = make_uint2(pk2(v.x, v.y), pk2(v.z, v.w));
        v = ((const float4*)Wo)[i];
        ((uint2*)g_woh)[i] = make_uint2(pk2(v.x, v.y), pk2(v.z, v.w));
    }
}

// =================================================================
// fp16 GEMM (fused over gridDim.z), 3-stage cp.async ring,
// ONE barrier per k-iter.  C = A @ W^T + b, f32 accumulate.
// halfout: z<2 outputs written half (Q/K proj); else f32 (O proj).
// z==2 (V projection): epilogue writes half TRANSPOSED to C2t[d][m].
// =================================================================
#define GSH 40   // smem row stride (halves)
#define GEMM_BUF (128 * GSH)                    // halves per tile buffer
#define GEMM_SMEM_BYTES (6 * GEMM_BUF * 2)      // 3xA + 3xB = 61440

__global__ __launch_bounds__(256, 2)
void gemm3_f16(const __half* __restrict__ A,
               const __half* __restrict__ W0, const __half* __restrict__ W1,
               const __half* __restrict__ W2,
               const float* __restrict__ B0, const float* __restrict__ B1,
               const float* __restrict__ B2,
               float* __restrict__ C0f,
               __half* __restrict__ H0, __half* __restrict__ H1,
               __half* __restrict__ C2t,
               int halfout, int M, int N, int K)
{
    extern __shared__ __half gsm[];

    const int z = blockIdx.z;
    const __half* W   = (z == 0) ? W0 : (z == 1) ? W1 : W2;
    const float* bias = (z == 0) ? B0 : (z == 1) ? B1 : B2;

    const int tid  = threadIdx.x;
    const int lane = tid & 31;
    const int warp = tid >> 5;
    const int wm   = warp >> 2;
    const int wn   = warp & 3;
    const int m0   = blockIdx.y * 128;
    const int n0   = blockIdx.x * 128;

    const int srow  = tid >> 2;          // 0..63 (+64 second)
    const int schk  = (tid & 3) * 8;     // halves 0,8,16,24

    const int aRow = lane & 15;
    const int aChk = (lane >> 4) * 8;
    const int bRow = (lane & 7) + ((lane >> 4) * 8);
    const int bChk = ((lane >> 3) & 1) * 8;

    uint32_t sAu[3], sBu[3];
    #pragma unroll
    for (int i = 0; i < 3; i++) {
        sAu[i] = (uint32_t)__cvta_generic_to_shared(gsm + i * GEMM_BUF);
        sBu[i] = (uint32_t)__cvta_generic_to_shared(gsm + (3 + i) * GEMM_BUF);
    }

    const int nIter = K / 32;            // 32

    // preload k-iters 0 and 1
    #pragma unroll
    for (int t = 0; t < 2; t++) {
        int k0 = t * 32;
        #pragma unroll
        for (int i = 0; i < 2; i++) {
            int row = srow + i * 64;
            cpa16(sAu[t] + 2u * (row * GSH + schk),
                  &A[(size_t)(m0 + row) * K + k0 + schk]);
            cpa16(sBu[t] + 2u * (row * GSH + schk),
                  &W[(size_t)(n0 + row) * K + k0 + schk]);
        }
        CPA_COMMIT();
    }

    float4 acc[4][4] = {};
    int cur = 0, nxt2 = 2;               // ring slots: it%3, (it+2)%3

    for (int it = 0; it < nIter; it++) {
        CPA_WAIT(1);
        __syncthreads();                 // tile it visible; slot nxt2 free

        if (it + 2 < nIter) {
            int k0 = (it + 2) * 32;
            #pragma unroll
            for (int i = 0; i < 2; i++) {
                int row = srow + i * 64;
                cpa16(sAu[nxt2] + 2u * (row * GSH + schk),
                      &A[(size_t)(m0 + row) * K + k0 + schk]);
                cpa16(sBu[nxt2] + 2u * (row * GSH + schk),
                      &W[(size_t)(n0 + row) * K + k0 + schk]);
            }
        }
        CPA_COMMIT();

        const uint32_t cAu = sAu[cur];
        const uint32_t cBu = sBu[cur];

        #pragma unroll
        for (int ks = 0; ks < 2; ks++) {
            int kk = ks * 16;
            uint32_t af[4][4], bf[4][2];
            #pragma unroll
            for (int mt = 0; mt < 4; mt++)
                ldsm4(af[mt][0], af[mt][1], af[mt][2], af[mt][3],
                      cAu + 2u * ((wm * 64 + mt * 16 + aRow) * GSH + kk + aChk));
            #pragma unroll
            for (int t = 0; t < 2; t++)
                ldsm4(bf[2*t][0], bf[2*t][1], bf[2*t+1][0], bf[2*t+1][1],
                      cBu + 2u * ((wn * 32 + t * 16 + bRow) * GSH + kk + bChk));
            #pragma unroll
            for (int mt = 0; mt < 4; mt++)
                #pragma unroll
                for (int nt = 0; nt < 4; nt++)
                    mma16(acc[mt][nt], af[mt], bf[nt][0], bf[nt][1]);
        }

        cur  = (cur  == 2) ? 0 : cur  + 1;
        nxt2 = (nxt2 == 2) ? 0 : nxt2 + 1;
    }

    if (z == 2) {
        #pragma unroll
        for (int nt = 0; nt < 4; nt++) {
            int col = n0 + wn * 32 + nt * 8 + 2 * (lane & 3);
            float2 bz = *(const float2*)&bias[col];
            #pragma unroll
            for (int mt = 0; mt < 4; mt++) {
                int row = m0 + wm * 64 + mt * 16 + (lane >> 2);
                C2t[(size_t) col      * M + row    ] = __float2half_rn(acc[mt][nt].x + bz.x);
                C2t[(size_t)(col + 1) * M + row    ] = __float2half_rn(acc[mt][nt].y + bz.y);
                C2t[(size_t) col      * M + row + 8] = __float2half_rn(acc[mt][nt].z + bz.x);
                C2t[(size_t)(col + 1) * M + row + 8] = __float2half_rn(acc[mt][nt].w + bz.y);
            }
        }
    } else if (halfout) {
        __half* H = (z == 0) ? H0 : H1;
        #pragma unroll
        for (int nt = 0; nt < 4; nt++) {
            int col = n0 + wn * 32 + nt * 8 + 2 * (lane & 3);
            float2 bz = *(const float2*)&bias[col];
            #pragma unroll
            for (int mt = 0; mt < 4; mt++) {
                int row = m0 + wm * 64 + mt * 16 + (lane >> 2);
                *(uint32_t*)&H[(size_t)row * N + col] =
                    pk2(acc[mt][nt].x + bz.x, acc[mt][nt].y + bz.y);
                *(uint32_t*)&H[(size_t)(row + 8) * N + col] =
                    pk2(acc[mt][nt].z + bz.x, acc[mt][nt].w + bz.y);
            }
        }
    } else {
        #pragma unroll
        for (int nt = 0; nt < 4; nt++) {
            int col = n0 + wn * 32 + nt * 8 + 2 * (lane & 3);
            float2 bz = *(const float2*)&bias[col];
            #pragma unroll
            for (int mt = 0; mt < 4; mt++) {
                int row = m0 + wm * 64 + mt * 16 + (lane >> 2);
                float2 v0 = { acc[mt][nt].x + bz.x, acc[mt][nt].y + bz.y };
                float2 v1 = { acc[mt][nt].z + bz.x, acc[mt][nt].w + bz.y };
                *(float2*)&C0f[(size_t)row * N + col]       = v0;
                *(float2*)&C0f[(size_t)(row + 8) * N + col] = v1;
            }
        }
    }
}

// =================================================================
// RoPE (in-place on half Q and K).
// =================================================================
__global__ void rope_kernel(__half* __restrict__ q, __half* __restrict__ k,
                            const float* __restrict__ cosp,
                            const float* __restrict__ sinp)
{
    int idx = blockIdx.x * blockDim.x + threadIdx.x;
    int d  = idx & 31;
    int h  = (idx >> 5) & (NHEAD - 1);
    int bs = idx >> 9;
    int s  = bs & (SEQ - 1);

    int base = bs * D_MODEL + h * HEAD_DIM + d;
    float c1 = cosp[s * HEAD_DIM + d];
    float s1 = sinp[s * HEAD_DIM + d];
    float c2 = cosp[s * HEAD_DIM + d + 32];
    float s2 = sinp[s * HEAD_DIM + d + 32];

    float q1 = __half2float(q[base]), q2 = __half2float(q[base + 32]);
    q[base]      = __float2half_rn(q1 * c1 - q2 * s1);
    q[base + 32] = __float2half_rn(q2 * c2 + q1 * s2);

    float k1 = __half2float(k[base]), k2 = __half2float(k[base + 32]);
    k[base]      = __float2half_rn(k1 * c1 - k2 * s1);
    k[base + 32] = __float2half_rn(k2 * c2 + k1 * s2);
}

// =================================================================
// Flash attention, fp16 m16n8k16: Q frags + P in registers,
// 3-stage cp.async K/V ring, ONE barrier per KV tile.
// CTA = 128 q-rows of one (b,h), 256 threads (8 warps).
// =================================================================
#define PS 72                                   // smem row stride (halves)
#define NT_KV (SEQ / 64)                        // 32 tiles
#define KV_BUF (64 * PS)                        // halves per K or V buffer
#define ATTN_SMEM_HALVES (6 * KV_BUF + 128 * PS)
#define ATTN_SMEM_BYTES  (ATTN_SMEM_HALVES * 2) // 73728

__global__ __launch_bounds__(256, 2)
void attn_f16(const __half* __restrict__ Q, const __half* __restrict__ K,
              const __half* __restrict__ Vt, __half* __restrict__ O)
{
    extern __shared__ __half smh[];
    // ring: K0,K1,K2,V0,V1,V2 then Q staging
    __half* sQs = smh + 6 * KV_BUF;

    const int b    = blockIdx.z;
    const int h    = blockIdx.y;
    const int qt   = blockIdx.x;
    const int tid  = threadIdx.x;
    const int lane = tid & 31;
    const int warp = tid >> 5;

    const int srow = tid >> 3;             // 0..31 (+32 second)
    const int schk = (tid & 7) * 8;        // halves 0..56

    const int qRow = warp * 16 + (lane & 15);
    const int qChk = (lane >> 4) * 8;
    const int kRow = (lane & 7) + ((lane >> 4) * 8);
    const int kChk = ((lane >> 3) & 1) * 8;

    uint32_t sKu[3], sVu[3];
    #pragma unroll
    for (int i = 0; i < 3; i++) {
        sKu[i] = (uint32_t)__cvta_generic_to_shared(smh + i * KV_BUF);
        sVu[i] = (uint32_t)__cvta_generic_to_shared(smh + (3 + i) * KV_BUF);
    }
    const uint32_t sQu = (uint32_t)__cvta_generic_to_shared(sQs);

    const __half* Qb  = Q  + ((size_t)(b * SEQ + qt * 128) * D_MODEL + h * 64);
    const __half* Kb  = K  + ((size_t)(b * SEQ) * D_MODEL + h * 64);
    const __half* Vtb = Vt + ((size_t)(h * 64) * MTOT + b * SEQ);

    // ---- issue cp.async for tiles 0 and 1 ----
    #pragma unroll
    for (int t = 0; t < 2; t++) {
        #pragma unroll
        for (int i = 0; i < 2; i++) {
            int row = srow + i * 32;
            cpa16(sKu[t] + 2u * (row * PS + schk),
                  &Kb [(size_t)(t * 64 + row) * D_MODEL + schk]);
            cpa16(sVu[t] + 2u * (row * PS + schk),
                  &Vtb[(size_t)row * MTOT + t * 64 + schk]);
        }
        CPA_COMMIT();
    }

    // ---- stage Q tile, hoist a-fragments into registers ----
    #pragma unroll
    for (int i = 0; i < 4; i++) {
        int f   = tid + i * 256;
        int row = f >> 3;
        int cc  = (f & 7) * 8;
        *(uint4*)&sQs[row * PS + cc] = *(const uint4*)&Qb[(size_t)row * D_MODEL + cc];
    }
    __syncthreads();
    uint32_t qf[4][4];
    #pragma unroll
    for (int ks = 0; ks < 4; ks++)
        ldsm4(qf[ks][0], qf[ks][1], qf[ks][2], qf[ks][3],
              sQu + 2u * (qRow * PS + ks * 16 + qChk));

    const float SC = 0.125f * 1.44269504088896340736f;  // 1/sqrt(64)*log2(e)

    float m0 = -1e30f, m1 = -1e30f, l0 = 0.f, l1 = 0.f;
    float4 oacc[8] = {};

    int cur = 0, nxt2 = 2;               // ring slots kt%3, (kt+2)%3

    for (int kt = 0; kt < NT_KV; kt++) {
        CPA_WAIT(1);
        __syncthreads();                 // tile kt visible; slot nxt2 free

        // ---- refill tile kt+2 immediately (overlaps whole tile compute) ----
        if (kt + 2 < NT_KV) {
            #pragma unroll
            for (int i = 0; i < 2; i++) {
                int row = srow + i * 32;
                cpa16(sKu[nxt2] + 2u * (row * PS + schk),
                      &Kb [(size_t)((kt + 2) * 64 + row) * D_MODEL + schk]);
                cpa16(sVu[nxt2] + 2u * (row * PS + schk),
                      &Vtb[(size_t)row * MTOT + (kt + 2) * 64 + schk]);
            }
        }
        CPA_COMMIT();

        const uint32_t cK = sKu[cur];
        const uint32_t cV = sVu[cur];

        // ---- scores = Q K^T ----
        float4 s[8] = {};
        #pragma unroll
        for (int ks = 0; ks < 4; ks++) {
            int kk = ks * 16;
            uint32_t bfr[8][2];
            #pragma unroll
            for (int t = 0; t < 4; t++)
                ldsm4(bfr[2*t][0], bfr[2*t][1], bfr[2*t+1][0], bfr[2*t+1][1],
                      cK + 2u * ((t * 16 + kRow) * PS + kk + kChk));
            #pragma unroll
            for (int nt = 0; nt < 8; nt++)
                mma16(s[nt], qf[ks], bfr[nt][0], bfr[nt][1]);
        }

        // ---- online softmax (base-2, scale folded into FFMA) ----
        float rm0 = -1e30f, rm1 = -1e30f;
        #pragma unroll
        for (int nt = 0; nt < 8; nt++) {
            rm0 = fmaxf(rm0, fmaxf(s[nt].x, s[nt].y));
            rm1 = fmaxf(rm1, fmaxf(s[nt].z, s[nt].w));
        }
        rm0 = fmaxf(rm0, __shfl_xor_sync(0xffffffff, rm0, 1));
        rm0 = fmaxf(rm0, __shfl_xor_sync(0xffffffff, rm0, 2));
        rm1 = fmaxf(rm1, __shfl_xor_sync(0xffffffff, rm1, 1));
        rm1 = fmaxf(rm1, __shfl_xor_sync(0xffffffff, rm1, 2));

        float mn0 = fmaxf(m0, rm0 * SC);
        float mn1 = fmaxf(m1, rm1 * SC);
        float al0 = exp2f(m0 - mn0);
        float al1 = exp2f(m1 - mn1);
        m0 = mn0; m1 = mn1;

        // P stays in registers (C-frag -> A-frag identity)
        uint32_t p[8][2];
        float rs0 = 0.f, rs1 = 0.f;
        #pragma unroll
        for (int nt = 0; nt < 8; nt++) {
            float px = exp2f(fmaf(s[nt].x, SC, -mn0));
            float py = exp2f(fmaf(s[nt].y, SC, -mn0));
            float pz = exp2f(fmaf(s[nt].z, SC, -mn1));
            float pw = exp2f(fmaf(s[nt].w, SC, -mn1));
            rs0 += px + py;
            rs1 += pz + pw;
            p[nt][0] = pk2(px, py);
            p[nt][1] = pk2(pz, pw);
        }
        rs0 += __shfl_xor_sync(0xffffffff, rs0, 1);
        rs0 += __shfl_xor_sync(0xffffffff, rs0, 2);
        rs1 += __shfl_xor_sync(0xffffffff, rs1, 1);
        rs1 += __shfl_xor_sync(0xffffffff, rs1, 2);

        l0 = l0 * al0 + rs0;
        l1 = l1 * al1 + rs1;

        #pragma unroll
        for (int nt = 0; nt < 8; nt++) {
            oacc[nt].x *= al0; oacc[nt].y *= al0;
            oacc[nt].z *= al1; oacc[nt].w *= al1;
        }

        // ---- oacc += P @ V ----
        #pragma unroll
        for (int ks = 0; ks < 4; ks++) {
            int kk = ks * 16;
            uint32_t af[4] = { p[2*ks][0], p[2*ks][1], p[2*ks+1][0], p[2*ks+1][1] };
            uint32_t bfr[8][2];
            #pragma unroll
            for (int t = 0; t < 4; t++)
                ldsm4(bfr[2*t][0], bfr[2*t][1], bfr[2*t+1][0], bfr[2*t+1][1],
                      cV + 2u * ((t * 16 + kRow) * PS + kk + kChk));
            #pragma unroll
            for (int nt = 0; nt < 8; nt++)
                mma16(oacc[nt], af, bfr[nt][0], bfr[nt][1]);
        }

        cur  = (cur  == 2) ? 0 : cur  + 1;
        nxt2 = (nxt2 == 2) ? 0 : nxt2 + 1;
    }

    // ---- epilogue: normalize, write half ctx ----
    const int er = warp * 16 + (lane >> 2);
    float inv0 = 1.f / l0;
    float inv1 = 1.f / l1;
    __half* Ob = O + ((size_t)(b * SEQ + qt * 128) * D_MODEL + h * 64);
    #pragma unroll
    for (int nt = 0; nt < 8; nt++) {
        int col = nt * 8 + 2 * (lane & 3);
        *(uint32_t*)&Ob[(size_t) er      * D_MODEL + col] =
            pk2(oacc[nt].x * inv0, oacc[nt].y * inv0);
        *(uint32_t*)&Ob[(size_t)(er + 8) * D_MODEL + col] =
            pk2(oacc[nt].z * inv1, oacc[nt].w * inv1);
    }
}

// =================================================================
extern "C" void kernel_launch(void* const* d_in, const int* in_sizes, int n_in,
                              void* d_out, int out_size)
{
    const float* x    = (const float*)d_in[0];
    const float* cosp = (const float*)d_in[1];
    const float* sinp = (const float*)d_in[2];
    const float* Wq   = (const float*)d_in[3];
    const float* bq   = (const float*)d_in[4];
    const float* Wk   = (const float*)d_in[5];
    const float* bk   = (const float*)d_in[6];
    const float* Wv   = (const float*)d_in[7];
    const float* bv   = (const float*)d_in[8];
    const float* Wo   = (const float*)d_in[9];
    const float* bo   = (const float*)d_in[10];
    float* out = (float*)d_out;

    __half *qh, *kh, *vth, *ctxh, *xh, *wqh, *wkh, *wvh, *woh;
    cudaGetSymbolAddress((void**)&qh,   g_qh);
    cudaGetSymbolAddress((void**)&kh,   g_kh);
    cudaGetSymbolAddress((void**)&vth,  g_vth);
    cudaGetSymbolAddress((void**)&ctxh, g_ctxh);
    cudaGetSymbolAddress((void**)&xh,   g_xh);
    cudaGetSymbolAddress((void**)&wqh,  g_wqh);
    cudaGetSymbolAddress((void**)&wkh,  g_wkh);
    cudaGetSymbolAddress((void**)&wvh,  g_wvh);
    cudaGetSymbolAddress((void**)&woh,  g_woh);

    tohalf_kernel<<<(MTOT * D_MODEL / 4 + 255) / 256, 256>>>(x, Wq, Wk, Wv, Wo);

    cudaFuncSetAttribute(gemm3_f16,
                         cudaFuncAttributeMaxDynamicSharedMemorySize,
                         GEMM_SMEM_BYTES);
    dim3 g3(D_MODEL / 128, MTOT / 128, 3);   // (8, 32, 3)
    gemm3_f16<<<g3, 256, GEMM_SMEM_BYTES>>>(xh, wqh, wkh, wvh, bq, bk, bv,
                           (float*)nullptr, qh, kh, vth, 1,
                           MTOT, D_MODEL, D_MODEL);

    rope_kernel<<<(MTOT * NHEAD * 32) / 256, 256>>>(qh, kh, cosp, sinp);

    cudaFuncSetAttribute(attn_f16,
                         cudaFuncAttributeMaxDynamicSharedMemorySize,
                         ATTN_SMEM_BYTES);
    attn_f16<<<dim3(SEQ / 128, NHEAD, BATCH), 256, ATTN_SMEM_BYTES>>>(qh, kh, vth, ctxh);

    dim3 g1(D_MODEL / 128, MTOT / 128, 1);
    gemm3_f16<<<g1, 256, GEMM_SMEM_BYTES>>>(ctxh, woh, woh, woh, bo, bo, bo,
                           out, (__half*)nullptr, (__half*)nullptr, (__half*)nullptr, 0,
                           MTOT, D_MODEL, D_MODEL);
}

// round 15
// speedup vs baseline: 12.6668x; 1.0218x over previous
#include <cuda_runtime.h>
#include <cuda_fp16.h>
#include <math.h>
#include <stdint.h>

#define D_MODEL 1024
#define NHEAD   16
#define HEAD_DIM 64
#define BATCH   2
#define SEQ     2048
#define MTOT    (BATCH*SEQ)          // 4096

// ---------------- scratch (no allocations allowed) ----------------
__device__ __half g_qh[MTOT*D_MODEL];     // Q proj (half) -> rope in-place
__device__ __half g_kh[MTOT*D_MODEL];
__device__ __half g_vth[D_MODEL*MTOT];    // V proj TRANSPOSED [d][m], half
__device__ __half g_ctxh[MTOT*D_MODEL];   // attention out, half
__device__ __half g_xh [MTOT*D_MODEL];    // x -> half
__device__ __half g_wqh[D_MODEL*D_MODEL];
__device__ __half g_wkh[D_MODEL*D_MODEL];
__device__ __half g_wvh[D_MODEL*D_MODEL];
__device__ __half g_woh[D_MODEL*D_MODEL];

// ---------------- helpers ----------------
__device__ __forceinline__ uint32_t pk2(float a, float b) {
    __half2 h = __floats2half2_rn(a, b);
    return *(uint32_t*)&h;
}

__device__ __forceinline__ void mma16(float4& d, const uint32_t a[4],
                                      uint32_t b0, uint32_t b1) {
    asm volatile(
        "mma.sync.aligned.m16n8k16.row.col.f32.f16.f16.f32 "
        "{%0,%1,%2,%3},{%4,%5,%6,%7},{%8,%9},{%0,%1,%2,%3};"
        : "+f"(d.x), "+f"(d.y), "+f"(d.z), "+f"(d.w)
        : "r"(a[0]), "r"(a[1]), "r"(a[2]), "r"(a[3]), "r"(b0), "r"(b1));
}

__device__ __forceinline__ void ldsm4(uint32_t& r0, uint32_t& r1,
                                      uint32_t& r2, uint32_t& r3, uint32_t addr) {
    asm volatile("ldmatrix.sync.aligned.m8n8.x4.shared.b16 {%0,%1,%2,%3}, [%4];"
                 : "=r"(r0), "=r"(r1), "=r"(r2), "=r"(r3) : "r"(addr));
}

__device__ __forceinline__ void cpa16(uint32_t dst_smem, const void* src) {
    asm volatile("cp.async.cg.shared.global [%0], [%1], 16;"
                 :: "r"(dst_smem), "l"(src));
}
#define CPA_COMMIT() asm volatile("cp.async.commit_group;" ::: "memory")
#define CPA_WAIT(n)  asm volatile("cp.async.wait_group %0;" :: "n"(n) : "memory")

// =================================================================
// Convert x and the four weight matrices to fp16 (rn) once.
// =================================================================
__global__ void tohalf_kernel(const float* __restrict__ x,
                              const float* __restrict__ Wq,
                              const float* __restrict__ Wk,
                              const float* __restrict__ Wv,
                              const float* __restrict__ Wo)
{
    int i = blockIdx.x * blockDim.x + threadIdx.x;   // float4 index
    const int NX = MTOT * D_MODEL / 4;
    const int NW = D_MODEL * D_MODEL / 4;
    if (i < NX) {
        float4 v = ((const float4*)x)[i];
        ((uint2*)g_xh)[i] = make_uint2(pk2(v.x, v.y), pk2(v.z, v.w));
    }
    if (i < NW) {
        float4 v = ((const float4*)Wq)[i];
        ((uint2*)g_wqh)[i] = make_uint2(pk2(v.x, v.y), pk2(v.z, v.w));
        v = ((const float4*)Wk)[i];
        ((uint2*)g_wkh)[i] = make_uint2(pk2(v.x, v.y), pk2(v.z, v.w));
        v = ((const float4*)Wv)[i];
        ((uint2*)g_wvh)[i] = make_uint2(pk2(v.x, v.y), pk2(v.z, v.w));
        v = ((const float4*)Wo)[i];
        ((uint2*)g_woh)[i] = make_uint2(pk2(v.x, v.y), pk2(v.z, v.w));
    }
}

// =================================================================
// fp16 GEMM (fused over gridDim.z), 3-stage cp.async ring,
// ONE barrier per k-iter.  C = A @ W^T + b, f32 accumulate.
// halfout: z<2 outputs written half (Q/K proj); else f32 (O proj).
// z==2 (V projection): epilogue writes half TRANSPOSED to C2t[d][m].
// =================================================================
#define GSH 40   // smem row stride (halves)
#define GEMM_BUF (128 * GSH)                    // halves per tile buffer
#define GEMM_SMEM_BYTES (6 * GEMM_BUF * 2)      // 3xA + 3xB = 61440

__global__ __launch_bounds__(256, 2)
void gemm3_f16(const __half* __restrict__ A,
               const __half* __restrict__ W0, const __half* __restrict__ W1,
               const __half* __restrict__ W2,
               const float* __restrict__ B0, const float* __restrict__ B1,
               const float* __restrict__ B2,
               float* __restrict__ C0f,
               __half* __restrict__ H0, __half* __restrict__ H1,
               __half* __restrict__ C2t,
               int halfout, int M, int N, int K)
{
    extern __shared__ __half gsm[];

    const int z = blockIdx.z;
    const __half* W   = (z == 0) ? W0 : (z == 1) ? W1 : W2;
    const float* bias = (z == 0) ? B0 : (z == 1) ? B1 : B2;

    const int tid  = threadIdx.x;
    const int lane = tid & 31;
    const int warp = tid >> 5;
    const int wm   = warp >> 2;
    const int wn   = warp & 3;
    const int m0   = blockIdx.y * 128;
    const int n0   = blockIdx.x * 128;

    const int srow  = tid >> 2;          // 0..63 (+64 second)
    const int schk  = (tid & 3) * 8;     // halves 0,8,16,24

    const int aRow = lane & 15;
    const int aChk = (lane >> 4) * 8;
    const int bRow = (lane & 7) + ((lane >> 4) * 8);
    const int bChk = ((lane >> 3) & 1) * 8;

    uint32_t sAu[3], sBu[3];
    #pragma unroll
    for (int i = 0; i < 3; i++) {
        sAu[i] = (uint32_t)__cvta_generic_to_shared(gsm + i * GEMM_BUF);
        sBu[i] = (uint32_t)__cvta_generic_to_shared(gsm + (3 + i) * GEMM_BUF);
    }

    const int nIter = K / 32;            // 32

    // preload k-iters 0 and 1
    #pragma unroll
    for (int t = 0; t < 2; t++) {
        int k0 = t * 32;
        #pragma unroll
        for (int i = 0; i < 2; i++) {
            int row = srow + i * 64;
            cpa16(sAu[t] + 2u * (row * GSH + schk),
                  &A[(size_t)(m0 + row) * K + k0 + schk]);
            cpa16(sBu[t] + 2u * (row * GSH + schk),
                  &W[(size_t)(n0 + row) * K + k0 + schk]);
        }
        CPA_COMMIT();
    }

    float4 acc[4][4] = {};
    int cur = 0, nxt2 = 2;               // ring slots: it%3, (it+2)%3

    for (int it = 0; it < nIter; it++) {
        CPA_WAIT(1);
        __syncthreads();                 // tile it visible; slot nxt2 free

        if (it + 2 < nIter) {
            int k0 = (it + 2) * 32;
            #pragma unroll
            for (int i = 0; i < 2; i++) {
                int row = srow + i * 64;
                cpa16(sAu[nxt2] + 2u * (row * GSH + schk),
                      &A[(size_t)(m0 + row) * K + k0 + schk]);
                cpa16(sBu[nxt2] + 2u * (row * GSH + schk),
                      &W[(size_t)(n0 + row) * K + k0 + schk]);
            }
        }
        CPA_COMMIT();

        const uint32_t cAu = sAu[cur];
        const uint32_t cBu = sBu[cur];

        #pragma unroll
        for (int ks = 0; ks < 2; ks++) {
            int kk = ks * 16;
            uint32_t af[4][4], bf[4][2];
            #pragma unroll
            for (int mt = 0; mt < 4; mt++)
                ldsm4(af[mt][0], af[mt][1], af[mt][2], af[mt][3],
                      cAu + 2u * ((wm * 64 + mt * 16 + aRow) * GSH + kk + aChk));
            #pragma unroll
            for (int t = 0; t < 2; t++)
                ldsm4(bf[2*t][0], bf[2*t][1], bf[2*t+1][0], bf[2*t+1][1],
                      cBu + 2u * ((wn * 32 + t * 16 + bRow) * GSH + kk + bChk));
            #pragma unroll
            for (int mt = 0; mt < 4; mt++)
                #pragma unroll
                for (int nt = 0; nt < 4; nt++)
                    mma16(acc[mt][nt], af[mt], bf[nt][0], bf[nt][1]);
        }

        cur  = (cur  == 2) ? 0 : cur  + 1;
        nxt2 = (nxt2 == 2) ? 0 : nxt2 + 1;
    }

    if (z == 2) {
        #pragma unroll
        for (int nt = 0; nt < 4; nt++) {
            int col = n0 + wn * 32 + nt * 8 + 2 * (lane & 3);
            float2 bz = *(const float2*)&bias[col];
            #pragma unroll
            for (int mt = 0; mt < 4; mt++) {
                int row = m0 + wm * 64 + mt * 16 + (lane >> 2);
                C2t[(size_t) col      * M + row    ] = __float2half_rn(acc[mt][nt].x + bz.x);
                C2t[(size_t)(col + 1) * M + row    ] = __float2half_rn(acc[mt][nt].y + bz.y);
                C2t[(size_t) col      * M + row + 8] = __float2half_rn(acc[mt][nt].z + bz.x);
                C2t[(size_t)(col + 1) * M + row + 8] = __float2half_rn(acc[mt][nt].w + bz.y);
            }
        }
    } else if (halfout) {
        __half* H = (z == 0) ? H0 : H1;
        #pragma unroll
        for (int nt = 0; nt < 4; nt++) {
            int col = n0 + wn * 32 + nt * 8 + 2 * (lane & 3);
            float2 bz = *(const float2*)&bias[col];
            #pragma unroll
            for (int mt = 0; mt < 4; mt++) {
                int row = m0 + wm * 64 + mt * 16 + (lane >> 2);
                *(uint32_t*)&H[(size_t)row * N + col] =
                    pk2(acc[mt][nt].x + bz.x, acc[mt][nt].y + bz.y);
                *(uint32_t*)&H[(size_t)(row + 8) * N + col] =
                    pk2(acc[mt][nt].z + bz.x, acc[mt][nt].w + bz.y);
            }
        }
    } else {
        #pragma unroll
        for (int nt = 0; nt < 4; nt++) {
            int col = n0 + wn * 32 + nt * 8 + 2 * (lane & 3);
            float2 bz = *(const float2*)&bias[col];
            #pragma unroll
            for (int mt = 0; mt < 4; mt++) {
                int row = m0 + wm * 64 + mt * 16 + (lane >> 2);
                float2 v0 = { acc[mt][nt].x + bz.x, acc[mt][nt].y + bz.y };
                float2 v1 = { acc[mt][nt].z + bz.x, acc[mt][nt].w + bz.y };
                *(float2*)&C0f[(size_t)row * N + col]       = v0;
                *(float2*)&C0f[(size_t)(row + 8) * N + col] = v1;
            }
        }
    }
}

// =================================================================
// RoPE (in-place on half Q and K).
// =================================================================
__global__ void rope_kernel(__half* __restrict__ q, __half* __restrict__ k,
                            const float* __restrict__ cosp,
                            const float* __restrict__ sinp)
{
    int idx = blockIdx.x * blockDim.x + threadIdx.x;
    int d  = idx & 31;
    int h  = (idx >> 5) & (NHEAD - 1);
    int bs = idx >> 9;
    int s  = bs & (SEQ - 1);

    int base = bs * D_MODEL + h * HEAD_DIM + d;
    float c1 = cosp[s * HEAD_DIM + d];
    float s1 = sinp[s * HEAD_DIM + d];
    float c2 = cosp[s * HEAD_DIM + d + 32];
    float s2 = sinp[s * HEAD_DIM + d + 32];

    float q1 = __half2float(q[base]), q2 = __half2float(q[base + 32]);
    q[base]      = __float2half_rn(q1 * c1 - q2 * s1);
    q[base + 32] = __float2half_rn(q2 * c2 + q1 * s2);

    float k1 = __half2float(k[base]), k2 = __half2float(k[base + 32]);
    k[base]      = __float2half_rn(k1 * c1 - k2 * s1);
    k[base + 32] = __float2half_rn(k2 * c2 + k1 * s2);
}

// =================================================================
// Flash attention, fp16 m16n8k16, DEFERRED-PV pipeline:
// iter kt does QK(kt), then [oacc rescale + PV(kt-1)] overlapped with
// softmax(kt) (shuffles issued early, PV fills their latency).
// K ring depth 3, V ring depth 4, one barrier per tile.
// CTA = 128 q-rows of one (b,h), 256 threads (8 warps).
// =================================================================
#define PS 72                                   // smem row stride (halves)
#define NT_KV (SEQ / 64)                        // 32 tiles
#define KV_BUF (64 * PS)                        // halves per buffer
#define ATTN_SMEM_HALVES ((3 + 4) * KV_BUF + 128 * PS)
#define ATTN_SMEM_BYTES  (ATTN_SMEM_HALVES * 2) // 82944

__global__ __launch_bounds__(256, 2)
void attn_f16(const __half* __restrict__ Q, const __half* __restrict__ K,
              const __half* __restrict__ Vt, __half* __restrict__ O)
{
    extern __shared__ __half smh[];
    // layout: K0,K1,K2, V0,V1,V2,V3, Q staging
    __half* sQs = smh + 7 * KV_BUF;

    const int b    = blockIdx.z;
    const int h    = blockIdx.y;
    const int qt   = blockIdx.x;
    const int tid  = threadIdx.x;
    const int lane = tid & 31;
    const int warp = tid >> 5;

    const int srow = tid >> 3;             // 0..31 (+32 second)
    const int schk = (tid & 7) * 8;        // halves 0..56

    const int qRow = warp * 16 + (lane & 15);
    const int qChk = (lane >> 4) * 8;
    const int kRow = (lane & 7) + ((lane >> 4) * 8);
    const int kChk = ((lane >> 3) & 1) * 8;

    uint32_t sKu[3], sVu[4];
    #pragma unroll
    for (int i = 0; i < 3; i++)
        sKu[i] = (uint32_t)__cvta_generic_to_shared(smh + i * KV_BUF);
    #pragma unroll
    for (int i = 0; i < 4; i++)
        sVu[i] = (uint32_t)__cvta_generic_to_shared(smh + (3 + i) * KV_BUF);
    const uint32_t sQu = (uint32_t)__cvta_generic_to_shared(sQs);

    const __half* Qb  = Q  + ((size_t)(b * SEQ + qt * 128) * D_MODEL + h * 64);
    const __half* Kb  = K  + ((size_t)(b * SEQ) * D_MODEL + h * 64);
    const __half* Vtb = Vt + ((size_t)(h * 64) * MTOT + b * SEQ);

    // ---- issue cp.async for tiles 0 and 1 (K->slot t, V->slot t) ----
    #pragma unroll
    for (int t = 0; t < 2; t++) {
        #pragma unroll
        for (int i = 0; i < 2; i++) {
            int row = srow + i * 32;
            cpa16(sKu[t] + 2u * (row * PS + schk),
                  &Kb [(size_t)(t * 64 + row) * D_MODEL + schk]);
            cpa16(sVu[t] + 2u * (row * PS + schk),
                  &Vtb[(size_t)row * MTOT + t * 64 + schk]);
        }
        CPA_COMMIT();
    }

    // ---- stage Q tile, hoist a-fragments into registers ----
    #pragma unroll
    for (int i = 0; i < 4; i++) {
        int f   = tid + i * 256;
        int row = f >> 3;
        int cc  = (f & 7) * 8;
        *(uint4*)&sQs[row * PS + cc] = *(const uint4*)&Qb[(size_t)row * D_MODEL + cc];
    }
    __syncthreads();
    uint32_t qf[4][4];
    #pragma unroll
    for (int ks = 0; ks < 4; ks++)
        ldsm4(qf[ks][0], qf[ks][1], qf[ks][2], qf[ks][3],
              sQu + 2u * (qRow * PS + ks * 16 + qChk));

    const float SC = 0.125f * 1.44269504088896340736f;  // 1/sqrt(64)*log2(e)

    float m0 = -1e30f, m1 = -1e30f, l0 = 0.f, l1 = 0.f;
    float4 oacc[8] = {};
    uint32_t pp[8][2];                   // P(kt-1) fragments
    float al0p = 0.f, al1p = 0.f;        // al(kt-1)

    // ================= peeled iteration 0 =================
    {
        CPA_WAIT(1);
        __syncthreads();
        // refill tile 2: K->slot 2, V->slot 2
        #pragma unroll
        for (int i = 0; i < 2; i++) {
            int row = srow + i * 32;
            cpa16(sKu[2] + 2u * (row * PS + schk),
                  &Kb [(size_t)(2 * 64 + row) * D_MODEL + schk]);
            cpa16(sVu[2] + 2u * (row * PS + schk),
                  &Vtb[(size_t)row * MTOT + 2 * 64 + schk]);
        }
        CPA_COMMIT();

        const uint32_t cK = sKu[0];
        float4 s[8] = {};
        #pragma unroll
        for (int ks = 0; ks < 4; ks++) {
            int kk = ks * 16;
            uint32_t bfr[8][2];
            #pragma unroll
            for (int t = 0; t < 4; t++)
                ldsm4(bfr[2*t][0], bfr[2*t][1], bfr[2*t+1][0], bfr[2*t+1][1],
                      cK + 2u * ((t * 16 + kRow) * PS + kk + kChk));
            #pragma unroll
            for (int nt = 0; nt < 8; nt++)
                mma16(s[nt], qf[ks], bfr[nt][0], bfr[nt][1]);
        }

        float rm0 = -1e30f, rm1 = -1e30f;
        #pragma unroll
        for (int nt = 0; nt < 8; nt++) {
            rm0 = fmaxf(rm0, fmaxf(s[nt].x, s[nt].y));
            rm1 = fmaxf(rm1, fmaxf(s[nt].z, s[nt].w));
        }
        rm0 = fmaxf(rm0, __shfl_xor_sync(0xffffffff, rm0, 1));
        rm0 = fmaxf(rm0, __shfl_xor_sync(0xffffffff, rm0, 2));
        rm1 = fmaxf(rm1, __shfl_xor_sync(0xffffffff, rm1, 1));
        rm1 = fmaxf(rm1, __shfl_xor_sync(0xffffffff, rm1, 2));

        float mn0 = fmaxf(m0, rm0 * SC);
        float mn1 = fmaxf(m1, rm1 * SC);
        al0p = exp2f(m0 - mn0);          // = 0
        al1p = exp2f(m1 - mn1);
        m0 = mn0; m1 = mn1;

        float rs0 = 0.f, rs1 = 0.f;
        #pragma unroll
        for (int nt = 0; nt < 8; nt++) {
            float px = exp2f(fmaf(s[nt].x, SC, -mn0));
            float py = exp2f(fmaf(s[nt].y, SC, -mn0));
            float pz = exp2f(fmaf(s[nt].z, SC, -mn1));
            float pw = exp2f(fmaf(s[nt].w, SC, -mn1));
            rs0 += px + py;
            rs1 += pz + pw;
            pp[nt][0] = pk2(px, py);
            pp[nt][1] = pk2(pz, pw);
        }
        rs0 += __shfl_xor_sync(0xffffffff, rs0, 1);
        rs0 += __shfl_xor_sync(0xffffffff, rs0, 2);
        rs1 += __shfl_xor_sync(0xffffffff, rs1, 1);
        rs1 += __shfl_xor_sync(0xffffffff, rs1, 2);
        l0 = rs0;
        l1 = rs1;
    }

    // ================= main loop kt = 1 .. NT-1 =================
    int kCur = 1, kFill = 0, vRead = 0, vFill = 3;
    for (int kt = 1; kt < NT_KV; kt++) {
        CPA_WAIT(1);
        __syncthreads();                 // K(kt),V(kt) visible; fill slots free

        if (kt + 2 < NT_KV) {
            #pragma unroll
            for (int i = 0; i < 2; i++) {
                int row = srow + i * 32;
                cpa16(sKu[kFill] + 2u * (row * PS + schk),
                      &Kb [(size_t)((kt + 2) * 64 + row) * D_MODEL + schk]);
                cpa16(sVu[vFill] + 2u * (row * PS + schk),
                      &Vtb[(size_t)row * MTOT + (kt + 2) * 64 + schk]);
            }
        }
        CPA_COMMIT();

        const uint32_t cK = sKu[kCur];
        const uint32_t cV = sVu[vRead];  // V(kt-1)

        // ---- QK(kt) ----
        float4 s[8] = {};
        #pragma unroll
        for (int ks = 0; ks < 4; ks++) {
            int kk = ks * 16;
            uint32_t bfr[8][2];
            #pragma unroll
            for (int t = 0; t < 4; t++)
                ldsm4(bfr[2*t][0], bfr[2*t][1], bfr[2*t+1][0], bfr[2*t+1][1],
                      cK + 2u * ((t * 16 + kRow) * PS + kk + kChk));
            #pragma unroll
            for (int nt = 0; nt < 8; nt++)
                mma16(s[nt], qf[ks], bfr[nt][0], bfr[nt][1]);
        }

        // ---- local max + issue shuffles EARLY (latency hidden by PV) ----
        float rm0 = -1e30f, rm1 = -1e30f;
        #pragma unroll
        for (int nt = 0; nt < 8; nt++) {
            rm0 = fmaxf(rm0, fmaxf(s[nt].x, s[nt].y));
            rm1 = fmaxf(rm1, fmaxf(s[nt].z, s[nt].w));
        }
        rm0 = fmaxf(rm0, __shfl_xor_sync(0xffffffff, rm0, 1));
        rm1 = fmaxf(rm1, __shfl_xor_sync(0xffffffff, rm1, 1));
        rm0 = fmaxf(rm0, __shfl_xor_sync(0xffffffff, rm0, 2));
        rm1 = fmaxf(rm1, __shfl_xor_sync(0xffffffff, rm1, 2));

        // ---- oacc rescale by al(kt-1) + PV(kt-1) — independent of rm ----
        #pragma unroll
        for (int nt = 0; nt < 8; nt++) {
            oacc[nt].x *= al0p; oacc[nt].y *= al0p;
            oacc[nt].z *= al1p; oacc[nt].w *= al1p;
        }
        #pragma unroll
        for (int ks = 0; ks < 4; ks++) {
            int kk = ks * 16;
            uint32_t af[4] = { pp[2*ks][0], pp[2*ks][1], pp[2*ks+1][0], pp[2*ks+1][1] };
            uint32_t bfr[8][2];
            #pragma unroll
            for (int t = 0; t < 4; t++)
                ldsm4(bfr[2*t][0], bfr[2*t][1], bfr[2*t+1][0], bfr[2*t+1][1],
                      cV + 2u * ((t * 16 + kRow) * PS + kk + kChk));
            #pragma unroll
            for (int nt = 0; nt < 8; nt++)
                mma16(oacc[nt], af, bfr[nt][0], bfr[nt][1]);
        }

        // ---- finish softmax(kt) ----
        float mn0 = fmaxf(m0, rm0 * SC);
        float mn1 = fmaxf(m1, rm1 * SC);
        al0p = exp2f(m0 - mn0);
        al1p = exp2f(m1 - mn1);
        m0 = mn0; m1 = mn1;

        float rs0 = 0.f, rs1 = 0.f;
        #pragma unroll
        for (int nt = 0; nt < 8; nt++) {
            float px = exp2f(fmaf(s[nt].x, SC, -mn0));
            float py = exp2f(fmaf(s[nt].y, SC, -mn0));
            float pz = exp2f(fmaf(s[nt].z, SC, -mn1));
            float pw = exp2f(fmaf(s[nt].w, SC, -mn1));
            rs0 += px + py;
            rs1 += pz + pw;
            pp[nt][0] = pk2(px, py);
            pp[nt][1] = pk2(pz, pw);
        }
        rs0 += __shfl_xor_sync(0xffffffff, rs0, 1);
        rs1 += __shfl_xor_sync(0xffffffff, rs1, 1);
        rs0 += __shfl_xor_sync(0xffffffff, rs0, 2);
        rs1 += __shfl_xor_sync(0xffffffff, rs1, 2);

        l0 = l0 * al0p + rs0;
        l1 = l1 * al1p + rs1;

        kCur  = (kCur  == 2) ? 0 : kCur  + 1;
        kFill = (kFill == 2) ? 0 : kFill + 1;
        vRead = (vRead == 3) ? 0 : vRead + 1;
        vFill = (vFill == 3) ? 0 : vFill + 1;
    }

    // ================= tail: PV(NT-1) =================
    {
        const uint32_t cV = sVu[vRead];  // V(NT-1), slot 31%4 = 3
        #pragma unroll
        for (int nt = 0; nt < 8; nt++) {
            oacc[nt].x *= al0p; oacc[nt].y *= al0p;
            oacc[nt].z *= al1p; oacc[nt].w *= al1p;
        }
        #pragma unroll
        for (int ks = 0; ks < 4; ks++) {
            int kk = ks * 16;
            uint32_t af[4] = { pp[2*ks][0], pp[2*ks][1], pp[2*ks+1][0], pp[2*ks+1][1] };
            uint32_t bfr[8][2];
            #pragma unroll
            for (int t = 0; t < 4; t++)
                ldsm4(bfr[2*t][0], bfr[2*t][1], bfr[2*t+1][0], bfr[2*t+1][1],
                      cV + 2u * ((t * 16 + kRow) * PS + kk + kChk));
            #pragma unroll
            for (int nt = 0; nt < 8; nt++)
                mma16(oacc[nt], af, bfr[nt][0], bfr[nt][1]);
        }
    }

    // ---- epilogue: normalize, write half ctx ----
    const int er = warp * 16 + (lane >> 2);
    float inv0 = 1.f / l0;
    float inv1 = 1.f / l1;
    __half* Ob = O + ((size_t)(b * SEQ + qt * 128) * D_MODEL + h * 64);
    #pragma unroll
    for (int nt = 0; nt < 8; nt++) {
        int col = nt * 8 + 2 * (lane & 3);
        *(uint32_t*)&Ob[(size_t) er      * D_MODEL + col] =
            pk2(oacc[nt].x * inv0, oacc[nt].y * inv0);
        *(uint32_t*)&Ob[(size_t)(er + 8) * D_MODEL + col] =
            pk2(oacc[nt].z * inv1, oacc[nt].w * inv1);
    }
}

// =================================================================
extern "C" void kernel_launch(void* const* d_in, const int* in_sizes, int n_in,
                              void* d_out, int out_size)
{
    const float* x    = (const float*)d_in[0];
    const float* cosp = (const float*)d_in[1];
    const float* sinp = (const float*)d_in[2];
    const float* Wq   = (const float*)d_in[3];
    const float* bq   = (const float*)d_in[4];
    const float* Wk   = (const float*)d_in[5];
    const float* bk   = (const float*)d_in[6];
    const float* Wv   = (const float*)d_in[7];
    const float* bv   = (const float*)d_in[8];
    const float* Wo   = (const float*)d_in[9];
    const float* bo   = (const float*)d_in[10];
    float* out = (float*)d_out;

    __half *qh, *kh, *vth, *ctxh, *xh, *wqh, *wkh, *wvh, *woh;
    cudaGetSymbolAddress((void**)&qh,   g_qh);
    cudaGetSymbolAddress((void**)&kh,   g_kh);
    cudaGetSymbolAddress((void**)&vth,  g_vth);
    cudaGetSymbolAddress((void**)&ctxh, g_ctxh);
    cudaGetSymbolAddress((void**)&xh,   g_xh);
    cudaGetSymbolAddress((void**)&wqh,  g_wqh);
    cudaGetSymbolAddress((void**)&wkh,  g_wkh);
    cudaGetSymbolAddress((void**)&wvh,  g_wvh);
    cudaGetSymbolAddress((void**)&woh,  g_woh);

    tohalf_kernel<<<(MTOT * D_MODEL / 4 + 255) / 256, 256>>>(x, Wq, Wk, Wv, Wo);

    cudaFuncSetAttribute(gemm3_f16,
                         cudaFuncAttributeMaxDynamicSharedMemorySize,
                         GEMM_SMEM_BYTES);
    dim3 g3(D_MODEL / 128, MTOT / 128, 3);   // (8, 32, 3)
    gemm3_f16<<<g3, 256, GEMM_SMEM_BYTES>>>(xh, wqh, wkh, wvh, bq, bk, bv,
                           (float*)nullptr, qh, kh, vth, 1,
                           MTOT, D_MODEL, D_MODEL);

    rope_kernel<<<(MTOT * NHEAD * 32) / 256, 256>>>(qh, kh, cosp, sinp);

    cudaFuncSetAttribute(attn_f16,
                         cudaFuncAttributeMaxDynamicSharedMemorySize,
                         ATTN_SMEM_BYTES);
    attn_f16<<<dim3(SEQ / 128, NHEAD, BATCH), 256, ATTN_SMEM_BYTES>>>(qh, kh, vth, ctxh);

    dim3 g1(D_MODEL / 128, MTOT / 128, 1);
    gemm3_f16<<<g1, 256, GEMM_SMEM_BYTES>>>(ctxh, woh, woh, woh, bo, bo, bo,
                           out, (__half*)nullptr, (__half*)nullptr, (__half*)nullptr, 0,
                           MTOT, D_MODEL, D_MODEL);
}